// round 1
// baseline (speedup 1.0000x reference)
#include <cuda_runtime.h>
#include <cstdint>

// Problem constants
#define BB   2
#define QQ   2048
#define KK   2048
#define EMB  2048
#define HH   32
#define DD   64
#define ROWS (BB * QQ)          // 4096 rows for q/ctx, also 4096 for k/v (B*K)

// -------- scratch (device globals; no allocation allowed) --------
__device__ float g_q  [ROWS * EMB];   // scaled q projection  [b*Q+q][h*D+d]
__device__ float g_k  [ROWS * EMB];   // k projection
__device__ float g_v  [ROWS * EMB];   // v projection
__device__ float g_ctx[ROWS * EMB];   // attention context

// ============================================================================
// SGEMM: C[M,N] = alpha * A[M,K] * B[K,N]   (all row-major, dims % tile == 0)
// 128x128 tile, BK=16, 256 threads, 8x8 per-thread microtile.
// ============================================================================
#define GBM 128
#define GBN 128
#define GBK 16

__global__ __launch_bounds__(256, 2)
void sgemm_kernel(const float* __restrict__ A, const float* __restrict__ B,
                  float* __restrict__ C, int M, int N, int K, float alpha)
{
    __shared__ float As[GBK][GBM];
    __shared__ float Bs[GBK][GBN];

    const int tid = threadIdx.x;
    const int tx  = tid % 16;           // 16 cols of threads
    const int ty  = tid / 16;           // 16 rows of threads
    const int block_row = blockIdx.y * GBM;
    const int block_col = blockIdx.x * GBN;

    float acc[8][8];
#pragma unroll
    for (int i = 0; i < 8; i++)
#pragma unroll
        for (int j = 0; j < 8; j++) acc[i][j] = 0.f;

    // A-load mapping: 128x16 tile = 512 float4; thread loads 2
    const int a_r = tid / 4;            // 0..63
    const int a_c = (tid % 4) * 4;      // 0,4,8,12
    // B-load mapping: 16x128 tile = 512 float4; thread loads 2
    const int b_r = tid / 32;           // 0..7
    const int b_c = (tid % 32) * 4;

    for (int k0 = 0; k0 < K; k0 += GBK) {
#pragma unroll
        for (int i = 0; i < 2; i++) {
            const int row = a_r + i * 64;
            float4 v4 = *(const float4*)(A + (size_t)(block_row + row) * K + k0 + a_c);
            As[a_c + 0][row] = v4.x;
            As[a_c + 1][row] = v4.y;
            As[a_c + 2][row] = v4.z;
            As[a_c + 3][row] = v4.w;
        }
#pragma unroll
        for (int i = 0; i < 2; i++) {
            const int row = b_r + i * 8;
            *(float4*)(&Bs[row][b_c]) =
                *(const float4*)(B + (size_t)(k0 + row) * N + block_col + b_c);
        }
        __syncthreads();

#pragma unroll
        for (int kk = 0; kk < GBK; kk++) {
            float ar[8], br[8];
#pragma unroll
            for (int i = 0; i < 8; i += 4) {
                float4 v4 = *(const float4*)(&As[kk][ty * 8 + i]);
                ar[i] = v4.x; ar[i+1] = v4.y; ar[i+2] = v4.z; ar[i+3] = v4.w;
            }
#pragma unroll
            for (int j = 0; j < 8; j += 4) {
                float4 v4 = *(const float4*)(&Bs[kk][tx * 8 + j]);
                br[j] = v4.x; br[j+1] = v4.y; br[j+2] = v4.z; br[j+3] = v4.w;
            }
#pragma unroll
            for (int i = 0; i < 8; i++)
#pragma unroll
                for (int j = 0; j < 8; j++)
                    acc[i][j] += ar[i] * br[j];
        }
        __syncthreads();
    }

#pragma unroll
    for (int i = 0; i < 8; i++) {
        const int row = block_row + ty * 8 + i;
        float* crow = C + (size_t)row * N + block_col + tx * 8;
#pragma unroll
        for (int j = 0; j < 8; j += 4) {
            float4 o;
            o.x = alpha * acc[i][j + 0];
            o.y = alpha * acc[i][j + 1];
            o.z = alpha * acc[i][j + 2];
            o.w = alpha * acc[i][j + 3];
            *(float4*)(crow + j) = o;
        }
    }
}

// ============================================================================
// Flash-style attention for one (b, h, 64-row q-tile) per block.
// 64 threads; thread t owns q-row t of the tile. Online softmax over K in
// chunks of 32. bias [B,1,Q,K] broadcast over heads (L2-friendly).
// ============================================================================
#define AT_BM 64
#define AT_BN 32

__global__ __launch_bounds__(64)
void attn_kernel(const float* __restrict__ q, const float* __restrict__ k,
                 const float* __restrict__ v, const float* __restrict__ bias,
                 float* __restrict__ ctx)
{
    const int qt = blockIdx.x;       // q tile (0..31)
    const int h  = blockIdx.y;       // head
    const int b  = blockIdx.z;       // batch
    const int t  = threadIdx.x;      // 0..63 -> q row within tile

    __shared__ float Ks[AT_BN][DD];
    __shared__ float Vs[AT_BN][DD];
    __shared__ float Bs[AT_BM][AT_BN + 1];   // +1 pad: kill bank conflicts

    const int q_row = qt * AT_BM + t;

    // Load this thread's q row (already scaled by 1/sqrt(D) in projection)
    float qr[DD];
    {
        const float* qptr = q + (size_t)(b * QQ + q_row) * EMB + h * DD;
#pragma unroll
        for (int d = 0; d < DD; d += 4) {
            float4 v4 = *(const float4*)(qptr + d);
            qr[d] = v4.x; qr[d+1] = v4.y; qr[d+2] = v4.z; qr[d+3] = v4.w;
        }
    }

    float ctx_acc[DD];
#pragma unroll
    for (int d = 0; d < DD; d++) ctx_acc[d] = 0.f;
    float m = -1e30f;
    float l = 0.f;

    const float* bias_base = bias + (size_t)b * QQ * KK + (size_t)(qt * AT_BM) * KK;
    const float* kbase0 = k + (size_t)(b * KK) * EMB + h * DD;
    const float* vbase0 = v + (size_t)(b * KK) * EMB + h * DD;

    for (int kc = 0; kc < KK; kc += AT_BN) {
        // ---- stage K/V chunk: 32 rows x 64 cols = 512 float4; 8 per thread
        const float* kbase = kbase0 + (size_t)kc * EMB;
        const float* vbase = vbase0 + (size_t)kc * EMB;
#pragma unroll
        for (int i = 0; i < 8; i++) {
            const int f   = t + i * 64;      // float4 index [0,512)
            const int row = f / 16;          // 16 float4 per 64-col row
            const int col = (f % 16) * 4;
            *(float4*)(&Ks[row][col]) = *(const float4*)(kbase + (size_t)row * EMB + col);
            *(float4*)(&Vs[row][col]) = *(const float4*)(vbase + (size_t)row * EMB + col);
        }
        // ---- stage bias chunk: 64 rows x 32 cols = 512 float4; 8 per thread
#pragma unroll
        for (int i = 0; i < 8; i++) {
            const int f   = t + i * 64;
            const int row = f / 8;           // 8 float4 per 32-col row
            const int col = (f % 8) * 4;
            float4 v4 = *(const float4*)(bias_base + (size_t)row * KK + kc + col);
            Bs[row][col + 0] = v4.x;
            Bs[row][col + 1] = v4.y;
            Bs[row][col + 2] = v4.z;
            Bs[row][col + 3] = v4.w;
        }
        __syncthreads();

        // ---- scores for this thread's row
        float s[AT_BN];
#pragma unroll
        for (int j = 0; j < AT_BN; j++) {
            float dot = 0.f;
#pragma unroll
            for (int d4 = 0; d4 < DD; d4 += 4) {
                float4 kv = *(const float4*)(&Ks[j][d4]);
                dot += qr[d4 + 0] * kv.x;
                dot += qr[d4 + 1] * kv.y;
                dot += qr[d4 + 2] * kv.z;
                dot += qr[d4 + 3] * kv.w;
            }
            s[j] = dot + Bs[t][j];
        }

        // ---- online softmax update
        float cmax = m;
#pragma unroll
        for (int j = 0; j < AT_BN; j++) cmax = fmaxf(cmax, s[j]);
        const float scale = __expf(m - cmax);
        m = cmax;
        float lsum = 0.f;
#pragma unroll
        for (int j = 0; j < AT_BN; j++) {
            s[j] = __expf(s[j] - m);
            lsum += s[j];
        }
        l = l * scale + lsum;
#pragma unroll
        for (int d = 0; d < DD; d++) ctx_acc[d] *= scale;
#pragma unroll
        for (int j = 0; j < AT_BN; j++) {
            const float p = s[j];
#pragma unroll
            for (int d4 = 0; d4 < DD; d4 += 4) {
                float4 vv = *(const float4*)(&Vs[j][d4]);
                ctx_acc[d4 + 0] += p * vv.x;
                ctx_acc[d4 + 1] += p * vv.y;
                ctx_acc[d4 + 2] += p * vv.z;
                ctx_acc[d4 + 3] += p * vv.w;
            }
        }
        __syncthreads();
    }

    const float inv = 1.f / l;
    float* out = ctx + (size_t)(b * QQ + q_row) * EMB + h * DD;
#pragma unroll
    for (int d = 0; d < DD; d += 4) {
        float4 o;
        o.x = ctx_acc[d + 0] * inv;
        o.y = ctx_acc[d + 1] * inv;
        o.z = ctx_acc[d + 2] * inv;
        o.w = ctx_acc[d + 3] * inv;
        *(float4*)(out + d) = o;
    }
}

// ============================================================================
// Launch
// inputs: 0=inputs_q [B,Q,EMB], 1=inputs_kv [B,K,EMB], 2=bias [B,1,Q,K],
//         3=wq [EMB,H,D], 4=wk, 5=wv, 6=wo [H,D,EMB]
// output: [B,Q,EMB] fp32
// ============================================================================
extern "C" void kernel_launch(void* const* d_in, const int* in_sizes, int n_in,
                              void* d_out, int out_size)
{
    const float* inputs_q  = (const float*)d_in[0];
    const float* inputs_kv = (const float*)d_in[1];
    const float* bias      = (const float*)d_in[2];
    const float* wq        = (const float*)d_in[3];
    const float* wk        = (const float*)d_in[4];
    const float* wv        = (const float*)d_in[5];
    const float* wo        = (const float*)d_in[6];
    float* out = (float*)d_out;

    float *p_q, *p_k, *p_v, *p_ctx;
    cudaGetSymbolAddress((void**)&p_q,   g_q);
    cudaGetSymbolAddress((void**)&p_k,   g_k);
    cudaGetSymbolAddress((void**)&p_v,   g_v);
    cudaGetSymbolAddress((void**)&p_ctx, g_ctx);

    const dim3 gemm_grid(EMB / GBN, ROWS / GBM);   // (16, 32)
    const dim3 gemm_blk(256);

    // Projections. wq/wk/wv are [EMB, H*D] row-major; q scaled by 1/sqrt(D).
    sgemm_kernel<<<gemm_grid, gemm_blk>>>(inputs_q,  wq, p_q, ROWS, EMB, EMB, 0.125f);
    sgemm_kernel<<<gemm_grid, gemm_blk>>>(inputs_kv, wk, p_k, ROWS, EMB, EMB, 1.0f);
    sgemm_kernel<<<gemm_grid, gemm_blk>>>(inputs_kv, wv, p_v, ROWS, EMB, EMB, 1.0f);

    // Attention: grid (q-tiles, heads, batch)
    attn_kernel<<<dim3(QQ / AT_BM, HH, BB), 64>>>(p_q, p_k, p_v, bias, p_ctx);

    // Output projection: ctx [ROWS, H*D] x wo [H*D, EMB] -> out
    sgemm_kernel<<<gemm_grid, gemm_blk>>>(p_ctx, wo, out, ROWS, EMB, EMB, 1.0f);
}

// round 2
// speedup vs baseline: 1.0722x; 1.0722x over previous
#include <cuda_runtime.h>
#include <cstdint>

// Problem constants
#define BB   2
#define QQ   2048
#define KK   2048
#define EMB  2048
#define HH   32
#define DD   64
#define ROWS (BB * QQ)

// -------- scratch (device globals; no allocation allowed) --------
__device__ float g_q  [ROWS * EMB];
__device__ float g_k  [ROWS * EMB];
__device__ float g_v  [ROWS * EMB];
__device__ float g_ctx[ROWS * EMB];

// ---------------- f32x2 packed helpers (sm_100+) ----------------
typedef unsigned long long u64t;

__device__ __forceinline__ u64t pack_dup(float x) {
    u64t r;
    asm("mov.b64 %0, {%1, %1};" : "=l"(r) : "f"(x));
    return r;
}
__device__ __forceinline__ void unpack2(u64t v, float& lo, float& hi) {
    asm("mov.b64 {%0, %1}, %2;" : "=f"(lo), "=f"(hi) : "l"(v));
}
__device__ __forceinline__ void fma2(u64t& d, u64t a, u64t b) {
    asm("fma.rn.f32x2 %0, %1, %2, %0;" : "+l"(d) : "l"(a), "l"(b));
}
__device__ __forceinline__ void mul2(u64t& d, u64t s) {
    asm("mul.rn.f32x2 %0, %0, %1;" : "+l"(d) : "l"(s));
}

// ============================================================================
// SGEMM: C[M,N] = alpha * A[M,K] * B[K,N]  (row-major, dims % tile == 0)
// 128x128 tile, BK=16, 256 threads, 8x8 microtile via packed f32x2 FMA.
// Accumulators paired along i (rows): a-pairs free from float4 smem loads.
// ============================================================================
#define GBM 128
#define GBN 128
#define GBK 16

__global__ __launch_bounds__(256, 2)
void sgemm_kernel(const float* __restrict__ A, const float* __restrict__ B,
                  float* __restrict__ C, int M, int N, int K, float alpha)
{
    __shared__ float As[GBK][GBM];
    __shared__ float Bs[GBK][GBN];

    const int tid = threadIdx.x;
    const int tx  = tid % 16;
    const int ty  = tid / 16;
    const int block_row = blockIdx.y * GBM;
    const int block_col = blockIdx.x * GBN;

    u64t acc2[4][8];   // [row-pair][col]: (acc[2i][j], acc[2i+1][j])
#pragma unroll
    for (int i = 0; i < 4; i++)
#pragma unroll
        for (int j = 0; j < 8; j++) acc2[i][j] = 0ull;

    const int a_r = tid / 4;
    const int a_c = (tid % 4) * 4;
    const int b_r = tid / 32;
    const int b_c = (tid % 32) * 4;

    for (int k0 = 0; k0 < K; k0 += GBK) {
#pragma unroll
        for (int i = 0; i < 2; i++) {
            const int row = a_r + i * 64;
            float4 v4 = *(const float4*)(A + (size_t)(block_row + row) * K + k0 + a_c);
            As[a_c + 0][row] = v4.x;
            As[a_c + 1][row] = v4.y;
            As[a_c + 2][row] = v4.z;
            As[a_c + 3][row] = v4.w;
        }
#pragma unroll
        for (int i = 0; i < 2; i++) {
            const int row = b_r + i * 8;
            *(float4*)(&Bs[row][b_c]) =
                *(const float4*)(B + (size_t)(k0 + row) * N + block_col + b_c);
        }
        __syncthreads();

#pragma unroll
        for (int kk = 0; kk < GBK; kk++) {
            // a row-pairs: direct 128-bit smem loads reinterpreted as 2x f32-pair
            ulonglong2 a0 = *(const ulonglong2*)(&As[kk][ty * 8]);
            ulonglong2 a1 = *(const ulonglong2*)(&As[kk][ty * 8 + 4]);
            u64t ap[4] = {a0.x, a0.y, a1.x, a1.y};

            float br[8];
#pragma unroll
            for (int j = 0; j < 8; j += 4) {
                float4 v4 = *(const float4*)(&Bs[kk][tx * 8 + j]);
                br[j] = v4.x; br[j+1] = v4.y; br[j+2] = v4.z; br[j+3] = v4.w;
            }
            u64t bd[8];
#pragma unroll
            for (int j = 0; j < 8; j++) bd[j] = pack_dup(br[j]);

#pragma unroll
            for (int i = 0; i < 4; i++)
#pragma unroll
                for (int j = 0; j < 8; j++)
                    fma2(acc2[i][j], ap[i], bd[j]);
        }
        __syncthreads();
    }

    // epilogue: unpack pairs, scale, store
#pragma unroll
    for (int i2 = 0; i2 < 4; i2++) {
        float r0[8], r1[8];
#pragma unroll
        for (int j = 0; j < 8; j++) unpack2(acc2[i2][j], r0[j], r1[j]);

        const int row0 = block_row + ty * 8 + i2 * 2;
        float* c0 = C + (size_t)row0 * N + block_col + tx * 8;
        float* c1 = c0 + N;
#pragma unroll
        for (int j = 0; j < 8; j += 4) {
            float4 o0, o1;
            o0.x = alpha * r0[j]; o0.y = alpha * r0[j+1]; o0.z = alpha * r0[j+2]; o0.w = alpha * r0[j+3];
            o1.x = alpha * r1[j]; o1.y = alpha * r1[j+1]; o1.z = alpha * r1[j+2]; o1.w = alpha * r1[j+3];
            *(float4*)(c0 + j) = o0;
            *(float4*)(c1 + j) = o1;
        }
    }
}

// ============================================================================
// Flash-style attention, one (b, h, 64-row q-tile) per block, 64 threads.
// Inner products via packed f32x2 FMA paired along d.
// ============================================================================
#define AT_BM 64
#define AT_BN 32

__global__ __launch_bounds__(64)
void attn_kernel(const float* __restrict__ q, const float* __restrict__ k,
                 const float* __restrict__ v, const float* __restrict__ bias,
                 float* __restrict__ ctx)
{
    const int qt = blockIdx.x;
    const int h  = blockIdx.y;
    const int b  = blockIdx.z;
    const int t  = threadIdx.x;

    __shared__ float Ks[AT_BN][DD];
    __shared__ float Vs[AT_BN][DD];
    __shared__ float Bs[AT_BM][AT_BN + 1];

    const int q_row = qt * AT_BM + t;

    // q row as 32 packed pairs
    u64t qr2[DD / 2];
    {
        const float* qptr = q + (size_t)(b * QQ + q_row) * EMB + h * DD;
#pragma unroll
        for (int d4 = 0; d4 < DD; d4 += 4) {
            ulonglong2 v2 = *(const ulonglong2*)(qptr + d4);
            qr2[d4 / 2]     = v2.x;
            qr2[d4 / 2 + 1] = v2.y;
        }
    }

    u64t ctx2[DD / 2];
#pragma unroll
    for (int i = 0; i < DD / 2; i++) ctx2[i] = 0ull;
    float m = -1e30f;
    float l = 0.f;

    const float* bias_base = bias + (size_t)b * QQ * KK + (size_t)(qt * AT_BM) * KK;
    const float* kbase0 = k + (size_t)(b * KK) * EMB + h * DD;
    const float* vbase0 = v + (size_t)(b * KK) * EMB + h * DD;

    for (int kc = 0; kc < KK; kc += AT_BN) {
        const float* kbase = kbase0 + (size_t)kc * EMB;
        const float* vbase = vbase0 + (size_t)kc * EMB;
#pragma unroll
        for (int i = 0; i < 8; i++) {
            const int f   = t + i * 64;
            const int row = f / 16;
            const int col = (f % 16) * 4;
            *(float4*)(&Ks[row][col]) = *(const float4*)(kbase + (size_t)row * EMB + col);
            *(float4*)(&Vs[row][col]) = *(const float4*)(vbase + (size_t)row * EMB + col);
        }
#pragma unroll
        for (int i = 0; i < 8; i++) {
            const int f   = t + i * 64;
            const int row = f / 8;
            const int col = (f % 8) * 4;
            float4 v4 = *(const float4*)(bias_base + (size_t)row * KK + kc + col);
            Bs[row][col + 0] = v4.x;
            Bs[row][col + 1] = v4.y;
            Bs[row][col + 2] = v4.z;
            Bs[row][col + 3] = v4.w;
        }
        __syncthreads();

        // ---- scores (packed dot products)
        float s[AT_BN];
#pragma unroll
        for (int j = 0; j < AT_BN; j++) {
            u64t dot2 = 0ull;
#pragma unroll
            for (int d4 = 0; d4 < DD; d4 += 4) {
                ulonglong2 kv = *(const ulonglong2*)(&Ks[j][d4]);
                fma2(dot2, qr2[d4 / 2],     kv.x);
                fma2(dot2, qr2[d4 / 2 + 1], kv.y);
            }
            float lo, hi;
            unpack2(dot2, lo, hi);
            s[j] = lo + hi + Bs[t][j];
        }

        // ---- online softmax update
        float cmax = m;
#pragma unroll
        for (int j = 0; j < AT_BN; j++) cmax = fmaxf(cmax, s[j]);
        const float scale = __expf(m - cmax);
        m = cmax;
        float lsum = 0.f;
#pragma unroll
        for (int j = 0; j < AT_BN; j++) {
            s[j] = __expf(s[j] - m);
            lsum += s[j];
        }
        l = l * scale + lsum;

        const u64t scale2 = pack_dup(scale);
#pragma unroll
        for (int i = 0; i < DD / 2; i++) mul2(ctx2[i], scale2);

#pragma unroll
        for (int j = 0; j < AT_BN; j++) {
            const u64t p2 = pack_dup(s[j]);
#pragma unroll
            for (int d4 = 0; d4 < DD; d4 += 4) {
                ulonglong2 vv = *(const ulonglong2*)(&Vs[j][d4]);
                fma2(ctx2[d4 / 2],     p2, vv.x);
                fma2(ctx2[d4 / 2 + 1], p2, vv.y);
            }
        }
        __syncthreads();
    }

    const float inv = 1.f / l;
    float* out = ctx + (size_t)(b * QQ + q_row) * EMB + h * DD;
#pragma unroll
    for (int d4 = 0; d4 < DD; d4 += 4) {
        float l0, h0, l1, h1;
        unpack2(ctx2[d4 / 2],     l0, h0);
        unpack2(ctx2[d4 / 2 + 1], l1, h1);
        float4 o;
        o.x = l0 * inv; o.y = h0 * inv; o.z = l1 * inv; o.w = h1 * inv;
        *(float4*)(out + d4) = o;
    }
}

// ============================================================================
// Launch
// ============================================================================
extern "C" void kernel_launch(void* const* d_in, const int* in_sizes, int n_in,
                              void* d_out, int out_size)
{
    const float* inputs_q  = (const float*)d_in[0];
    const float* inputs_kv = (const float*)d_in[1];
    const float* bias      = (const float*)d_in[2];
    const float* wq        = (const float*)d_in[3];
    const float* wk        = (const float*)d_in[4];
    const float* wv        = (const float*)d_in[5];
    const float* wo        = (const float*)d_in[6];
    float* out = (float*)d_out;

    float *p_q, *p_k, *p_v, *p_ctx;
    cudaGetSymbolAddress((void**)&p_q,   g_q);
    cudaGetSymbolAddress((void**)&p_k,   g_k);
    cudaGetSymbolAddress((void**)&p_v,   g_v);
    cudaGetSymbolAddress((void**)&p_ctx, g_ctx);

    const dim3 gemm_grid(EMB / GBN, ROWS / GBM);
    const dim3 gemm_blk(256);

    sgemm_kernel<<<gemm_grid, gemm_blk>>>(inputs_q,  wq, p_q, ROWS, EMB, EMB, 0.125f);
    sgemm_kernel<<<gemm_grid, gemm_blk>>>(inputs_kv, wk, p_k, ROWS, EMB, EMB, 1.0f);
    sgemm_kernel<<<gemm_grid, gemm_blk>>>(inputs_kv, wv, p_v, ROWS, EMB, EMB, 1.0f);

    attn_kernel<<<dim3(QQ / AT_BM, HH, BB), 64>>>(p_q, p_k, p_v, bias, p_ctx);

    sgemm_kernel<<<gemm_grid, gemm_blk>>>(p_ctx, wo, out, ROWS, EMB, EMB, 1.0f);
}

// round 4
// speedup vs baseline: 1.5142x; 1.4123x over previous
#include <cuda_runtime.h>
#include <cuda_bf16.h>
#include <cstdint>

// Problem constants
#define BB   2
#define QQ   2048
#define KK   2048
#define EMB  2048
#define HH   32
#define DD   64
#define ROWS (BB * QQ)          // 4096

// ---------------- scratch (device globals; no allocation allowed) ----------
__device__ float g_q  [ROWS * EMB];
__device__ float g_k  [ROWS * EMB];
__device__ float g_v  [ROWS * EMB];
__device__ float g_ctx[ROWS * EMB];

__device__ __nv_bfloat16 g_aq_h [ROWS * EMB];
__device__ __nv_bfloat16 g_aq_l [ROWS * EMB];
__device__ __nv_bfloat16 g_akv_h[ROWS * EMB];
__device__ __nv_bfloat16 g_akv_l[ROWS * EMB];
__device__ __nv_bfloat16 g_ac_h [ROWS * EMB];
__device__ __nv_bfloat16 g_ac_l [ROWS * EMB];

__device__ __nv_bfloat16 g_wqt_h[EMB * EMB];
__device__ __nv_bfloat16 g_wqt_l[EMB * EMB];
__device__ __nv_bfloat16 g_wkt_h[EMB * EMB];
__device__ __nv_bfloat16 g_wkt_l[EMB * EMB];
__device__ __nv_bfloat16 g_wvt_h[EMB * EMB];
__device__ __nv_bfloat16 g_wvt_l[EMB * EMB];
__device__ __nv_bfloat16 g_wot_h[EMB * EMB];
__device__ __nv_bfloat16 g_wot_l[EMB * EMB];

// ---------------- helpers ---------------------------------------------------
typedef unsigned long long u64t;

__device__ __forceinline__ u64t pack_dup(float x) {
    u64t r; asm("mov.b64 %0, {%1, %1};" : "=l"(r) : "f"(x)); return r;
}
__device__ __forceinline__ void unpack2(u64t v, float& lo, float& hi) {
    asm("mov.b64 {%0, %1}, %2;" : "=f"(lo), "=f"(hi) : "l"(v));
}
__device__ __forceinline__ void fma2(u64t& d, u64t a, u64t b) {
    asm("fma.rn.f32x2 %0, %1, %2, %0;" : "+l"(d) : "l"(a), "l"(b));
}
__device__ __forceinline__ void mul2(u64t& d, u64t s) {
    asm("mul.rn.f32x2 %0, %0, %1;" : "+l"(d) : "l"(s));
}
__device__ __forceinline__ uint32_t smem_u32(const void* p) {
    uint32_t a;
    asm("{ .reg .u64 t; cvta.to.shared.u64 t, %1; cvt.u32.u64 %0, t; }"
        : "=r"(a) : "l"(p));
    return a;
}

#define CP_ASYNC16(dst, src) \
    asm volatile("cp.async.cg.shared.global [%0], [%1], 16;" :: "r"(dst), "l"(src))
#define CP_COMMIT() asm volatile("cp.async.commit_group;" ::: "memory")
#define CP_WAIT(n)  asm volatile("cp.async.wait_group %0;" :: "n"(n) : "memory")

__device__ __forceinline__ void ldsm_x4(uint32_t* d, uint32_t addr) {
    asm volatile("ldmatrix.sync.aligned.m8n8.x4.shared.b16 {%0,%1,%2,%3}, [%4];"
                 : "=r"(d[0]), "=r"(d[1]), "=r"(d[2]), "=r"(d[3]) : "r"(addr));
}
__device__ __forceinline__ void ldsm_x2(uint32_t* d, uint32_t addr) {
    asm volatile("ldmatrix.sync.aligned.m8n8.x2.shared.b16 {%0,%1}, [%2];"
                 : "=r"(d[0]), "=r"(d[1]) : "r"(addr));
}
__device__ __forceinline__ void mma16816(float* d, const uint32_t* a, const uint32_t* b) {
    asm volatile(
        "mma.sync.aligned.m16n8k16.row.col.f32.bf16.bf16.f32 "
        "{%0,%1,%2,%3}, {%4,%5,%6,%7}, {%8,%9}, {%0,%1,%2,%3};"
        : "+f"(d[0]), "+f"(d[1]), "+f"(d[2]), "+f"(d[3])
        : "r"(a[0]), "r"(a[1]), "r"(a[2]), "r"(a[3]), "r"(b[0]), "r"(b[1]));
}

// ============================================================================
// fp32 -> bf16 hi/lo split (elementwise)
// ============================================================================
__global__ __launch_bounds__(256)
void split_kernel(const float* __restrict__ x, __nv_bfloat16* __restrict__ hi,
                  __nv_bfloat16* __restrict__ lo, int n)
{
    int i = (blockIdx.x * 256 + threadIdx.x) * 4;
    if (i >= n) return;
    float4 v = *(const float4*)(x + i);
    __nv_bfloat16 h0 = __float2bfloat16(v.x);
    __nv_bfloat16 h1 = __float2bfloat16(v.y);
    __nv_bfloat16 h2 = __float2bfloat16(v.z);
    __nv_bfloat16 h3 = __float2bfloat16(v.w);
    __nv_bfloat16 l0 = __float2bfloat16(v.x - __bfloat162float(h0));
    __nv_bfloat16 l1 = __float2bfloat16(v.y - __bfloat162float(h1));
    __nv_bfloat16 l2 = __float2bfloat16(v.z - __bfloat162float(h2));
    __nv_bfloat16 l3 = __float2bfloat16(v.w - __bfloat162float(h3));
    __nv_bfloat162* ph = (__nv_bfloat162*)(hi + i);
    __nv_bfloat162* pl = (__nv_bfloat162*)(lo + i);
    ph[0] = __nv_bfloat162(h0, h1);
    ph[1] = __nv_bfloat162(h2, h3);
    pl[0] = __nv_bfloat162(l0, l1);
    pl[1] = __nv_bfloat162(l2, l3);
}

// ============================================================================
// Weight transpose + split:  w [R][C] fp32 -> wt hi/lo [C][R] bf16  (R=C=2048)
// ============================================================================
__global__ __launch_bounds__(256)
void wsplit_kernel(const float* __restrict__ w, __nv_bfloat16* __restrict__ th,
                   __nv_bfloat16* __restrict__ tl)
{
    __shared__ float tile[32][33];
    const int bx = blockIdx.x * 32;
    const int by = blockIdx.y * 32;
    const int tx = threadIdx.x % 32;
    const int ty = threadIdx.x / 32;
#pragma unroll
    for (int j = 0; j < 32; j += 8)
        tile[ty + j][tx] = w[(size_t)(by + ty + j) * 2048 + bx + tx];
    __syncthreads();
#pragma unroll
    for (int j = 0; j < 32; j += 8) {
        float v = tile[tx][ty + j];
        __nv_bfloat16 h = __float2bfloat16(v);
        __nv_bfloat16 l = __float2bfloat16(v - __bfloat162float(h));
        th[(size_t)(bx + ty + j) * 2048 + by + tx] = h;
        tl[(size_t)(bx + ty + j) * 2048 + by + tx] = l;
    }
}

// ============================================================================
// bf16-split GEMM on mma.sync (tensor pipe):
//   C[4096,2048] = alpha * (Ah*Bh^T + Ah*Bl^T + Al*Bh^T)
// A*: [4096][2048] bf16 row-major;  B*: [2048][2048] bf16 row-major [N][K].
// CTA tile 128x128, 8 warps (2x4), warp tile 64x32, K-chunk 32, cp.async
// double buffer, 3 passes fused into one 192-chunk loop.
// ============================================================================
#define GSTRIDE 40      // bf16 elements per smem row (80 B, conflict-free ldmatrix)
#define NCHUNK  192     // 3 passes x 64 chunks of K=32

__global__ __launch_bounds__(256)
void gemm_bf16_mma(const __nv_bfloat16* __restrict__ Ah,
                   const __nv_bfloat16* __restrict__ Al,
                   const __nv_bfloat16* __restrict__ Bh,
                   const __nv_bfloat16* __restrict__ Bl,
                   float* __restrict__ C, float alpha)
{
    __shared__ __align__(16) __nv_bfloat16 As[2][128 * GSTRIDE];
    __shared__ __align__(16) __nv_bfloat16 Bs[2][128 * GSTRIDE];

    const int tid  = threadIdx.x;
    const int wid  = tid / 32;
    const int lane = tid % 32;
    const int block_row = blockIdx.y * 128;
    const int block_col = blockIdx.x * 128;

    const int wm = (wid & 1) * 64;       // warp m base within tile
    const int wn = (wid >> 1) * 32;      // warp n base within tile

    // ---- loader mapping: 512 16B-granules per operand; 2 per thread
    const int r0 = tid >> 2;             // rows 0..63
    const int kq = (tid & 3) * 8;        // k element offset (8 bf16 = 16B)
    const size_t a_off0 = (size_t)(block_row + r0)      * 2048 + kq;
    const size_t a_off1 = (size_t)(block_row + r0 + 64) * 2048 + kq;
    const size_t b_off0 = (size_t)(block_col + r0)      * 2048 + kq;
    const size_t b_off1 = (size_t)(block_col + r0 + 64) * 2048 + kq;
    const uint32_t sA0 = smem_u32(&As[0][0]);
    const uint32_t sB0 = smem_u32(&Bs[0][0]);
    const uint32_t d0 = r0 * 80 + (tid & 3) * 16;
    const uint32_t d1 = (r0 + 64) * 80 + (tid & 3) * 16;

    // ---- ldmatrix per-lane offsets (bytes)
    const uint32_t a_lm = (wm + (lane & 15)) * 80 + (lane >> 4) * 16;
    const uint32_t b_lm = (wn + (lane & 7)) * 80 + ((lane >> 3) & 1) * 16;

    float acc[4][4][4];
#pragma unroll
    for (int i = 0; i < 4; i++)
#pragma unroll
        for (int j = 0; j < 4; j++)
#pragma unroll
            for (int r = 0; r < 4; r++) acc[i][j][r] = 0.f;

    // ---- prologue: load chunk 0 into buf 0
    {
        const __nv_bfloat16* Ap = Ah;
        const __nv_bfloat16* Bp = Bh;
        CP_ASYNC16(sA0 + d0, Ap + a_off0);
        CP_ASYNC16(sA0 + d1, Ap + a_off1);
        CP_ASYNC16(sB0 + d0, Bp + b_off0);
        CP_ASYNC16(sB0 + d1, Bp + b_off1);
        CP_COMMIT();
    }

    for (int i = 0; i < NCHUNK; i++) {
        const int buf = i & 1;
        // issue loads for chunk i+1 into the other buffer
        if (i + 1 < NCHUNK) {
            const int n  = i + 1;
            const int p  = n >> 6;
            const int kk = (n & 63) * 32;
            const __nv_bfloat16* Ap = (p == 2) ? Al : Ah;
            const __nv_bfloat16* Bp = (p == 1) ? Bl : Bh;
            const uint32_t sa = sA0 + (buf ^ 1) * (128 * GSTRIDE * 2);
            const uint32_t sbm = sB0 + (buf ^ 1) * (128 * GSTRIDE * 2);
            CP_ASYNC16(sa + d0,  Ap + a_off0 + kk);
            CP_ASYNC16(sa + d1,  Ap + a_off1 + kk);
            CP_ASYNC16(sbm + d0, Bp + b_off0 + kk);
            CP_ASYNC16(sbm + d1, Bp + b_off1 + kk);
            CP_COMMIT();
            CP_WAIT(1);
        } else {
            CP_WAIT(0);
        }
        __syncthreads();

        const uint32_t sa = sA0 + buf * (128 * GSTRIDE * 2);
        const uint32_t sbm = sB0 + buf * (128 * GSTRIDE * 2);
#pragma unroll
        for (int ks = 0; ks < 2; ks++) {
            uint32_t afrag[4][4], bfrag[4][2];
#pragma unroll
            for (int mt = 0; mt < 4; mt++)
                ldsm_x4(afrag[mt], sa + a_lm + mt * (16 * 80) + ks * 32);
#pragma unroll
            for (int nt = 0; nt < 4; nt++)
                ldsm_x2(bfrag[nt], sbm + b_lm + nt * (8 * 80) + ks * 32);
#pragma unroll
            for (int mt = 0; mt < 4; mt++)
#pragma unroll
                for (int nt = 0; nt < 4; nt++)
                    mma16816(acc[mt][nt], afrag[mt], bfrag[nt]);
        }
        __syncthreads();
    }

    // ---- epilogue
#pragma unroll
    for (int mt = 0; mt < 4; mt++) {
        const int row = block_row + wm + mt * 16 + lane / 4;
#pragma unroll
        for (int nt = 0; nt < 4; nt++) {
            const int col = block_col + wn + nt * 8 + (lane % 4) * 2;
            float2 v0, v1;
            v0.x = alpha * acc[mt][nt][0];
            v0.y = alpha * acc[mt][nt][1];
            v1.x = alpha * acc[mt][nt][2];
            v1.y = alpha * acc[mt][nt][3];
            *(float2*)(C + (size_t)row * 2048 + col)       = v0;
            *(float2*)(C + (size_t)(row + 8) * 2048 + col) = v1;
        }
    }
}

// ============================================================================
// Flash-style attention (unchanged): one (b, h, 64-q-row tile) per block.
// ============================================================================
#define AT_BM 64
#define AT_BN 32

__global__ __launch_bounds__(64)
void attn_kernel(const float* __restrict__ q, const float* __restrict__ k,
                 const float* __restrict__ v, const float* __restrict__ bias,
                 float* __restrict__ ctx)
{
    const int qt = blockIdx.x;
    const int h  = blockIdx.y;
    const int b  = blockIdx.z;
    const int t  = threadIdx.x;

    __shared__ float Ks[AT_BN][DD];
    __shared__ float Vs[AT_BN][DD];
    __shared__ float Bsm[AT_BM][AT_BN + 1];

    const int q_row = qt * AT_BM + t;

    u64t qr2[DD / 2];
    {
        const float* qptr = q + (size_t)(b * QQ + q_row) * EMB + h * DD;
#pragma unroll
        for (int d4 = 0; d4 < DD; d4 += 4) {
            ulonglong2 v2 = *(const ulonglong2*)(qptr + d4);
            qr2[d4 / 2]     = v2.x;
            qr2[d4 / 2 + 1] = v2.y;
        }
    }

    u64t ctx2[DD / 2];
#pragma unroll
    for (int i = 0; i < DD / 2; i++) ctx2[i] = 0ull;
    float m = -1e30f;
    float l = 0.f;

    const float* bias_base = bias + (size_t)b * QQ * KK + (size_t)(qt * AT_BM) * KK;
    const float* kbase0 = k + (size_t)(b * KK) * EMB + h * DD;
    const float* vbase0 = v + (size_t)(b * KK) * EMB + h * DD;

    for (int kc = 0; kc < KK; kc += AT_BN) {
        const float* kbase = kbase0 + (size_t)kc * EMB;
        const float* vbase = vbase0 + (size_t)kc * EMB;
#pragma unroll
        for (int i = 0; i < 8; i++) {
            const int f   = t + i * 64;
            const int row = f / 16;
            const int col = (f % 16) * 4;
            *(float4*)(&Ks[row][col]) = *(const float4*)(kbase + (size_t)row * EMB + col);
            *(float4*)(&Vs[row][col]) = *(const float4*)(vbase + (size_t)row * EMB + col);
        }
#pragma unroll
        for (int i = 0; i < 8; i++) {
            const int f   = t + i * 64;
            const int row = f / 8;
            const int col = (f % 8) * 4;
            float4 v4 = *(const float4*)(bias_base + (size_t)row * KK + kc + col);
            Bsm[row][col + 0] = v4.x;
            Bsm[row][col + 1] = v4.y;
            Bsm[row][col + 2] = v4.z;
            Bsm[row][col + 3] = v4.w;
        }
        __syncthreads();

        float s[AT_BN];
#pragma unroll
        for (int j = 0; j < AT_BN; j++) {
            u64t dot2 = 0ull;
#pragma unroll
            for (int d4 = 0; d4 < DD; d4 += 4) {
                ulonglong2 kv = *(const ulonglong2*)(&Ks[j][d4]);
                fma2(dot2, qr2[d4 / 2],     kv.x);
                fma2(dot2, qr2[d4 / 2 + 1], kv.y);
            }
            float lo, hi;
            unpack2(dot2, lo, hi);
            s[j] = lo + hi + Bsm[t][j];
        }

        float cmax = m;
#pragma unroll
        for (int j = 0; j < AT_BN; j++) cmax = fmaxf(cmax, s[j]);
        const float scale = __expf(m - cmax);
        m = cmax;
        float lsum = 0.f;
#pragma unroll
        for (int j = 0; j < AT_BN; j++) {
            s[j] = __expf(s[j] - m);
            lsum += s[j];
        }
        l = l * scale + lsum;

        const u64t scale2 = pack_dup(scale);
#pragma unroll
        for (int i = 0; i < DD / 2; i++) mul2(ctx2[i], scale2);

#pragma unroll
        for (int j = 0; j < AT_BN; j++) {
            const u64t p2 = pack_dup(s[j]);
#pragma unroll
            for (int d4 = 0; d4 < DD; d4 += 4) {
                ulonglong2 vv = *(const ulonglong2*)(&Vs[j][d4]);
                fma2(ctx2[d4 / 2],     p2, vv.x);
                fma2(ctx2[d4 / 2 + 1], p2, vv.y);
            }
        }
        __syncthreads();
    }

    const float inv = 1.f / l;
    float* out = ctx + (size_t)(b * QQ + q_row) * EMB + h * DD;
#pragma unroll
    for (int d4 = 0; d4 < DD; d4 += 4) {
        float l0, h0, l1, h1;
        unpack2(ctx2[d4 / 2],     l0, h0);
        unpack2(ctx2[d4 / 2 + 1], l1, h1);
        float4 o;
        o.x = l0 * inv; o.y = h0 * inv; o.z = l1 * inv; o.w = h1 * inv;
        *(float4*)(out + d4) = o;
    }
}

// ============================================================================
// Launch
// ============================================================================
extern "C" void kernel_launch(void* const* d_in, const int* in_sizes, int n_in,
                              void* d_out, int out_size)
{
    const float* inputs_q  = (const float*)d_in[0];
    const float* inputs_kv = (const float*)d_in[1];
    const float* bias      = (const float*)d_in[2];
    const float* wq        = (const float*)d_in[3];
    const float* wk        = (const float*)d_in[4];
    const float* wv        = (const float*)d_in[5];
    const float* wo        = (const float*)d_in[6];
    float* out = (float*)d_out;

    float *p_q, *p_k, *p_v, *p_ctx;
    cudaGetSymbolAddress((void**)&p_q,   g_q);
    cudaGetSymbolAddress((void**)&p_k,   g_k);
    cudaGetSymbolAddress((void**)&p_v,   g_v);
    cudaGetSymbolAddress((void**)&p_ctx, g_ctx);

    __nv_bfloat16 *aq_h, *aq_l, *akv_h, *akv_l, *ac_h, *ac_l;
    __nv_bfloat16 *wqt_h, *wqt_l, *wkt_h, *wkt_l, *wvt_h, *wvt_l, *wot_h, *wot_l;
    cudaGetSymbolAddress((void**)&aq_h,  g_aq_h);
    cudaGetSymbolAddress((void**)&aq_l,  g_aq_l);
    cudaGetSymbolAddress((void**)&akv_h, g_akv_h);
    cudaGetSymbolAddress((void**)&akv_l, g_akv_l);
    cudaGetSymbolAddress((void**)&ac_h,  g_ac_h);
    cudaGetSymbolAddress((void**)&ac_l,  g_ac_l);
    cudaGetSymbolAddress((void**)&wqt_h, g_wqt_h);
    cudaGetSymbolAddress((void**)&wqt_l, g_wqt_l);
    cudaGetSymbolAddress((void**)&wkt_h, g_wkt_h);
    cudaGetSymbolAddress((void**)&wkt_l, g_wkt_l);
    cudaGetSymbolAddress((void**)&wvt_h, g_wvt_h);
    cudaGetSymbolAddress((void**)&wvt_l, g_wvt_l);
    cudaGetSymbolAddress((void**)&wot_h, g_wot_h);
    cudaGetSymbolAddress((void**)&wot_l, g_wot_l);

    const int n_act = ROWS * EMB;
    const int split_grid = n_act / 4 / 256;
    const dim3 wgrid(64, 64);
    const dim3 ggrid(EMB / 128, ROWS / 128);   // (16, 32)

    // Operand prep
    split_kernel<<<split_grid, 256>>>(inputs_q,  aq_h,  aq_l,  n_act);
    split_kernel<<<split_grid, 256>>>(inputs_kv, akv_h, akv_l, n_act);
    wsplit_kernel<<<wgrid, 256>>>(wq, wqt_h, wqt_l);
    wsplit_kernel<<<wgrid, 256>>>(wk, wkt_h, wkt_l);
    wsplit_kernel<<<wgrid, 256>>>(wv, wvt_h, wvt_l);
    wsplit_kernel<<<wgrid, 256>>>(wo, wot_h, wot_l);

    // Projections on tensor cores (q scaled by 1/sqrt(D))
    gemm_bf16_mma<<<ggrid, 256>>>(aq_h,  aq_l,  wqt_h, wqt_l, p_q, 0.125f);
    gemm_bf16_mma<<<ggrid, 256>>>(akv_h, akv_l, wkt_h, wkt_l, p_k, 1.0f);
    gemm_bf16_mma<<<ggrid, 256>>>(akv_h, akv_l, wvt_h, wvt_l, p_v, 1.0f);

    // Attention
    attn_kernel<<<dim3(QQ / AT_BM, HH, BB), 64>>>(p_q, p_k, p_v, bias, p_ctx);

    // Output projection
    split_kernel<<<split_grid, 256>>>(p_ctx, ac_h, ac_l, n_act);
    gemm_bf16_mma<<<ggrid, 256>>>(ac_h, ac_l, wot_h, wot_l, out, 1.0f);
}

// round 6
// speedup vs baseline: 2.4703x; 1.6314x over previous
#include <cuda_runtime.h>
#include <cuda_bf16.h>
#include <cstdint>

// Problem constants
#define BB   2
#define QQ   2048
#define KK   2048
#define EMB  2048
#define HH   32
#define DD   64
#define ROWS (BB * QQ)          // 4096

// ---------------- scratch (device globals; no allocation allowed) ----------
__device__ __nv_bfloat16 g_xq_h [ROWS * EMB];
__device__ __nv_bfloat16 g_xq_l [ROWS * EMB];
__device__ __nv_bfloat16 g_xkv_h[ROWS * EMB];
__device__ __nv_bfloat16 g_xkv_l[ROWS * EMB];
__device__ __nv_bfloat16 g_qh[ROWS * EMB];
__device__ __nv_bfloat16 g_ql[ROWS * EMB];
__device__ __nv_bfloat16 g_kh[ROWS * EMB];
__device__ __nv_bfloat16 g_kl[ROWS * EMB];
__device__ __nv_bfloat16 g_vh[ROWS * EMB];
__device__ __nv_bfloat16 g_vl[ROWS * EMB];
__device__ __nv_bfloat16 g_ch[ROWS * EMB];
__device__ __nv_bfloat16 g_cl[ROWS * EMB];

__device__ __nv_bfloat16 g_wqt_h[EMB * EMB];
__device__ __nv_bfloat16 g_wqt_l[EMB * EMB];
__device__ __nv_bfloat16 g_wkt_h[EMB * EMB];
__device__ __nv_bfloat16 g_wkt_l[EMB * EMB];
__device__ __nv_bfloat16 g_wvt_h[EMB * EMB];
__device__ __nv_bfloat16 g_wvt_l[EMB * EMB];
__device__ __nv_bfloat16 g_wot_h[EMB * EMB];
__device__ __nv_bfloat16 g_wot_l[EMB * EMB];

// ---------------- helpers ---------------------------------------------------
__device__ __forceinline__ uint32_t smem_u32(const void* p) {
    uint32_t a;
    asm("{ .reg .u64 t; cvta.to.shared.u64 t, %1; cvt.u32.u64 %0, t; }"
        : "=r"(a) : "l"(p));
    return a;
}

#define CP_ASYNC16(dst, src) \
    asm volatile("cp.async.cg.shared.global [%0], [%1], 16;" :: "r"(dst), "l"(src))
#define CP_COMMIT() asm volatile("cp.async.commit_group;" ::: "memory")
#define CP_WAIT(n)  asm volatile("cp.async.wait_group %0;" :: "n"(n) : "memory")

__device__ __forceinline__ void ldsm_x4(uint32_t* d, uint32_t addr) {
    asm volatile("ldmatrix.sync.aligned.m8n8.x4.shared.b16 {%0,%1,%2,%3}, [%4];"
                 : "=r"(d[0]), "=r"(d[1]), "=r"(d[2]), "=r"(d[3]) : "r"(addr));
}
__device__ __forceinline__ void ldsm_x2(uint32_t* d, uint32_t addr) {
    asm volatile("ldmatrix.sync.aligned.m8n8.x2.shared.b16 {%0,%1}, [%2];"
                 : "=r"(d[0]), "=r"(d[1]) : "r"(addr));
}
__device__ __forceinline__ void ldsm_x2_t(uint32_t* d, uint32_t addr) {
    asm volatile("ldmatrix.sync.aligned.m8n8.x2.trans.shared.b16 {%0,%1}, [%2];"
                 : "=r"(d[0]), "=r"(d[1]) : "r"(addr));
}
__device__ __forceinline__ void mma16816(float* d, const uint32_t* a, const uint32_t* b) {
    asm volatile(
        "mma.sync.aligned.m16n8k16.row.col.f32.bf16.bf16.f32 "
        "{%0,%1,%2,%3}, {%4,%5,%6,%7}, {%8,%9}, {%0,%1,%2,%3};"
        : "+f"(d[0]), "+f"(d[1]), "+f"(d[2]), "+f"(d[3])
        : "r"(a[0]), "r"(a[1]), "r"(a[2]), "r"(a[3]), "r"(b[0]), "r"(b[1]));
}
// pack 2 floats -> bf16x2 (lo = first arg)
__device__ __forceinline__ uint32_t cvt2bf(float lo, float hi) {
    uint32_t u;
    asm("cvt.rn.bf16x2.f32 %0, %1, %2;" : "=r"(u) : "f"(hi), "f"(lo));
    return u;
}
__device__ __forceinline__ float bf_lo(uint32_t u) { return __uint_as_float(u << 16); }
__device__ __forceinline__ float bf_hi(uint32_t u) { return __uint_as_float(u & 0xffff0000u); }

// split-store two f32 as hi/lo bf16x2 pairs
__device__ __forceinline__ void split_store(float v0, float v1,
                                            __nv_bfloat16* ch, __nv_bfloat16* cl) {
    uint32_t uh = cvt2bf(v0, v1);
    float r0 = v0 - bf_lo(uh);
    float r1 = v1 - bf_hi(uh);
    uint32_t ul = cvt2bf(r0, r1);
    *(uint32_t*)ch = uh;
    *(uint32_t*)cl = ul;
}

// ============================================================================
// fp32 -> bf16 hi/lo split (elementwise)
// ============================================================================
__global__ __launch_bounds__(256)
void split_kernel(const float* __restrict__ x, __nv_bfloat16* __restrict__ hi,
                  __nv_bfloat16* __restrict__ lo, int n)
{
    int i = (blockIdx.x * 256 + threadIdx.x) * 4;
    if (i >= n) return;
    float4 v = *(const float4*)(x + i);
    __nv_bfloat16 h0 = __float2bfloat16(v.x);
    __nv_bfloat16 h1 = __float2bfloat16(v.y);
    __nv_bfloat16 h2 = __float2bfloat16(v.z);
    __nv_bfloat16 h3 = __float2bfloat16(v.w);
    __nv_bfloat16 l0 = __float2bfloat16(v.x - __bfloat162float(h0));
    __nv_bfloat16 l1 = __float2bfloat16(v.y - __bfloat162float(h1));
    __nv_bfloat16 l2 = __float2bfloat16(v.z - __bfloat162float(h2));
    __nv_bfloat16 l3 = __float2bfloat16(v.w - __bfloat162float(h3));
    __nv_bfloat162* ph = (__nv_bfloat162*)(hi + i);
    __nv_bfloat162* pl = (__nv_bfloat162*)(lo + i);
    ph[0] = __nv_bfloat162(h0, h1);
    ph[1] = __nv_bfloat162(h2, h3);
    pl[0] = __nv_bfloat162(l0, l1);
    pl[1] = __nv_bfloat162(l2, l3);
}

// ============================================================================
// Weight transpose + split:  w [R][C] fp32 -> wt hi/lo [C][R] bf16  (R=C=2048)
// ============================================================================
__global__ __launch_bounds__(256)
void wsplit_kernel(const float* __restrict__ w, __nv_bfloat16* __restrict__ th,
                   __nv_bfloat16* __restrict__ tl)
{
    __shared__ float tile[32][33];
    const int bx = blockIdx.x * 32;
    const int by = blockIdx.y * 32;
    const int tx = threadIdx.x % 32;
    const int ty = threadIdx.x / 32;
#pragma unroll
    for (int j = 0; j < 32; j += 8)
        tile[ty + j][tx] = w[(size_t)(by + ty + j) * 2048 + bx + tx];
    __syncthreads();
#pragma unroll
    for (int j = 0; j < 32; j += 8) {
        float v = tile[tx][ty + j];
        __nv_bfloat16 h = __float2bfloat16(v);
        __nv_bfloat16 l = __float2bfloat16(v - __bfloat162float(h));
        th[(size_t)(bx + ty + j) * 2048 + by + tx] = h;
        tl[(size_t)(bx + ty + j) * 2048 + by + tx] = l;
    }
}

// ============================================================================
// bf16-split GEMM on mma.sync:
//   C = alpha * (Ah*Bh^T + Ah*Bl^T + Al*Bh^T)
// Output: f32 (Cf) OR split bf16 hi/lo (Ch/Cl) if Cf == nullptr.
// ============================================================================
#define GSTRIDE 40
#define NCHUNK  192

__global__ __launch_bounds__(256)
void gemm_bf16_mma(const __nv_bfloat16* __restrict__ Ah,
                   const __nv_bfloat16* __restrict__ Al,
                   const __nv_bfloat16* __restrict__ Bh,
                   const __nv_bfloat16* __restrict__ Bl,
                   float* __restrict__ Cf,
                   __nv_bfloat16* __restrict__ Ch,
                   __nv_bfloat16* __restrict__ Cl, float alpha)
{
    __shared__ __align__(16) __nv_bfloat16 As[2][128 * GSTRIDE];
    __shared__ __align__(16) __nv_bfloat16 Bs[2][128 * GSTRIDE];

    const int tid  = threadIdx.x;
    const int wid  = tid / 32;
    const int lane = tid % 32;
    const int block_row = blockIdx.y * 128;
    const int block_col = blockIdx.x * 128;

    const int wm = (wid & 1) * 64;
    const int wn = (wid >> 1) * 32;

    const int r0 = tid >> 2;
    const int kq = (tid & 3) * 8;
    const size_t a_off0 = (size_t)(block_row + r0)      * 2048 + kq;
    const size_t a_off1 = (size_t)(block_row + r0 + 64) * 2048 + kq;
    const size_t b_off0 = (size_t)(block_col + r0)      * 2048 + kq;
    const size_t b_off1 = (size_t)(block_col + r0 + 64) * 2048 + kq;
    const uint32_t sA0 = smem_u32(&As[0][0]);
    const uint32_t sB0 = smem_u32(&Bs[0][0]);
    const uint32_t d0 = r0 * 80 + (tid & 3) * 16;
    const uint32_t d1 = (r0 + 64) * 80 + (tid & 3) * 16;

    const uint32_t a_lm = (wm + (lane & 15)) * 80 + (lane >> 4) * 16;
    const uint32_t b_lm = (wn + (lane & 7)) * 80 + ((lane >> 3) & 1) * 16;

    float acc[4][4][4];
#pragma unroll
    for (int i = 0; i < 4; i++)
#pragma unroll
        for (int j = 0; j < 4; j++)
#pragma unroll
            for (int r = 0; r < 4; r++) acc[i][j][r] = 0.f;

    {
        CP_ASYNC16(sA0 + d0, Ah + a_off0);
        CP_ASYNC16(sA0 + d1, Ah + a_off1);
        CP_ASYNC16(sB0 + d0, Bh + b_off0);
        CP_ASYNC16(sB0 + d1, Bh + b_off1);
        CP_COMMIT();
    }

    for (int i = 0; i < NCHUNK; i++) {
        const int buf = i & 1;
        if (i + 1 < NCHUNK) {
            const int n  = i + 1;
            const int p  = n >> 6;
            const int kk = (n & 63) * 32;
            const __nv_bfloat16* Ap = (p == 2) ? Al : Ah;
            const __nv_bfloat16* Bp = (p == 1) ? Bl : Bh;
            const uint32_t sa = sA0 + (buf ^ 1) * (128 * GSTRIDE * 2);
            const uint32_t sbm = sB0 + (buf ^ 1) * (128 * GSTRIDE * 2);
            CP_ASYNC16(sa + d0,  Ap + a_off0 + kk);
            CP_ASYNC16(sa + d1,  Ap + a_off1 + kk);
            CP_ASYNC16(sbm + d0, Bp + b_off0 + kk);
            CP_ASYNC16(sbm + d1, Bp + b_off1 + kk);
            CP_COMMIT();
            CP_WAIT(1);
        } else {
            CP_WAIT(0);
        }
        __syncthreads();

        const uint32_t sa = sA0 + buf * (128 * GSTRIDE * 2);
        const uint32_t sbm = sB0 + buf * (128 * GSTRIDE * 2);
#pragma unroll
        for (int ks = 0; ks < 2; ks++) {
            uint32_t afrag[4][4], bfrag[4][2];
#pragma unroll
            for (int mt = 0; mt < 4; mt++)
                ldsm_x4(afrag[mt], sa + a_lm + mt * (16 * 80) + ks * 32);
#pragma unroll
            for (int nt = 0; nt < 4; nt++)
                ldsm_x2(bfrag[nt], sbm + b_lm + nt * (8 * 80) + ks * 32);
#pragma unroll
            for (int mt = 0; mt < 4; mt++)
#pragma unroll
                for (int nt = 0; nt < 4; nt++)
                    mma16816(acc[mt][nt], afrag[mt], bfrag[nt]);
        }
        __syncthreads();
    }

#pragma unroll
    for (int mt = 0; mt < 4; mt++) {
        const int row = block_row + wm + mt * 16 + lane / 4;
#pragma unroll
        for (int nt = 0; nt < 4; nt++) {
            const int col = block_col + wn + nt * 8 + (lane % 4) * 2;
            float v0 = alpha * acc[mt][nt][0];
            float v1 = alpha * acc[mt][nt][1];
            float v2 = alpha * acc[mt][nt][2];
            float v3 = alpha * acc[mt][nt][3];
            if (Cf) {
                *(float2*)(Cf + (size_t)row * 2048 + col)       = make_float2(v0, v1);
                *(float2*)(Cf + (size_t)(row + 8) * 2048 + col) = make_float2(v2, v3);
            } else {
                split_store(v0, v1, Ch + (size_t)row * 2048 + col,
                                    Cl + (size_t)row * 2048 + col);
                split_store(v2, v3, Ch + (size_t)(row + 8) * 2048 + col,
                                    Cl + (size_t)(row + 8) * 2048 + col);
            }
        }
    }
}

// ============================================================================
// Flash attention on mma.sync.
// CTA: 128 q-rows for one (b, h). 8 warps x 16 rows. 64-key chunks.
// S = Qh*Kh + Qh*Kl + Ql*Kh (+bias);  softmax;
// ctx += Ph*Vh + Ph*Vl + Pl*Vh   (P split hi/lo in registers).
// smem: double-buffered Kh,Kl,Vh,Vl tiles [64][64] bf16, row stride 144 B.
// ============================================================================
#define KVS 144                      // bytes per smem row
#define KVT (64 * KVS)               // 9216 bytes per tile
#define ATT_SMEM (2 * 4 * KVT)       // 73728

__global__ __launch_bounds__(256)
void attn_mma(const __nv_bfloat16* __restrict__ qh, const __nv_bfloat16* __restrict__ ql,
              const __nv_bfloat16* __restrict__ kh, const __nv_bfloat16* __restrict__ kl,
              const __nv_bfloat16* __restrict__ vh, const __nv_bfloat16* __restrict__ vl,
              const float* __restrict__ bias,
              __nv_bfloat16* __restrict__ ch, __nv_bfloat16* __restrict__ cl)
{
    extern __shared__ __align__(16) char sm[];
    const uint32_t smb = smem_u32(sm);

    const int tid  = threadIdx.x;
    const int wid  = tid / 32;
    const int lane = tid % 32;
    const int qt = blockIdx.x;       // 0..15
    const int h  = blockIdx.y;       // 0..31
    const int b  = blockIdx.z;       // 0..1
    const int g  = lane >> 2;
    const int t  = lane & 3;

    const int qrow  = qt * 128 + wid * 16 + g;          // within batch
    const size_t arow = (size_t)(b * 2048 + qrow);      // activation row (row g)
    const int dbase = h * 64;

    // ---- Q fragments (resident): [ktile][4regs]
    uint32_t qhf[4][4], qlf[4][4];
    {
        const __nv_bfloat16* q0h = qh + arow * 2048 + dbase;
        const __nv_bfloat16* q0l = ql + arow * 2048 + dbase;
#pragma unroll
        for (int kk = 0; kk < 4; kk++) {
            qhf[kk][0] = *(const uint32_t*)(q0h + kk * 16 + 2 * t);
            qhf[kk][1] = *(const uint32_t*)(q0h + (size_t)8 * 2048 + kk * 16 + 2 * t);
            qhf[kk][2] = *(const uint32_t*)(q0h + kk * 16 + 8 + 2 * t);
            qhf[kk][3] = *(const uint32_t*)(q0h + (size_t)8 * 2048 + kk * 16 + 8 + 2 * t);
            qlf[kk][0] = *(const uint32_t*)(q0l + kk * 16 + 2 * t);
            qlf[kk][1] = *(const uint32_t*)(q0l + (size_t)8 * 2048 + kk * 16 + 2 * t);
            qlf[kk][2] = *(const uint32_t*)(q0l + kk * 16 + 8 + 2 * t);
            qlf[kk][3] = *(const uint32_t*)(q0l + (size_t)8 * 2048 + kk * 16 + 8 + 2 * t);
        }
    }

    float ctx[8][4];
#pragma unroll
    for (int nt = 0; nt < 8; nt++)
#pragma unroll
        for (int r = 0; r < 4; r++) ctx[nt][r] = 0.f;
    float m0 = -1e30f, m1 = -1e30f, l0 = 0.f, l1 = 0.f;

    // ---- chunk loader (cp.async): Kh,Kl,Vh,Vl [64][64] -> smem buf
    const int lr  = tid >> 3;        // 0..31
    const int lgr = tid & 7;         // granule
#define LOAD_CHUNK(kc, bufi) do {                                              \
    const uint32_t base_ = smb + (bufi) * (4 * KVT);                           \
    _Pragma("unroll")                                                          \
    for (int i_ = 0; i_ < 8; i_++) {                                           \
        const __nv_bfloat16* s_ = (i_ < 2) ? kh : (i_ < 4) ? kl                \
                                  : (i_ < 6) ? vh : vl;                        \
        const int r_ = lr + 32 * (i_ & 1);                                     \
        const int mat_ = i_ >> 1;                                              \
        const __nv_bfloat16* src_ = s_ +                                       \
            (size_t)(b * 2048 + (kc) + r_) * 2048 + dbase + lgr * 8;           \
        CP_ASYNC16(base_ + mat_ * KVT + r_ * KVS + lgr * 16, src_);            \
    }                                                                          \
} while (0)

    LOAD_CHUNK(0, 0);
    CP_COMMIT();

    const float* bias_b = bias + (size_t)b * 2048 * 2048
                        + (size_t)(qt * 128 + wid * 16 + g) * 2048;

    for (int c = 0; c < 32; c++) {
        const int buf = c & 1;
        if (c + 1 < 32) {
            LOAD_CHUNK((c + 1) * 64, buf ^ 1);
            CP_COMMIT();
            CP_WAIT(1);
        } else {
            CP_WAIT(0);
        }
        __syncthreads();

        const uint32_t kh_s = smb + buf * (4 * KVT);
        const uint32_t kl_s = kh_s + KVT;
        const uint32_t vh_s = kh_s + 2 * KVT;
        const uint32_t vl_s = kh_s + 3 * KVT;

        // ---- S init with bias
        float s[8][4];
        {
            const float* bb  = bias_b + c * 64;
            const float* bb8 = bb + 8 * 2048;
#pragma unroll
            for (int nt = 0; nt < 8; nt++) {
                float2 v01 = *(const float2*)(bb  + nt * 8 + 2 * t);
                float2 v23 = *(const float2*)(bb8 + nt * 8 + 2 * t);
                s[nt][0] = v01.x; s[nt][1] = v01.y;
                s[nt][2] = v23.x; s[nt][3] = v23.y;
            }
        }

        // ---- 3 MMA passes for S
        const uint32_t kaddr = (lane & 7) * KVS + ((lane >> 3) & 1) * 16;
#pragma unroll
        for (int p = 0; p < 3; p++) {
            const uint32_t ks = (p == 1) ? kl_s : kh_s;
            const uint32_t (*af)[4] = (p == 2) ? qlf : qhf;
#pragma unroll
            for (int kk = 0; kk < 4; kk++) {
#pragma unroll
                for (int nt = 0; nt < 8; nt++) {
                    uint32_t bf[2];
                    ldsm_x2(bf, ks + nt * (8 * KVS) + kaddr + kk * 32);
                    mma16816(s[nt], af[kk], bf);
                }
            }
        }

        // ---- online softmax
        float mx0 = -1e30f, mx1 = -1e30f;
#pragma unroll
        for (int nt = 0; nt < 8; nt++) {
            mx0 = fmaxf(mx0, fmaxf(s[nt][0], s[nt][1]));
            mx1 = fmaxf(mx1, fmaxf(s[nt][2], s[nt][3]));
        }
        mx0 = fmaxf(mx0, __shfl_xor_sync(0xffffffffu, mx0, 1));
        mx0 = fmaxf(mx0, __shfl_xor_sync(0xffffffffu, mx0, 2));
        mx1 = fmaxf(mx1, __shfl_xor_sync(0xffffffffu, mx1, 1));
        mx1 = fmaxf(mx1, __shfl_xor_sync(0xffffffffu, mx1, 2));
        const float mn0 = fmaxf(m0, mx0);
        const float mn1 = fmaxf(m1, mx1);
        const float sc0 = __expf(m0 - mn0);
        const float sc1 = __expf(m1 - mn1);
        m0 = mn0; m1 = mn1;

        // ---- P = exp(s - m), split into bf16 hi/lo in registers
        uint32_t ph01[8], ph23[8], pl01[8], pl23[8];
        float rs0 = 0.f, rs1 = 0.f;
#pragma unroll
        for (int nt = 0; nt < 8; nt++) {
            float e0 = __expf(s[nt][0] - mn0);
            float e1 = __expf(s[nt][1] - mn0);
            float e2 = __expf(s[nt][2] - mn1);
            float e3 = __expf(s[nt][3] - mn1);
            uint32_t uh01 = cvt2bf(e0, e1);
            uint32_t uh23 = cvt2bf(e2, e3);
            ph01[nt] = uh01; ph23[nt] = uh23;
            pl01[nt] = cvt2bf(e0 - bf_lo(uh01), e1 - bf_hi(uh01));
            pl23[nt] = cvt2bf(e2 - bf_lo(uh23), e3 - bf_hi(uh23));
            rs0 += e0 + e1;
            rs1 += e2 + e3;
        }
        rs0 += __shfl_xor_sync(0xffffffffu, rs0, 1);
        rs0 += __shfl_xor_sync(0xffffffffu, rs0, 2);
        rs1 += __shfl_xor_sync(0xffffffffu, rs1, 1);
        rs1 += __shfl_xor_sync(0xffffffffu, rs1, 2);
        l0 = l0 * sc0 + rs0;
        l1 = l1 * sc1 + rs1;

#pragma unroll
        for (int nt = 0; nt < 8; nt++) {
            ctx[nt][0] *= sc0; ctx[nt][1] *= sc0;
            ctx[nt][2] *= sc1; ctx[nt][3] *= sc1;
        }

        // ---- PV: ctx += Ph*Vh + Ph*Vl + Pl*Vh
        const uint32_t vaddr = (lane & 15) * KVS;
#pragma unroll
        for (int j = 0; j < 4; j++) {
            const uint32_t pah[4] = {ph01[2 * j], ph23[2 * j], ph01[2 * j + 1], ph23[2 * j + 1]};
            const uint32_t pal[4] = {pl01[2 * j], pl23[2 * j], pl01[2 * j + 1], pl23[2 * j + 1]};
#pragma unroll
            for (int nt = 0; nt < 8; nt++) {
                uint32_t bh[2], bl[2];
                ldsm_x2_t(bh, vh_s + j * (16 * KVS) + vaddr + nt * 16);
                mma16816(ctx[nt], pah, bh);
                mma16816(ctx[nt], pal, bh);
                ldsm_x2_t(bl, vl_s + j * (16 * KVS) + vaddr + nt * 16);
                mma16816(ctx[nt], pah, bl);
            }
        }
        __syncthreads();
    }

    // ---- epilogue: normalize, split to bf16 hi/lo
    const float inv0 = 1.f / l0;
    const float inv1 = 1.f / l1;
#pragma unroll
    for (int nt = 0; nt < 8; nt++) {
        const int col = dbase + nt * 8 + 2 * t;
        split_store(ctx[nt][0] * inv0, ctx[nt][1] * inv0,
                    ch + arow * 2048 + col, cl + arow * 2048 + col);
        split_store(ctx[nt][2] * inv1, ctx[nt][3] * inv1,
                    ch + (arow + 8) * 2048 + col, cl + (arow + 8) * 2048 + col);
    }
}

// ============================================================================
// Launch
// ============================================================================
extern "C" void kernel_launch(void* const* d_in, const int* in_sizes, int n_in,
                              void* d_out, int out_size)
{
    const float* inputs_q  = (const float*)d_in[0];
    const float* inputs_kv = (const float*)d_in[1];
    const float* bias      = (const float*)d_in[2];
    const float* wq        = (const float*)d_in[3];
    const float* wk        = (const float*)d_in[4];
    const float* wv        = (const float*)d_in[5];
    const float* wo        = (const float*)d_in[6];
    float* out = (float*)d_out;

    __nv_bfloat16 *xq_h, *xq_l, *xkv_h, *xkv_l;
    __nv_bfloat16 *qh, *ql, *kh, *kl, *vh, *vl, *ch, *cl;
    __nv_bfloat16 *wqt_h, *wqt_l, *wkt_h, *wkt_l, *wvt_h, *wvt_l, *wot_h, *wot_l;
    cudaGetSymbolAddress((void**)&xq_h,  g_xq_h);
    cudaGetSymbolAddress((void**)&xq_l,  g_xq_l);
    cudaGetSymbolAddress((void**)&xkv_h, g_xkv_h);
    cudaGetSymbolAddress((void**)&xkv_l, g_xkv_l);
    cudaGetSymbolAddress((void**)&qh, g_qh);
    cudaGetSymbolAddress((void**)&ql, g_ql);
    cudaGetSymbolAddress((void**)&kh, g_kh);
    cudaGetSymbolAddress((void**)&kl, g_kl);
    cudaGetSymbolAddress((void**)&vh, g_vh);
    cudaGetSymbolAddress((void**)&vl, g_vl);
    cudaGetSymbolAddress((void**)&ch, g_ch);
    cudaGetSymbolAddress((void**)&cl, g_cl);
    cudaGetSymbolAddress((void**)&wqt_h, g_wqt_h);
    cudaGetSymbolAddress((void**)&wqt_l, g_wqt_l);
    cudaGetSymbolAddress((void**)&wkt_h, g_wkt_h);
    cudaGetSymbolAddress((void**)&wkt_l, g_wkt_l);
    cudaGetSymbolAddress((void**)&wvt_h, g_wvt_h);
    cudaGetSymbolAddress((void**)&wvt_l, g_wvt_l);
    cudaGetSymbolAddress((void**)&wot_h, g_wot_h);
    cudaGetSymbolAddress((void**)&wot_l, g_wot_l);

    static bool attr_done = false;
    if (!attr_done) {
        cudaFuncSetAttribute(attn_mma, cudaFuncAttributeMaxDynamicSharedMemorySize,
                             ATT_SMEM);
        attr_done = true;
    }

    const int n_act = ROWS * EMB;
    const int split_grid = n_act / 4 / 256;
    const dim3 wgrid(64, 64);
    const dim3 ggrid(EMB / 128, ROWS / 128);   // (16, 32)

    // Operand prep
    split_kernel<<<split_grid, 256>>>(inputs_q,  xq_h,  xq_l,  n_act);
    split_kernel<<<split_grid, 256>>>(inputs_kv, xkv_h, xkv_l, n_act);
    wsplit_kernel<<<wgrid, 256>>>(wq, wqt_h, wqt_l);
    wsplit_kernel<<<wgrid, 256>>>(wk, wkt_h, wkt_l);
    wsplit_kernel<<<wgrid, 256>>>(wv, wvt_h, wvt_l);
    wsplit_kernel<<<wgrid, 256>>>(wo, wot_h, wot_l);

    // Projections -> split bf16 outputs (q scaled by 1/sqrt(D))
    gemm_bf16_mma<<<ggrid, 256>>>(xq_h,  xq_l,  wqt_h, wqt_l, nullptr, qh, ql, 0.125f);
    gemm_bf16_mma<<<ggrid, 256>>>(xkv_h, xkv_l, wkt_h, wkt_l, nullptr, kh, kl, 1.0f);
    gemm_bf16_mma<<<ggrid, 256>>>(xkv_h, xkv_l, wvt_h, wvt_l, nullptr, vh, vl, 1.0f);

    // Flash attention on tensor cores -> split ctx
    attn_mma<<<dim3(16, 32, 2), 256, ATT_SMEM>>>(qh, ql, kh, kl, vh, vl, bias, ch, cl);

    // Output projection -> f32 out
    gemm_bf16_mma<<<ggrid, 256>>>(ch, cl, wot_h, wot_l, out, nullptr, nullptr, 1.0f);
}

// round 7
// speedup vs baseline: 3.6293x; 1.4692x over previous
#include <cuda_runtime.h>
#include <cuda_fp16.h>
#include <cstdint>

// Problem constants
#define BB   2
#define QQ   2048
#define KK   2048
#define EMB  2048
#define HH   32
#define DD   64
#define ROWS (BB * QQ)          // 4096

// ---------------- scratch (device globals; no allocation allowed) ----------
__device__ __half g_xq [ROWS * EMB];      // activations, single fp16
__device__ __half g_xkv[ROWS * EMB];
__device__ __half g_qs [ROWS * EMB];      // q projection, single fp16 (scaled)
__device__ __half g_kh [ROWS * EMB];      // k hi/lo
__device__ __half g_kl [ROWS * EMB];
__device__ __half g_vh [ROWS * EMB];      // v hi/lo
__device__ __half g_vl [ROWS * EMB];
__device__ __half g_cs [ROWS * EMB];      // ctx, single fp16

__device__ __half g_wqt_h[EMB * EMB];
__device__ __half g_wqt_l[EMB * EMB];
__device__ __half g_wkt_h[EMB * EMB];
__device__ __half g_wkt_l[EMB * EMB];
__device__ __half g_wvt_h[EMB * EMB];
__device__ __half g_wvt_l[EMB * EMB];
__device__ __half g_wot_h[EMB * EMB];
__device__ __half g_wot_l[EMB * EMB];

// ---------------- helpers ---------------------------------------------------
__device__ __forceinline__ uint32_t smem_u32(const void* p) {
    uint32_t a;
    asm("{ .reg .u64 t; cvta.to.shared.u64 t, %1; cvt.u32.u64 %0, t; }"
        : "=r"(a) : "l"(p));
    return a;
}

#define CP_ASYNC16(dst, src) \
    asm volatile("cp.async.cg.shared.global [%0], [%1], 16;" :: "r"(dst), "l"(src))
#define CP_COMMIT() asm volatile("cp.async.commit_group;" ::: "memory")
#define CP_WAIT(n)  asm volatile("cp.async.wait_group %0;" :: "n"(n) : "memory")

__device__ __forceinline__ void ldsm_x4(uint32_t* d, uint32_t addr) {
    asm volatile("ldmatrix.sync.aligned.m8n8.x4.shared.b16 {%0,%1,%2,%3}, [%4];"
                 : "=r"(d[0]), "=r"(d[1]), "=r"(d[2]), "=r"(d[3]) : "r"(addr));
}
__device__ __forceinline__ void ldsm_x2(uint32_t* d, uint32_t addr) {
    asm volatile("ldmatrix.sync.aligned.m8n8.x2.shared.b16 {%0,%1}, [%2];"
                 : "=r"(d[0]), "=r"(d[1]) : "r"(addr));
}
__device__ __forceinline__ void ldsm_x2_t(uint32_t* d, uint32_t addr) {
    asm volatile("ldmatrix.sync.aligned.m8n8.x2.trans.shared.b16 {%0,%1}, [%2];"
                 : "=r"(d[0]), "=r"(d[1]) : "r"(addr));
}
__device__ __forceinline__ void mma16816(float* d, const uint32_t* a, const uint32_t* b) {
    asm volatile(
        "mma.sync.aligned.m16n8k16.row.col.f32.f16.f16.f32 "
        "{%0,%1,%2,%3}, {%4,%5,%6,%7}, {%8,%9}, {%0,%1,%2,%3};"
        : "+f"(d[0]), "+f"(d[1]), "+f"(d[2]), "+f"(d[3])
        : "r"(a[0]), "r"(a[1]), "r"(a[2]), "r"(a[3]), "r"(b[0]), "r"(b[1]));
}

__device__ __forceinline__ uint32_t pack2h(float a, float b) {
    __half2 h = __floats2half2_rn(a, b);
    return *(uint32_t*)&h;
}
// split-store two f32 as fp16 hi/lo pairs
__device__ __forceinline__ void split_store_h(float v0, float v1,
                                              __half* ch, __half* cl) {
    __half2 h = __floats2half2_rn(v0, v1);
    float r0 = v0 - __low2float(h);
    float r1 = v1 - __high2float(h);
    __half2 l = __floats2half2_rn(r0, r1);
    *(__half2*)ch = h;
    *(__half2*)cl = l;
}

// ============================================================================
// fp32 -> fp16 convert (single, elementwise)
// ============================================================================
__global__ __launch_bounds__(256)
void conv_kernel(const float* __restrict__ x, __half* __restrict__ y, int n)
{
    int i = (blockIdx.x * 256 + threadIdx.x) * 4;
    if (i >= n) return;
    float4 v = *(const float4*)(x + i);
    __half2* p = (__half2*)(y + i);
    p[0] = __floats2half2_rn(v.x, v.y);
    p[1] = __floats2half2_rn(v.z, v.w);
}

// ============================================================================
// Weight transpose + fp16 hi/lo split: w [R][C] fp32 -> wt hi/lo [C][R]
// ============================================================================
__global__ __launch_bounds__(256)
void wsplit_kernel(const float* __restrict__ w, __half* __restrict__ th,
                   __half* __restrict__ tl)
{
    __shared__ float tile[32][33];
    const int bx = blockIdx.x * 32;
    const int by = blockIdx.y * 32;
    const int tx = threadIdx.x % 32;
    const int ty = threadIdx.x / 32;
#pragma unroll
    for (int j = 0; j < 32; j += 8)
        tile[ty + j][tx] = w[(size_t)(by + ty + j) * 2048 + bx + tx];
    __syncthreads();
#pragma unroll
    for (int j = 0; j < 32; j += 8) {
        float v = tile[tx][ty + j];
        __half h = __float2half(v);
        __half l = __float2half(v - __half2float(h));
        th[(size_t)(bx + ty + j) * 2048 + by + tx] = h;
        tl[(size_t)(bx + ty + j) * 2048 + by + tx] = l;
    }
}

// ============================================================================
// fp16 one-sided-split GEMM on mma.sync:
//   C = alpha * (A*Bh^T + A*Bl^T)
// A: [4096][2048] fp16 row-major; Bh/Bl: [2048][2048] fp16 [N][K].
// CTA tile 128x128, 8 warps (2x4), K-chunk 32; per chunk: A, Bh, Bl tiles.
// Output: f32 (Cf) | split fp16 (Ch+Cl) | single fp16 (Ch).
// ============================================================================
#define TS      80                   // bytes per smem row
#define TILE_B  (128 * TS)           // 10240 per tile
#define GEMM_SMEM (2 * 3 * TILE_B)   // 61440

__global__ __launch_bounds__(256)
void gemm_fp16_mma(const __half* __restrict__ A,
                   const __half* __restrict__ Bh,
                   const __half* __restrict__ Bl,
                   float* __restrict__ Cf,
                   __half* __restrict__ Ch,
                   __half* __restrict__ Cl, float alpha)
{
    extern __shared__ __align__(16) char smg[];
    const uint32_t smb = smem_u32(smg);

    const int tid  = threadIdx.x;
    const int wid  = tid / 32;
    const int lane = tid % 32;
    const int block_row = blockIdx.y * 128;
    const int block_col = blockIdx.x * 128;

    const int wm = (wid & 1) * 64;
    const int wn = (wid >> 1) * 32;

    // loader: per tile 512 16B-granules, 2 per thread
    const int g0r = tid >> 2;            // granule tid: row 0..63
    const int g0c = tid & 3;
    const size_t a_src0 = (size_t)(block_row + g0r)      * 2048 + g0c * 8;
    const size_t a_src1 = (size_t)(block_row + g0r + 64) * 2048 + g0c * 8;
    const size_t b_src0 = (size_t)(block_col + g0r)      * 2048 + g0c * 8;
    const size_t b_src1 = (size_t)(block_col + g0r + 64) * 2048 + g0c * 8;
    const uint32_t dst0 = g0r * TS + g0c * 16;
    const uint32_t dst1 = (g0r + 64) * TS + g0c * 16;

    const uint32_t a_lm = (wm + (lane & 15)) * TS + (lane >> 4) * 16;
    const uint32_t b_lm = (wn + (lane & 7)) * TS + ((lane >> 3) & 1) * 16;

    float acc[4][4][4];
#pragma unroll
    for (int i = 0; i < 4; i++)
#pragma unroll
        for (int j = 0; j < 4; j++)
#pragma unroll
            for (int r = 0; r < 4; r++) acc[i][j][r] = 0.f;

#define G_LOAD(kk, bufi) do {                                                  \
    const uint32_t bb_ = smb + (bufi) * (3 * TILE_B);                          \
    CP_ASYNC16(bb_ + dst0,              A  + a_src0 + (kk));                   \
    CP_ASYNC16(bb_ + dst1,              A  + a_src1 + (kk));                   \
    CP_ASYNC16(bb_ + TILE_B + dst0,     Bh + b_src0 + (kk));                   \
    CP_ASYNC16(bb_ + TILE_B + dst1,     Bh + b_src1 + (kk));                   \
    CP_ASYNC16(bb_ + 2 * TILE_B + dst0, Bl + b_src0 + (kk));                   \
    CP_ASYNC16(bb_ + 2 * TILE_B + dst1, Bl + b_src1 + (kk));                   \
} while (0)

    G_LOAD(0, 0);
    CP_COMMIT();

    for (int i = 0; i < 64; i++) {
        const int buf = i & 1;
        if (i + 1 < 64) {
            G_LOAD((i + 1) * 32, buf ^ 1);
            CP_COMMIT();
            CP_WAIT(1);
        } else {
            CP_WAIT(0);
        }
        __syncthreads();

        const uint32_t base = smb + buf * (3 * TILE_B);
#pragma unroll
        for (int ks = 0; ks < 2; ks++) {
            uint32_t afrag[4][4];
#pragma unroll
            for (int mt = 0; mt < 4; mt++)
                ldsm_x4(afrag[mt], base + a_lm + mt * (16 * TS) + ks * 32);
#pragma unroll
            for (int nt = 0; nt < 4; nt++) {
                uint32_t bh[2], bl[2];
                ldsm_x2(bh, base + TILE_B + b_lm + nt * (8 * TS) + ks * 32);
                ldsm_x2(bl, base + 2 * TILE_B + b_lm + nt * (8 * TS) + ks * 32);
#pragma unroll
                for (int mt = 0; mt < 4; mt++) {
                    mma16816(acc[mt][nt], afrag[mt], bh);
                    mma16816(acc[mt][nt], afrag[mt], bl);
                }
            }
        }
        __syncthreads();
    }

#pragma unroll
    for (int mt = 0; mt < 4; mt++) {
        const int row = block_row + wm + mt * 16 + lane / 4;
#pragma unroll
        for (int nt = 0; nt < 4; nt++) {
            const int col = block_col + wn + nt * 8 + (lane % 4) * 2;
            float v0 = alpha * acc[mt][nt][0];
            float v1 = alpha * acc[mt][nt][1];
            float v2 = alpha * acc[mt][nt][2];
            float v3 = alpha * acc[mt][nt][3];
            if (Cf) {
                *(float2*)(Cf + (size_t)row * 2048 + col)       = make_float2(v0, v1);
                *(float2*)(Cf + (size_t)(row + 8) * 2048 + col) = make_float2(v2, v3);
            } else if (Cl) {
                split_store_h(v0, v1, Ch + (size_t)row * 2048 + col,
                                      Cl + (size_t)row * 2048 + col);
                split_store_h(v2, v3, Ch + (size_t)(row + 8) * 2048 + col,
                                      Cl + (size_t)(row + 8) * 2048 + col);
            } else {
                *(uint32_t*)(Ch + (size_t)row * 2048 + col)       = pack2h(v0, v1);
                *(uint32_t*)(Ch + (size_t)(row + 8) * 2048 + col) = pack2h(v2, v3);
            }
        }
    }
}

// ============================================================================
// Flash attention on mma.sync (fp16).
// CTA: 128 q-rows for one (b, h). 8 warps x 16 rows. 64-key chunks.
// S = Q*(Kh + Kl) + bias  (Q single fp16, 2 passes);  softmax;
// ctx += P*(Vh + Vl)      (P single fp16, 2 passes).
// smem: double-buffered Kh,Kl,Vh,Vl tiles [64][64] fp16, row stride 144 B.
// ============================================================================
#define KVS 144
#define KVT (64 * KVS)
#define ATT_SMEM (2 * 4 * KVT)       // 73728

__global__ __launch_bounds__(256)
void attn_mma(const __half* __restrict__ q,
              const __half* __restrict__ kh, const __half* __restrict__ kl,
              const __half* __restrict__ vh, const __half* __restrict__ vl,
              const float* __restrict__ bias,
              __half* __restrict__ cs)
{
    extern __shared__ __align__(16) char sm[];
    const uint32_t smb = smem_u32(sm);

    const int tid  = threadIdx.x;
    const int wid  = tid / 32;
    const int lane = tid % 32;
    const int qt = blockIdx.x;
    const int h  = blockIdx.y;
    const int b  = blockIdx.z;
    const int g  = lane >> 2;
    const int t  = lane & 3;

    const int qrow  = qt * 128 + wid * 16 + g;
    const size_t arow = (size_t)(b * 2048 + qrow);
    const int dbase = h * 64;

    // ---- Q fragments (single fp16, resident)
    uint32_t qf[4][4];
    {
        const __half* q0 = q + arow * 2048 + dbase;
#pragma unroll
        for (int kk = 0; kk < 4; kk++) {
            qf[kk][0] = *(const uint32_t*)(q0 + kk * 16 + 2 * t);
            qf[kk][1] = *(const uint32_t*)(q0 + (size_t)8 * 2048 + kk * 16 + 2 * t);
            qf[kk][2] = *(const uint32_t*)(q0 + kk * 16 + 8 + 2 * t);
            qf[kk][3] = *(const uint32_t*)(q0 + (size_t)8 * 2048 + kk * 16 + 8 + 2 * t);
        }
    }

    float ctx[8][4];
#pragma unroll
    for (int nt = 0; nt < 8; nt++)
#pragma unroll
        for (int r = 0; r < 4; r++) ctx[nt][r] = 0.f;
    float m0 = -1e30f, m1 = -1e30f, l0 = 0.f, l1 = 0.f;

    const int lr  = tid >> 3;
    const int lgr = tid & 7;
#define LOAD_CHUNK(kc, bufi) do {                                              \
    const uint32_t base_ = smb + (bufi) * (4 * KVT);                           \
    _Pragma("unroll")                                                          \
    for (int i_ = 0; i_ < 8; i_++) {                                           \
        const __half* s_ = (i_ < 2) ? kh : (i_ < 4) ? kl                       \
                           : (i_ < 6) ? vh : vl;                               \
        const int r_ = lr + 32 * (i_ & 1);                                     \
        const int mat_ = i_ >> 1;                                              \
        const __half* src_ = s_ +                                              \
            (size_t)(b * 2048 + (kc) + r_) * 2048 + dbase + lgr * 8;           \
        CP_ASYNC16(base_ + mat_ * KVT + r_ * KVS + lgr * 16, src_);            \
    }                                                                          \
} while (0)

    LOAD_CHUNK(0, 0);
    CP_COMMIT();

    const float* bias_b = bias + (size_t)b * 2048 * 2048
                        + (size_t)(qt * 128 + wid * 16 + g) * 2048;

    for (int c = 0; c < 32; c++) {
        const int buf = c & 1;
        if (c + 1 < 32) {
            LOAD_CHUNK((c + 1) * 64, buf ^ 1);
            CP_COMMIT();
            CP_WAIT(1);
        } else {
            CP_WAIT(0);
        }
        __syncthreads();

        const uint32_t kh_s = smb + buf * (4 * KVT);
        const uint32_t kl_s = kh_s + KVT;
        const uint32_t vh_s = kh_s + 2 * KVT;
        const uint32_t vl_s = kh_s + 3 * KVT;

        // ---- S init with bias
        float s[8][4];
        {
            const float* bb  = bias_b + c * 64;
            const float* bb8 = bb + 8 * 2048;
#pragma unroll
            for (int nt = 0; nt < 8; nt++) {
                float2 v01 = *(const float2*)(bb  + nt * 8 + 2 * t);
                float2 v23 = *(const float2*)(bb8 + nt * 8 + 2 * t);
                s[nt][0] = v01.x; s[nt][1] = v01.y;
                s[nt][2] = v23.x; s[nt][3] = v23.y;
            }
        }

        // ---- 2 MMA passes for S (Kh then Kl, Q single)
        const uint32_t kaddr = (lane & 7) * KVS + ((lane >> 3) & 1) * 16;
#pragma unroll
        for (int p = 0; p < 2; p++) {
            const uint32_t ks = (p == 1) ? kl_s : kh_s;
#pragma unroll
            for (int kk = 0; kk < 4; kk++) {
#pragma unroll
                for (int nt = 0; nt < 8; nt++) {
                    uint32_t bf[2];
                    ldsm_x2(bf, ks + nt * (8 * KVS) + kaddr + kk * 32);
                    mma16816(s[nt], qf[kk], bf);
                }
            }
        }

        // ---- online softmax
        float mx0 = -1e30f, mx1 = -1e30f;
#pragma unroll
        for (int nt = 0; nt < 8; nt++) {
            mx0 = fmaxf(mx0, fmaxf(s[nt][0], s[nt][1]));
            mx1 = fmaxf(mx1, fmaxf(s[nt][2], s[nt][3]));
        }
        mx0 = fmaxf(mx0, __shfl_xor_sync(0xffffffffu, mx0, 1));
        mx0 = fmaxf(mx0, __shfl_xor_sync(0xffffffffu, mx0, 2));
        mx1 = fmaxf(mx1, __shfl_xor_sync(0xffffffffu, mx1, 1));
        mx1 = fmaxf(mx1, __shfl_xor_sync(0xffffffffu, mx1, 2));
        const float mn0 = fmaxf(m0, mx0);
        const float mn1 = fmaxf(m1, mx1);
        const float sc0 = __expf(m0 - mn0);
        const float sc1 = __expf(m1 - mn1);
        m0 = mn0; m1 = mn1;

        uint32_t p01[8], p23[8];
        float rs0 = 0.f, rs1 = 0.f;
#pragma unroll
        for (int nt = 0; nt < 8; nt++) {
            float e0 = __expf(s[nt][0] - mn0);
            float e1 = __expf(s[nt][1] - mn0);
            float e2 = __expf(s[nt][2] - mn1);
            float e3 = __expf(s[nt][3] - mn1);
            p01[nt] = pack2h(e0, e1);
            p23[nt] = pack2h(e2, e3);
            rs0 += e0 + e1;
            rs1 += e2 + e3;
        }
        rs0 += __shfl_xor_sync(0xffffffffu, rs0, 1);
        rs0 += __shfl_xor_sync(0xffffffffu, rs0, 2);
        rs1 += __shfl_xor_sync(0xffffffffu, rs1, 1);
        rs1 += __shfl_xor_sync(0xffffffffu, rs1, 2);
        l0 = l0 * sc0 + rs0;
        l1 = l1 * sc1 + rs1;

#pragma unroll
        for (int nt = 0; nt < 8; nt++) {
            ctx[nt][0] *= sc0; ctx[nt][1] *= sc0;
            ctx[nt][2] *= sc1; ctx[nt][3] *= sc1;
        }

        // ---- PV: ctx += P*(Vh + Vl)
        const uint32_t vaddr = (lane & 15) * KVS;
#pragma unroll
        for (int j = 0; j < 4; j++) {
            const uint32_t pa[4] = {p01[2 * j], p23[2 * j], p01[2 * j + 1], p23[2 * j + 1]};
#pragma unroll
            for (int nt = 0; nt < 8; nt++) {
                uint32_t bh[2], bl[2];
                ldsm_x2_t(bh, vh_s + j * (16 * KVS) + vaddr + nt * 16);
                mma16816(ctx[nt], pa, bh);
                ldsm_x2_t(bl, vl_s + j * (16 * KVS) + vaddr + nt * 16);
                mma16816(ctx[nt], pa, bl);
            }
        }
        __syncthreads();
    }

    // ---- epilogue: normalize, store single fp16 ctx
    const float inv0 = 1.f / l0;
    const float inv1 = 1.f / l1;
#pragma unroll
    for (int nt = 0; nt < 8; nt++) {
        const int col = dbase + nt * 8 + 2 * t;
        *(uint32_t*)(cs + arow * 2048 + col) =
            pack2h(ctx[nt][0] * inv0, ctx[nt][1] * inv0);
        *(uint32_t*)(cs + (arow + 8) * 2048 + col) =
            pack2h(ctx[nt][2] * inv1, ctx[nt][3] * inv1);
    }
}

// ============================================================================
// Launch
// ============================================================================
extern "C" void kernel_launch(void* const* d_in, const int* in_sizes, int n_in,
                              void* d_out, int out_size)
{
    const float* inputs_q  = (const float*)d_in[0];
    const float* inputs_kv = (const float*)d_in[1];
    const float* bias      = (const float*)d_in[2];
    const float* wq        = (const float*)d_in[3];
    const float* wk        = (const float*)d_in[4];
    const float* wv        = (const float*)d_in[5];
    const float* wo        = (const float*)d_in[6];
    float* out = (float*)d_out;

    __half *xq, *xkv, *qs, *kh, *kl, *vh, *vl, *cs;
    __half *wqt_h, *wqt_l, *wkt_h, *wkt_l, *wvt_h, *wvt_l, *wot_h, *wot_l;
    cudaGetSymbolAddress((void**)&xq,  g_xq);
    cudaGetSymbolAddress((void**)&xkv, g_xkv);
    cudaGetSymbolAddress((void**)&qs,  g_qs);
    cudaGetSymbolAddress((void**)&kh,  g_kh);
    cudaGetSymbolAddress((void**)&kl,  g_kl);
    cudaGetSymbolAddress((void**)&vh,  g_vh);
    cudaGetSymbolAddress((void**)&vl,  g_vl);
    cudaGetSymbolAddress((void**)&cs,  g_cs);
    cudaGetSymbolAddress((void**)&wqt_h, g_wqt_h);
    cudaGetSymbolAddress((void**)&wqt_l, g_wqt_l);
    cudaGetSymbolAddress((void**)&wkt_h, g_wkt_h);
    cudaGetSymbolAddress((void**)&wkt_l, g_wkt_l);
    cudaGetSymbolAddress((void**)&wvt_h, g_wvt_h);
    cudaGetSymbolAddress((void**)&wvt_l, g_wvt_l);
    cudaGetSymbolAddress((void**)&wot_h, g_wot_h);
    cudaGetSymbolAddress((void**)&wot_l, g_wot_l);

    static bool attr_done = false;
    if (!attr_done) {
        cudaFuncSetAttribute(attn_mma, cudaFuncAttributeMaxDynamicSharedMemorySize,
                             ATT_SMEM);
        cudaFuncSetAttribute(gemm_fp16_mma, cudaFuncAttributeMaxDynamicSharedMemorySize,
                             GEMM_SMEM);
        attr_done = true;
    }

    const int n_act = ROWS * EMB;
    const int conv_grid = n_act / 4 / 256;
    const dim3 wgrid(64, 64);
    const dim3 ggrid(EMB / 128, ROWS / 128);   // (16, 32)

    // Operand prep
    conv_kernel<<<conv_grid, 256>>>(inputs_q,  xq,  n_act);
    conv_kernel<<<conv_grid, 256>>>(inputs_kv, xkv, n_act);
    wsplit_kernel<<<wgrid, 256>>>(wq, wqt_h, wqt_l);
    wsplit_kernel<<<wgrid, 256>>>(wk, wkt_h, wkt_l);
    wsplit_kernel<<<wgrid, 256>>>(wv, wvt_h, wvt_l);
    wsplit_kernel<<<wgrid, 256>>>(wo, wot_h, wot_l);

    // Projections (q scaled by 1/sqrt(D)); q single fp16, k/v split fp16
    gemm_fp16_mma<<<ggrid, 256, GEMM_SMEM>>>(xq,  wqt_h, wqt_l, nullptr, qs, nullptr, 0.125f);
    gemm_fp16_mma<<<ggrid, 256, GEMM_SMEM>>>(xkv, wkt_h, wkt_l, nullptr, kh, kl, 1.0f);
    gemm_fp16_mma<<<ggrid, 256, GEMM_SMEM>>>(xkv, wvt_h, wvt_l, nullptr, vh, vl, 1.0f);

    // Flash attention -> single fp16 ctx
    attn_mma<<<dim3(16, 32, 2), 256, ATT_SMEM>>>(qs, kh, kl, vh, vl, bias, cs);

    // Output projection -> f32 out
    gemm_fp16_mma<<<ggrid, 256, GEMM_SMEM>>>(cs, wot_h, wot_l, out, nullptr, nullptr, 1.0f);
}

// round 8
// speedup vs baseline: 4.0930x; 1.1278x over previous
#include <cuda_runtime.h>
#include <cuda_fp16.h>
#include <cstdint>

// Problem constants
#define BB   2
#define QQ   2048
#define KK   2048
#define EMB  2048
#define HH   32
#define DD   64
#define ROWS (BB * QQ)          // 4096

// ---------------- scratch (device globals; no allocation allowed) ----------
__device__ __half g_xq [ROWS * EMB];      // activations, single fp16
__device__ __half g_xkv[ROWS * EMB];
__device__ __half g_qs [ROWS * EMB];      // q projection, single fp16 (scaled)
__device__ __half g_ks [ROWS * EMB];      // k projection, single fp16
__device__ __half g_vs [ROWS * EMB];      // v projection, single fp16
__device__ __half g_cs [ROWS * EMB];      // ctx, single fp16

__device__ __half g_wqt_h[EMB * EMB];
__device__ __half g_wqt_l[EMB * EMB];
__device__ __half g_wkt_h[EMB * EMB];
__device__ __half g_wkt_l[EMB * EMB];
__device__ __half g_wvt_h[EMB * EMB];
__device__ __half g_wvt_l[EMB * EMB];
__device__ __half g_wot_h[EMB * EMB];
__device__ __half g_wot_l[EMB * EMB];

// ---------------- helpers ---------------------------------------------------
__device__ __forceinline__ uint32_t smem_u32(const void* p) {
    uint32_t a;
    asm("{ .reg .u64 t; cvta.to.shared.u64 t, %1; cvt.u32.u64 %0, t; }"
        : "=r"(a) : "l"(p));
    return a;
}

#define CP_ASYNC16(dst, src) \
    asm volatile("cp.async.cg.shared.global [%0], [%1], 16;" :: "r"(dst), "l"(src))
#define CP_COMMIT() asm volatile("cp.async.commit_group;" ::: "memory")
#define CP_WAIT(n)  asm volatile("cp.async.wait_group %0;" :: "n"(n) : "memory")

__device__ __forceinline__ void ldsm_x4(uint32_t* d, uint32_t addr) {
    asm volatile("ldmatrix.sync.aligned.m8n8.x4.shared.b16 {%0,%1,%2,%3}, [%4];"
                 : "=r"(d[0]), "=r"(d[1]), "=r"(d[2]), "=r"(d[3]) : "r"(addr));
}
__device__ __forceinline__ void ldsm_x2(uint32_t* d, uint32_t addr) {
    asm volatile("ldmatrix.sync.aligned.m8n8.x2.shared.b16 {%0,%1}, [%2];"
                 : "=r"(d[0]), "=r"(d[1]) : "r"(addr));
}
__device__ __forceinline__ void ldsm_x2_t(uint32_t* d, uint32_t addr) {
    asm volatile("ldmatrix.sync.aligned.m8n8.x2.trans.shared.b16 {%0,%1}, [%2];"
                 : "=r"(d[0]), "=r"(d[1]) : "r"(addr));
}
__device__ __forceinline__ void mma16816(float* d, const uint32_t* a, const uint32_t* b) {
    asm volatile(
        "mma.sync.aligned.m16n8k16.row.col.f32.f16.f16.f32 "
        "{%0,%1,%2,%3}, {%4,%5,%6,%7}, {%8,%9}, {%0,%1,%2,%3};"
        : "+f"(d[0]), "+f"(d[1]), "+f"(d[2]), "+f"(d[3])
        : "r"(a[0]), "r"(a[1]), "r"(a[2]), "r"(a[3]), "r"(b[0]), "r"(b[1]));
}

__device__ __forceinline__ uint32_t pack2h(float a, float b) {
    __half2 h = __floats2half2_rn(a, b);
    return *(uint32_t*)&h;
}
// split-store two f32 as fp16 hi/lo pairs
__device__ __forceinline__ void split_store_h(float v0, float v1,
                                              __half* ch, __half* cl) {
    __half2 h = __floats2half2_rn(v0, v1);
    float r0 = v0 - __low2float(h);
    float r1 = v1 - __high2float(h);
    __half2 l = __floats2half2_rn(r0, r1);
    *(__half2*)ch = h;
    *(__half2*)cl = l;
}

// ============================================================================
// fp32 -> fp16 convert (single, elementwise)
// ============================================================================
__global__ __launch_bounds__(256)
void conv_kernel(const float* __restrict__ x, __half* __restrict__ y, int n)
{
    int i = (blockIdx.x * 256 + threadIdx.x) * 4;
    if (i >= n) return;
    float4 v = *(const float4*)(x + i);
    __half2* p = (__half2*)(y + i);
    p[0] = __floats2half2_rn(v.x, v.y);
    p[1] = __floats2half2_rn(v.z, v.w);
}

// ============================================================================
// Weight transpose + fp16 hi/lo split: w [R][C] fp32 -> wt hi/lo [C][R]
// ============================================================================
__global__ __launch_bounds__(256)
void wsplit_kernel(const float* __restrict__ w, __half* __restrict__ th,
                   __half* __restrict__ tl)
{
    __shared__ float tile[32][33];
    const int bx = blockIdx.x * 32;
    const int by = blockIdx.y * 32;
    const int tx = threadIdx.x % 32;
    const int ty = threadIdx.x / 32;
#pragma unroll
    for (int j = 0; j < 32; j += 8)
        tile[ty + j][tx] = w[(size_t)(by + ty + j) * 2048 + bx + tx];
    __syncthreads();
#pragma unroll
    for (int j = 0; j < 32; j += 8) {
        float v = tile[tx][ty + j];
        __half h = __float2half(v);
        __half l = __float2half(v - __half2float(h));
        th[(size_t)(bx + ty + j) * 2048 + by + tx] = h;
        tl[(size_t)(bx + ty + j) * 2048 + by + tx] = l;
    }
}

// ============================================================================
// fp16 one-sided-split GEMM on mma.sync:
//   C = alpha * (A*Bh^T + A*Bl^T)
// A: [4096][2048] fp16 row-major; Bh/Bl: [2048][2048] fp16 [N][K].
// CTA tile 128x128, 8 warps (2x4), K-chunk 32; per chunk: A, Bh, Bl tiles.
// Output: f32 (Cf) | split fp16 (Ch+Cl) | single fp16 (Ch).
// ============================================================================
#define TS      80                   // bytes per smem row
#define TILE_B  (128 * TS)           // 10240 per tile
#define GEMM_SMEM (2 * 3 * TILE_B)   // 61440

__global__ __launch_bounds__(256)
void gemm_fp16_mma(const __half* __restrict__ A,
                   const __half* __restrict__ Bh,
                   const __half* __restrict__ Bl,
                   float* __restrict__ Cf,
                   __half* __restrict__ Ch,
                   __half* __restrict__ Cl, float alpha)
{
    extern __shared__ __align__(16) char smg[];
    const uint32_t smb = smem_u32(smg);

    const int tid  = threadIdx.x;
    const int wid  = tid / 32;
    const int lane = tid % 32;
    const int block_row = blockIdx.y * 128;
    const int block_col = blockIdx.x * 128;

    const int wm = (wid & 1) * 64;
    const int wn = (wid >> 1) * 32;

    const int g0r = tid >> 2;
    const int g0c = tid & 3;
    const size_t a_src0 = (size_t)(block_row + g0r)      * 2048 + g0c * 8;
    const size_t a_src1 = (size_t)(block_row + g0r + 64) * 2048 + g0c * 8;
    const size_t b_src0 = (size_t)(block_col + g0r)      * 2048 + g0c * 8;
    const size_t b_src1 = (size_t)(block_col + g0r + 64) * 2048 + g0c * 8;
    const uint32_t dst0 = g0r * TS + g0c * 16;
    const uint32_t dst1 = (g0r + 64) * TS + g0c * 16;

    const uint32_t a_lm = (wm + (lane & 15)) * TS + (lane >> 4) * 16;
    const uint32_t b_lm = (wn + (lane & 7)) * TS + ((lane >> 3) & 1) * 16;

    float acc[4][4][4];
#pragma unroll
    for (int i = 0; i < 4; i++)
#pragma unroll
        for (int j = 0; j < 4; j++)
#pragma unroll
            for (int r = 0; r < 4; r++) acc[i][j][r] = 0.f;

#define G_LOAD(kk, bufi) do {                                                  \
    const uint32_t bb_ = smb + (bufi) * (3 * TILE_B);                          \
    CP_ASYNC16(bb_ + dst0,              A  + a_src0 + (kk));                   \
    CP_ASYNC16(bb_ + dst1,              A  + a_src1 + (kk));                   \
    CP_ASYNC16(bb_ + TILE_B + dst0,     Bh + b_src0 + (kk));                   \
    CP_ASYNC16(bb_ + TILE_B + dst1,     Bh + b_src1 + (kk));                   \
    CP_ASYNC16(bb_ + 2 * TILE_B + dst0, Bl + b_src0 + (kk));                   \
    CP_ASYNC16(bb_ + 2 * TILE_B + dst1, Bl + b_src1 + (kk));                   \
} while (0)

    G_LOAD(0, 0);
    CP_COMMIT();

    for (int i = 0; i < 64; i++) {
        const int buf = i & 1;
        if (i + 1 < 64) {
            G_LOAD((i + 1) * 32, buf ^ 1);
            CP_COMMIT();
            CP_WAIT(1);
        } else {
            CP_WAIT(0);
        }
        __syncthreads();

        const uint32_t base = smb + buf * (3 * TILE_B);
#pragma unroll
        for (int ks = 0; ks < 2; ks++) {
            uint32_t afrag[4][4];
#pragma unroll
            for (int mt = 0; mt < 4; mt++)
                ldsm_x4(afrag[mt], base + a_lm + mt * (16 * TS) + ks * 32);
#pragma unroll
            for (int nt = 0; nt < 4; nt++) {
                uint32_t bh[2], bl[2];
                ldsm_x2(bh, base + TILE_B + b_lm + nt * (8 * TS) + ks * 32);
                ldsm_x2(bl, base + 2 * TILE_B + b_lm + nt * (8 * TS) + ks * 32);
#pragma unroll
                for (int mt = 0; mt < 4; mt++) {
                    mma16816(acc[mt][nt], afrag[mt], bh);
                    mma16816(acc[mt][nt], afrag[mt], bl);
                }
            }
        }
        __syncthreads();
    }

#pragma unroll
    for (int mt = 0; mt < 4; mt++) {
        const int row = block_row + wm + mt * 16 + lane / 4;
#pragma unroll
        for (int nt = 0; nt < 4; nt++) {
            const int col = block_col + wn + nt * 8 + (lane % 4) * 2;
            float v0 = alpha * acc[mt][nt][0];
            float v1 = alpha * acc[mt][nt][1];
            float v2 = alpha * acc[mt][nt][2];
            float v3 = alpha * acc[mt][nt][3];
            if (Cf) {
                *(float2*)(Cf + (size_t)row * 2048 + col)       = make_float2(v0, v1);
                *(float2*)(Cf + (size_t)(row + 8) * 2048 + col) = make_float2(v2, v3);
            } else if (Cl) {
                split_store_h(v0, v1, Ch + (size_t)row * 2048 + col,
                                      Cl + (size_t)row * 2048 + col);
                split_store_h(v2, v3, Ch + (size_t)(row + 8) * 2048 + col,
                                      Cl + (size_t)(row + 8) * 2048 + col);
            } else {
                *(uint32_t*)(Ch + (size_t)row * 2048 + col)       = pack2h(v0, v1);
                *(uint32_t*)(Ch + (size_t)(row + 8) * 2048 + col) = pack2h(v2, v3);
            }
        }
    }
}

// ============================================================================
// Flash attention on mma.sync (fp16, single-precision K/V).
// CTA: 128 q-rows for one (b, h). 8 warps x 16 rows. 64-key chunks.
// S = Q*K + bias (1 pass);  softmax;  ctx += P*V (1 pass).
// l accumulated from ROUNDED P so P-rounding common-mode cancels in ctx/l.
// smem: double-buffered K,V tiles [64][64] fp16, row stride 144 B.
// ============================================================================
#define KVS 144
#define KVT (64 * KVS)
#define ATT_SMEM (2 * 2 * KVT)       // 36864

__global__ __launch_bounds__(256)
void attn_mma(const __half* __restrict__ q,
              const __half* __restrict__ k,
              const __half* __restrict__ v,
              const float* __restrict__ bias,
              __half* __restrict__ cs)
{
    extern __shared__ __align__(16) char sm[];
    const uint32_t smb = smem_u32(sm);

    const int tid  = threadIdx.x;
    const int wid  = tid / 32;
    const int lane = tid % 32;
    const int qt = blockIdx.x;
    const int h  = blockIdx.y;
    const int b  = blockIdx.z;
    const int g  = lane >> 2;
    const int t  = lane & 3;

    const int qrow  = qt * 128 + wid * 16 + g;
    const size_t arow = (size_t)(b * 2048 + qrow);
    const int dbase = h * 64;

    // ---- Q fragments (single fp16, resident)
    uint32_t qf[4][4];
    {
        const __half* q0 = q + arow * 2048 + dbase;
#pragma unroll
        for (int kk = 0; kk < 4; kk++) {
            qf[kk][0] = *(const uint32_t*)(q0 + kk * 16 + 2 * t);
            qf[kk][1] = *(const uint32_t*)(q0 + (size_t)8 * 2048 + kk * 16 + 2 * t);
            qf[kk][2] = *(const uint32_t*)(q0 + kk * 16 + 8 + 2 * t);
            qf[kk][3] = *(const uint32_t*)(q0 + (size_t)8 * 2048 + kk * 16 + 8 + 2 * t);
        }
    }

    float ctx[8][4];
#pragma unroll
    for (int nt = 0; nt < 8; nt++)
#pragma unroll
        for (int r = 0; r < 4; r++) ctx[nt][r] = 0.f;
    float m0 = -1e30f, m1 = -1e30f, l0 = 0.f, l1 = 0.f;

    const int lr  = tid >> 3;
    const int lgr = tid & 7;
#define LOAD_CHUNK(kc, bufi) do {                                              \
    const uint32_t base_ = smb + (bufi) * (2 * KVT);                           \
    _Pragma("unroll")                                                          \
    for (int i_ = 0; i_ < 4; i_++) {                                           \
        const __half* s_ = (i_ < 2) ? k : v;                                   \
        const int r_ = lr + 32 * (i_ & 1);                                     \
        const int mat_ = i_ >> 1;                                              \
        const __half* src_ = s_ +                                              \
            (size_t)(b * 2048 + (kc) + r_) * 2048 + dbase + lgr * 8;           \
        CP_ASYNC16(base_ + mat_ * KVT + r_ * KVS + lgr * 16, src_);            \
    }                                                                          \
} while (0)

    LOAD_CHUNK(0, 0);
    CP_COMMIT();

    const float* bias_b = bias + (size_t)b * 2048 * 2048
                        + (size_t)(qt * 128 + wid * 16 + g) * 2048;

    for (int c = 0; c < 32; c++) {
        const int buf = c & 1;
        if (c + 1 < 32) {
            LOAD_CHUNK((c + 1) * 64, buf ^ 1);
            CP_COMMIT();
            CP_WAIT(1);
        } else {
            CP_WAIT(0);
        }
        __syncthreads();

        const uint32_t k_s = smb + buf * (2 * KVT);
        const uint32_t v_s = k_s + KVT;

        // ---- S init with bias
        float s[8][4];
        {
            const float* bb  = bias_b + c * 64;
            const float* bb8 = bb + 8 * 2048;
#pragma unroll
            for (int nt = 0; nt < 8; nt++) {
                float2 v01 = *(const float2*)(bb  + nt * 8 + 2 * t);
                float2 v23 = *(const float2*)(bb8 + nt * 8 + 2 * t);
                s[nt][0] = v01.x; s[nt][1] = v01.y;
                s[nt][2] = v23.x; s[nt][3] = v23.y;
            }
        }

        // ---- single QK pass
        const uint32_t kaddr = (lane & 7) * KVS + ((lane >> 3) & 1) * 16;
#pragma unroll
        for (int kk = 0; kk < 4; kk++) {
#pragma unroll
            for (int nt = 0; nt < 8; nt++) {
                uint32_t bf[2];
                ldsm_x2(bf, k_s + nt * (8 * KVS) + kaddr + kk * 32);
                mma16816(s[nt], qf[kk], bf);
            }
        }

        // ---- online softmax
        float mx0 = -1e30f, mx1 = -1e30f;
#pragma unroll
        for (int nt = 0; nt < 8; nt++) {
            mx0 = fmaxf(mx0, fmaxf(s[nt][0], s[nt][1]));
            mx1 = fmaxf(mx1, fmaxf(s[nt][2], s[nt][3]));
        }
        mx0 = fmaxf(mx0, __shfl_xor_sync(0xffffffffu, mx0, 1));
        mx0 = fmaxf(mx0, __shfl_xor_sync(0xffffffffu, mx0, 2));
        mx1 = fmaxf(mx1, __shfl_xor_sync(0xffffffffu, mx1, 1));
        mx1 = fmaxf(mx1, __shfl_xor_sync(0xffffffffu, mx1, 2));
        const float mn0 = fmaxf(m0, mx0);
        const float mn1 = fmaxf(m1, mx1);
        const float sc0 = __expf(m0 - mn0);
        const float sc1 = __expf(m1 - mn1);
        m0 = mn0; m1 = mn1;

        // ---- P = exp(s - m) rounded to fp16; l from ROUNDED p
        uint32_t p01[8], p23[8];
        float rs0 = 0.f, rs1 = 0.f;
#pragma unroll
        for (int nt = 0; nt < 8; nt++) {
            float e0 = __expf(s[nt][0] - mn0);
            float e1 = __expf(s[nt][1] - mn0);
            float e2 = __expf(s[nt][2] - mn1);
            float e3 = __expf(s[nt][3] - mn1);
            __half2 h01 = __floats2half2_rn(e0, e1);
            __half2 h23 = __floats2half2_rn(e2, e3);
            p01[nt] = *(uint32_t*)&h01;
            p23[nt] = *(uint32_t*)&h23;
            rs0 += __low2float(h01) + __high2float(h01);
            rs1 += __low2float(h23) + __high2float(h23);
        }
        rs0 += __shfl_xor_sync(0xffffffffu, rs0, 1);
        rs0 += __shfl_xor_sync(0xffffffffu, rs0, 2);
        rs1 += __shfl_xor_sync(0xffffffffu, rs1, 1);
        rs1 += __shfl_xor_sync(0xffffffffu, rs1, 2);
        l0 = l0 * sc0 + rs0;
        l1 = l1 * sc1 + rs1;

#pragma unroll
        for (int nt = 0; nt < 8; nt++) {
            ctx[nt][0] *= sc0; ctx[nt][1] *= sc0;
            ctx[nt][2] *= sc1; ctx[nt][3] *= sc1;
        }

        // ---- single PV pass
        const uint32_t vaddr = (lane & 15) * KVS;
#pragma unroll
        for (int j = 0; j < 4; j++) {
            const uint32_t pa[4] = {p01[2 * j], p23[2 * j], p01[2 * j + 1], p23[2 * j + 1]};
#pragma unroll
            for (int nt = 0; nt < 8; nt++) {
                uint32_t bv[2];
                ldsm_x2_t(bv, v_s + j * (16 * KVS) + vaddr + nt * 16);
                mma16816(ctx[nt], pa, bv);
            }
        }
        __syncthreads();
    }

    // ---- epilogue: normalize, store single fp16 ctx
    const float inv0 = 1.f / l0;
    const float inv1 = 1.f / l1;
#pragma unroll
    for (int nt = 0; nt < 8; nt++) {
        const int col = dbase + nt * 8 + 2 * t;
        *(uint32_t*)(cs + arow * 2048 + col) =
            pack2h(ctx[nt][0] * inv0, ctx[nt][1] * inv0);
        *(uint32_t*)(cs + (arow + 8) * 2048 + col) =
            pack2h(ctx[nt][2] * inv1, ctx[nt][3] * inv1);
    }
}

// ============================================================================
// Launch
// ============================================================================
extern "C" void kernel_launch(void* const* d_in, const int* in_sizes, int n_in,
                              void* d_out, int out_size)
{
    const float* inputs_q  = (const float*)d_in[0];
    const float* inputs_kv = (const float*)d_in[1];
    const float* bias      = (const float*)d_in[2];
    const float* wq        = (const float*)d_in[3];
    const float* wk        = (const float*)d_in[4];
    const float* wv        = (const float*)d_in[5];
    const float* wo        = (const float*)d_in[6];
    float* out = (float*)d_out;

    __half *xq, *xkv, *qs, *ks, *vs, *cs;
    __half *wqt_h, *wqt_l, *wkt_h, *wkt_l, *wvt_h, *wvt_l, *wot_h, *wot_l;
    cudaGetSymbolAddress((void**)&xq,  g_xq);
    cudaGetSymbolAddress((void**)&xkv, g_xkv);
    cudaGetSymbolAddress((void**)&qs,  g_qs);
    cudaGetSymbolAddress((void**)&ks,  g_ks);
    cudaGetSymbolAddress((void**)&vs,  g_vs);
    cudaGetSymbolAddress((void**)&cs,  g_cs);
    cudaGetSymbolAddress((void**)&wqt_h, g_wqt_h);
    cudaGetSymbolAddress((void**)&wqt_l, g_wqt_l);
    cudaGetSymbolAddress((void**)&wkt_h, g_wkt_h);
    cudaGetSymbolAddress((void**)&wkt_l, g_wkt_l);
    cudaGetSymbolAddress((void**)&wvt_h, g_wvt_h);
    cudaGetSymbolAddress((void**)&wvt_l, g_wvt_l);
    cudaGetSymbolAddress((void**)&wot_h, g_wot_h);
    cudaGetSymbolAddress((void**)&wot_l, g_wot_l);

    static bool attr_done = false;
    if (!attr_done) {
        cudaFuncSetAttribute(attn_mma, cudaFuncAttributeMaxDynamicSharedMemorySize,
                             ATT_SMEM);
        cudaFuncSetAttribute(gemm_fp16_mma, cudaFuncAttributeMaxDynamicSharedMemorySize,
                             GEMM_SMEM);
        attr_done = true;
    }

    const int n_act = ROWS * EMB;
    const int conv_grid = n_act / 4 / 256;
    const dim3 wgrid(64, 64);
    const dim3 ggrid(EMB / 128, ROWS / 128);   // (16, 32)

    // Operand prep
    conv_kernel<<<conv_grid, 256>>>(inputs_q,  xq,  n_act);
    conv_kernel<<<conv_grid, 256>>>(inputs_kv, xkv, n_act);
    wsplit_kernel<<<wgrid, 256>>>(wq, wqt_h, wqt_l);
    wsplit_kernel<<<wgrid, 256>>>(wk, wkt_h, wkt_l);
    wsplit_kernel<<<wgrid, 256>>>(wv, wvt_h, wvt_l);
    wsplit_kernel<<<wgrid, 256>>>(wo, wot_h, wot_l);

    // Projections (q scaled by 1/sqrt(D)); all outputs single fp16
    gemm_fp16_mma<<<ggrid, 256, GEMM_SMEM>>>(xq,  wqt_h, wqt_l, nullptr, qs, nullptr, 0.125f);
    gemm_fp16_mma<<<ggrid, 256, GEMM_SMEM>>>(xkv, wkt_h, wkt_l, nullptr, ks, nullptr, 1.0f);
    gemm_fp16_mma<<<ggrid, 256, GEMM_SMEM>>>(xkv, wvt_h, wvt_l, nullptr, vs, nullptr, 1.0f);

    // Flash attention -> single fp16 ctx
    attn_mma<<<dim3(16, 32, 2), 256, ATT_SMEM>>>(qs, ks, vs, bias, cs);

    // Output projection -> f32 out
    gemm_fp16_mma<<<ggrid, 256, GEMM_SMEM>>>(cs, wot_h, wot_l, out, nullptr, nullptr, 1.0f);
}

// round 9
// speedup vs baseline: 4.7222x; 1.1537x over previous
#include <cuda_runtime.h>
#include <cuda_fp16.h>
#include <cstdint>

// Problem constants
#define BB   2
#define QQ   2048
#define KK   2048
#define EMB  2048
#define HH   32
#define DD   64
#define ROWS (BB * QQ)          // 4096

// ---------------- scratch (device globals; no allocation allowed) ----------
__device__ __half g_xq [ROWS * EMB];
__device__ __half g_xkv[ROWS * EMB];
__device__ __half g_qs [ROWS * EMB];
__device__ __half g_ks [ROWS * EMB];
__device__ __half g_vs [ROWS * EMB];
__device__ __half g_cs [ROWS * EMB];

__device__ __half g_wqt_h[EMB * EMB];
__device__ __half g_wqt_l[EMB * EMB];
__device__ __half g_wkt_h[EMB * EMB];
__device__ __half g_wvt_h[EMB * EMB];
__device__ __half g_wot_h[EMB * EMB];
__device__ __half g_wot_l[EMB * EMB];

// ---------------- helpers ---------------------------------------------------
__device__ __forceinline__ uint32_t smem_u32(const void* p) {
    uint32_t a;
    asm("{ .reg .u64 t; cvta.to.shared.u64 t, %1; cvt.u32.u64 %0, t; }"
        : "=r"(a) : "l"(p));
    return a;
}

#define CP_ASYNC16(dst, src) \
    asm volatile("cp.async.cg.shared.global [%0], [%1], 16;" :: "r"(dst), "l"(src))
#define CP_COMMIT() asm volatile("cp.async.commit_group;" ::: "memory")
#define CP_WAIT(n)  asm volatile("cp.async.wait_group %0;" :: "n"(n) : "memory")

__device__ __forceinline__ void ldsm_x4(uint32_t* d, uint32_t addr) {
    asm volatile("ldmatrix.sync.aligned.m8n8.x4.shared.b16 {%0,%1,%2,%3}, [%4];"
                 : "=r"(d[0]), "=r"(d[1]), "=r"(d[2]), "=r"(d[3]) : "r"(addr));
}
__device__ __forceinline__ void ldsm_x2(uint32_t* d, uint32_t addr) {
    asm volatile("ldmatrix.sync.aligned.m8n8.x2.shared.b16 {%0,%1}, [%2];"
                 : "=r"(d[0]), "=r"(d[1]) : "r"(addr));
}
__device__ __forceinline__ void ldsm_x2_t(uint32_t* d, uint32_t addr) {
    asm volatile("ldmatrix.sync.aligned.m8n8.x2.trans.shared.b16 {%0,%1}, [%2];"
                 : "=r"(d[0]), "=r"(d[1]) : "r"(addr));
}
__device__ __forceinline__ void mma16816(float* d, const uint32_t* a, const uint32_t* b) {
    asm volatile(
        "mma.sync.aligned.m16n8k16.row.col.f32.f16.f16.f32 "
        "{%0,%1,%2,%3}, {%4,%5,%6,%7}, {%8,%9}, {%0,%1,%2,%3};"
        : "+f"(d[0]), "+f"(d[1]), "+f"(d[2]), "+f"(d[3])
        : "r"(a[0]), "r"(a[1]), "r"(a[2]), "r"(a[3]), "r"(b[0]), "r"(b[1]));
}

__device__ __forceinline__ uint32_t pack2h(float a, float b) {
    __half2 h = __floats2half2_rn(a, b);
    return *(uint32_t*)&h;
}
__device__ __forceinline__ void split_store_h(float v0, float v1,
                                              __half* ch, __half* cl) {
    __half2 h = __floats2half2_rn(v0, v1);
    float r0 = v0 - __low2float(h);
    float r1 = v1 - __high2float(h);
    __half2 l = __floats2half2_rn(r0, r1);
    *(__half2*)ch = h;
    *(__half2*)cl = l;
}

// ============================================================================
// fp32 -> fp16 convert (elementwise)
// ============================================================================
__global__ __launch_bounds__(256)
void conv_kernel(const float* __restrict__ x, __half* __restrict__ y, int n)
{
    int i = (blockIdx.x * 256 + threadIdx.x) * 4;
    if (i >= n) return;
    float4 v = *(const float4*)(x + i);
    __half2* p = (__half2*)(y + i);
    p[0] = __floats2half2_rn(v.x, v.y);
    p[1] = __floats2half2_rn(v.z, v.w);
}

// ============================================================================
// Weight transpose + fp16 hi/lo split: w [R][C] fp32 -> wt hi/lo [C][R]
// ============================================================================
__global__ __launch_bounds__(256)
void wsplit_kernel(const float* __restrict__ w, __half* __restrict__ th,
                   __half* __restrict__ tl)
{
    __shared__ float tile[32][33];
    const int bx = blockIdx.x * 32;
    const int by = blockIdx.y * 32;
    const int tx = threadIdx.x % 32;
    const int ty = threadIdx.x / 32;
#pragma unroll
    for (int j = 0; j < 32; j += 8)
        tile[ty + j][tx] = w[(size_t)(by + ty + j) * 2048 + bx + tx];
    __syncthreads();
#pragma unroll
    for (int j = 0; j < 32; j += 8) {
        float v = tile[tx][ty + j];
        __half h = __float2half(v);
        __half l = __float2half(v - __half2float(h));
        th[(size_t)(bx + ty + j) * 2048 + by + tx] = h;
        tl[(size_t)(bx + ty + j) * 2048 + by + tx] = l;
    }
}

// Weight transpose, single fp16 output
__global__ __launch_bounds__(256)
void wconv_kernel(const float* __restrict__ w, __half* __restrict__ th)
{
    __shared__ float tile[32][33];
    const int bx = blockIdx.x * 32;
    const int by = blockIdx.y * 32;
    const int tx = threadIdx.x % 32;
    const int ty = threadIdx.x / 32;
#pragma unroll
    for (int j = 0; j < 32; j += 8)
        tile[ty + j][tx] = w[(size_t)(by + ty + j) * 2048 + bx + tx];
    __syncthreads();
#pragma unroll
    for (int j = 0; j < 32; j += 8)
        th[(size_t)(bx + ty + j) * 2048 + by + tx] = __float2half(tile[tx][ty + j]);
}

// ============================================================================
// fp16 GEMM on mma.sync, optional one-sided weight split:
//   C = alpha * (A*Bh^T [+ A*Bl^T if Bl])
// A: [4096][2048]; Bh/Bl: [2048][2048] [N][K]. CTA tile 128x128, 8 warps,
// K-chunk 32, 3-stage cp.async pipeline.
// Output: f32 (Cf) | split fp16 (Ch+Cl) | single fp16 (Ch).
// ============================================================================
#define TS      80                   // bytes per smem row
#define TILE_B  (128 * TS)           // 10240 per tile
#define NSTAGE  3
#define GEMM_SMEM (NSTAGE * 3 * TILE_B)   // 92160

__global__ __launch_bounds__(256, 2)
void gemm_fp16_mma(const __half* __restrict__ A,
                   const __half* __restrict__ Bh,
                   const __half* __restrict__ Bl,
                   float* __restrict__ Cf,
                   __half* __restrict__ Ch,
                   __half* __restrict__ Cl, float alpha)
{
    extern __shared__ __align__(16) char smg[];
    const uint32_t smb = smem_u32(smg);

    const int tid  = threadIdx.x;
    const int wid  = tid / 32;
    const int lane = tid % 32;
    const int block_row = blockIdx.y * 128;
    const int block_col = blockIdx.x * 128;

    const int wm = (wid & 1) * 64;
    const int wn = (wid >> 1) * 32;

    const int g0r = tid >> 2;
    const int g0c = tid & 3;
    const size_t a_src0 = (size_t)(block_row + g0r)      * 2048 + g0c * 8;
    const size_t a_src1 = (size_t)(block_row + g0r + 64) * 2048 + g0c * 8;
    const size_t b_src0 = (size_t)(block_col + g0r)      * 2048 + g0c * 8;
    const size_t b_src1 = (size_t)(block_col + g0r + 64) * 2048 + g0c * 8;
    const uint32_t dst0 = g0r * TS + g0c * 16;
    const uint32_t dst1 = (g0r + 64) * TS + g0c * 16;

    const uint32_t a_lm = (wm + (lane & 15)) * TS + (lane >> 4) * 16;
    const uint32_t b_lm = (wn + (lane & 7)) * TS + ((lane >> 3) & 1) * 16;

    const bool has_bl = (Bl != nullptr);

    float acc[4][4][4];
#pragma unroll
    for (int i = 0; i < 4; i++)
#pragma unroll
        for (int j = 0; j < 4; j++)
#pragma unroll
            for (int r = 0; r < 4; r++) acc[i][j][r] = 0.f;

#define G_LOAD(kk, bufi) do {                                                  \
    const uint32_t bb_ = smb + (bufi) * (3 * TILE_B);                          \
    CP_ASYNC16(bb_ + dst0,          A  + a_src0 + (kk));                       \
    CP_ASYNC16(bb_ + dst1,          A  + a_src1 + (kk));                       \
    CP_ASYNC16(bb_ + TILE_B + dst0, Bh + b_src0 + (kk));                       \
    CP_ASYNC16(bb_ + TILE_B + dst1, Bh + b_src1 + (kk));                       \
    if (has_bl) {                                                              \
        CP_ASYNC16(bb_ + 2 * TILE_B + dst0, Bl + b_src0 + (kk));               \
        CP_ASYNC16(bb_ + 2 * TILE_B + dst1, Bl + b_src1 + (kk));               \
    }                                                                          \
} while (0)

    G_LOAD(0, 0);
    CP_COMMIT();
    G_LOAD(32, 1);
    CP_COMMIT();

    for (int i = 0; i < 64; i++) {
        const int buf = i % NSTAGE;
        if (i + 2 < 64) {
            G_LOAD((i + 2) * 32, (i + 2) % NSTAGE);
            CP_COMMIT();
            CP_WAIT(2);
        } else if (i + 1 < 64) {
            CP_WAIT(1);
        } else {
            CP_WAIT(0);
        }
        __syncthreads();

        const uint32_t base = smb + buf * (3 * TILE_B);
#pragma unroll
        for (int ks = 0; ks < 2; ks++) {
            uint32_t afrag[4][4];
#pragma unroll
            for (int mt = 0; mt < 4; mt++)
                ldsm_x4(afrag[mt], base + a_lm + mt * (16 * TS) + ks * 32);
#pragma unroll
            for (int nt = 0; nt < 4; nt++) {
                uint32_t bh[2];
                ldsm_x2(bh, base + TILE_B + b_lm + nt * (8 * TS) + ks * 32);
#pragma unroll
                for (int mt = 0; mt < 4; mt++)
                    mma16816(acc[mt][nt], afrag[mt], bh);
                if (has_bl) {
                    uint32_t bl[2];
                    ldsm_x2(bl, base + 2 * TILE_B + b_lm + nt * (8 * TS) + ks * 32);
#pragma unroll
                    for (int mt = 0; mt < 4; mt++)
                        mma16816(acc[mt][nt], afrag[mt], bl);
                }
            }
        }
        __syncthreads();
    }

#pragma unroll
    for (int mt = 0; mt < 4; mt++) {
        const int row = block_row + wm + mt * 16 + lane / 4;
#pragma unroll
        for (int nt = 0; nt < 4; nt++) {
            const int col = block_col + wn + nt * 8 + (lane % 4) * 2;
            float v0 = alpha * acc[mt][nt][0];
            float v1 = alpha * acc[mt][nt][1];
            float v2 = alpha * acc[mt][nt][2];
            float v3 = alpha * acc[mt][nt][3];
            if (Cf) {
                *(float2*)(Cf + (size_t)row * 2048 + col)       = make_float2(v0, v1);
                *(float2*)(Cf + (size_t)(row + 8) * 2048 + col) = make_float2(v2, v3);
            } else if (Cl) {
                split_store_h(v0, v1, Ch + (size_t)row * 2048 + col,
                                      Cl + (size_t)row * 2048 + col);
                split_store_h(v2, v3, Ch + (size_t)(row + 8) * 2048 + col,
                                      Cl + (size_t)(row + 8) * 2048 + col);
            } else {
                *(uint32_t*)(Ch + (size_t)row * 2048 + col)       = pack2h(v0, v1);
                *(uint32_t*)(Ch + (size_t)(row + 8) * 2048 + col) = pack2h(v2, v3);
            }
        }
    }
}

// ============================================================================
// Flash attention on mma.sync (fp16, single-precision K/V). Unchanged from R8.
// ============================================================================
#define KVS 144
#define KVT (64 * KVS)
#define ATT_SMEM (2 * 2 * KVT)       // 36864

__global__ __launch_bounds__(256)
void attn_mma(const __half* __restrict__ q,
              const __half* __restrict__ k,
              const __half* __restrict__ v,
              const float* __restrict__ bias,
              __half* __restrict__ cs)
{
    extern __shared__ __align__(16) char sm[];
    const uint32_t smb = smem_u32(sm);

    const int tid  = threadIdx.x;
    const int wid  = tid / 32;
    const int lane = tid % 32;
    const int qt = blockIdx.x;
    const int h  = blockIdx.y;
    const int b  = blockIdx.z;
    const int g  = lane >> 2;
    const int t  = lane & 3;

    const int qrow  = qt * 128 + wid * 16 + g;
    const size_t arow = (size_t)(b * 2048 + qrow);
    const int dbase = h * 64;

    uint32_t qf[4][4];
    {
        const __half* q0 = q + arow * 2048 + dbase;
#pragma unroll
        for (int kk = 0; kk < 4; kk++) {
            qf[kk][0] = *(const uint32_t*)(q0 + kk * 16 + 2 * t);
            qf[kk][1] = *(const uint32_t*)(q0 + (size_t)8 * 2048 + kk * 16 + 2 * t);
            qf[kk][2] = *(const uint32_t*)(q0 + kk * 16 + 8 + 2 * t);
            qf[kk][3] = *(const uint32_t*)(q0 + (size_t)8 * 2048 + kk * 16 + 8 + 2 * t);
        }
    }

    float ctx[8][4];
#pragma unroll
    for (int nt = 0; nt < 8; nt++)
#pragma unroll
        for (int r = 0; r < 4; r++) ctx[nt][r] = 0.f;
    float m0 = -1e30f, m1 = -1e30f, l0 = 0.f, l1 = 0.f;

    const int lr  = tid >> 3;
    const int lgr = tid & 7;
#define LOAD_CHUNK(kc, bufi) do {                                              \
    const uint32_t base_ = smb + (bufi) * (2 * KVT);                           \
    _Pragma("unroll")                                                          \
    for (int i_ = 0; i_ < 4; i_++) {                                           \
        const __half* s_ = (i_ < 2) ? k : v;                                   \
        const int r_ = lr + 32 * (i_ & 1);                                     \
        const int mat_ = i_ >> 1;                                              \
        const __half* src_ = s_ +                                              \
            (size_t)(b * 2048 + (kc) + r_) * 2048 + dbase + lgr * 8;           \
        CP_ASYNC16(base_ + mat_ * KVT + r_ * KVS + lgr * 16, src_);            \
    }                                                                          \
} while (0)

    LOAD_CHUNK(0, 0);
    CP_COMMIT();

    const float* bias_b = bias + (size_t)b * 2048 * 2048
                        + (size_t)(qt * 128 + wid * 16 + g) * 2048;

    for (int c = 0; c < 32; c++) {
        const int buf = c & 1;
        if (c + 1 < 32) {
            LOAD_CHUNK((c + 1) * 64, buf ^ 1);
            CP_COMMIT();
            CP_WAIT(1);
        } else {
            CP_WAIT(0);
        }
        __syncthreads();

        const uint32_t k_s = smb + buf * (2 * KVT);
        const uint32_t v_s = k_s + KVT;

        float s[8][4];
        {
            const float* bb  = bias_b + c * 64;
            const float* bb8 = bb + 8 * 2048;
#pragma unroll
            for (int nt = 0; nt < 8; nt++) {
                float2 v01 = *(const float2*)(bb  + nt * 8 + 2 * t);
                float2 v23 = *(const float2*)(bb8 + nt * 8 + 2 * t);
                s[nt][0] = v01.x; s[nt][1] = v01.y;
                s[nt][2] = v23.x; s[nt][3] = v23.y;
            }
        }

        const uint32_t kaddr = (lane & 7) * KVS + ((lane >> 3) & 1) * 16;
#pragma unroll
        for (int kk = 0; kk < 4; kk++) {
#pragma unroll
            for (int nt = 0; nt < 8; nt++) {
                uint32_t bf[2];
                ldsm_x2(bf, k_s + nt * (8 * KVS) + kaddr + kk * 32);
                mma16816(s[nt], qf[kk], bf);
            }
        }

        float mx0 = -1e30f, mx1 = -1e30f;
#pragma unroll
        for (int nt = 0; nt < 8; nt++) {
            mx0 = fmaxf(mx0, fmaxf(s[nt][0], s[nt][1]));
            mx1 = fmaxf(mx1, fmaxf(s[nt][2], s[nt][3]));
        }
        mx0 = fmaxf(mx0, __shfl_xor_sync(0xffffffffu, mx0, 1));
        mx0 = fmaxf(mx0, __shfl_xor_sync(0xffffffffu, mx0, 2));
        mx1 = fmaxf(mx1, __shfl_xor_sync(0xffffffffu, mx1, 1));
        mx1 = fmaxf(mx1, __shfl_xor_sync(0xffffffffu, mx1, 2));
        const float mn0 = fmaxf(m0, mx0);
        const float mn1 = fmaxf(m1, mx1);
        const float sc0 = __expf(m0 - mn0);
        const float sc1 = __expf(m1 - mn1);
        m0 = mn0; m1 = mn1;

        uint32_t p01[8], p23[8];
        float rs0 = 0.f, rs1 = 0.f;
#pragma unroll
        for (int nt = 0; nt < 8; nt++) {
            float e0 = __expf(s[nt][0] - mn0);
            float e1 = __expf(s[nt][1] - mn0);
            float e2 = __expf(s[nt][2] - mn1);
            float e3 = __expf(s[nt][3] - mn1);
            __half2 h01 = __floats2half2_rn(e0, e1);
            __half2 h23 = __floats2half2_rn(e2, e3);
            p01[nt] = *(uint32_t*)&h01;
            p23[nt] = *(uint32_t*)&h23;
            rs0 += __low2float(h01) + __high2float(h01);
            rs1 += __low2float(h23) + __high2float(h23);
        }
        rs0 += __shfl_xor_sync(0xffffffffu, rs0, 1);
        rs0 += __shfl_xor_sync(0xffffffffu, rs0, 2);
        rs1 += __shfl_xor_sync(0xffffffffu, rs1, 1);
        rs1 += __shfl_xor_sync(0xffffffffu, rs1, 2);
        l0 = l0 * sc0 + rs0;
        l1 = l1 * sc1 + rs1;

#pragma unroll
        for (int nt = 0; nt < 8; nt++) {
            ctx[nt][0] *= sc0; ctx[nt][1] *= sc0;
            ctx[nt][2] *= sc1; ctx[nt][3] *= sc1;
        }

        const uint32_t vaddr = (lane & 15) * KVS;
#pragma unroll
        for (int j = 0; j < 4; j++) {
            const uint32_t pa[4] = {p01[2 * j], p23[2 * j], p01[2 * j + 1], p23[2 * j + 1]};
#pragma unroll
            for (int nt = 0; nt < 8; nt++) {
                uint32_t bv[2];
                ldsm_x2_t(bv, v_s + j * (16 * KVS) + vaddr + nt * 16);
                mma16816(ctx[nt], pa, bv);
            }
        }
        __syncthreads();
    }

    const float inv0 = 1.f / l0;
    const float inv1 = 1.f / l1;
#pragma unroll
    for (int nt = 0; nt < 8; nt++) {
        const int col = dbase + nt * 8 + 2 * t;
        *(uint32_t*)(cs + arow * 2048 + col) =
            pack2h(ctx[nt][0] * inv0, ctx[nt][1] * inv0);
        *(uint32_t*)(cs + (arow + 8) * 2048 + col) =
            pack2h(ctx[nt][2] * inv1, ctx[nt][3] * inv1);
    }
}

// ============================================================================
// Launch
// ============================================================================
extern "C" void kernel_launch(void* const* d_in, const int* in_sizes, int n_in,
                              void* d_out, int out_size)
{
    const float* inputs_q  = (const float*)d_in[0];
    const float* inputs_kv = (const float*)d_in[1];
    const float* bias      = (const float*)d_in[2];
    const float* wq        = (const float*)d_in[3];
    const float* wk        = (const float*)d_in[4];
    const float* wv        = (const float*)d_in[5];
    const float* wo        = (const float*)d_in[6];
    float* out = (float*)d_out;

    __half *xq, *xkv, *qs, *ks, *vs, *cs;
    __half *wqt_h, *wqt_l, *wkt_h, *wvt_h, *wot_h, *wot_l;
    cudaGetSymbolAddress((void**)&xq,  g_xq);
    cudaGetSymbolAddress((void**)&xkv, g_xkv);
    cudaGetSymbolAddress((void**)&qs,  g_qs);
    cudaGetSymbolAddress((void**)&ks,  g_ks);
    cudaGetSymbolAddress((void**)&vs,  g_vs);
    cudaGetSymbolAddress((void**)&cs,  g_cs);
    cudaGetSymbolAddress((void**)&wqt_h, g_wqt_h);
    cudaGetSymbolAddress((void**)&wqt_l, g_wqt_l);
    cudaGetSymbolAddress((void**)&wkt_h, g_wkt_h);
    cudaGetSymbolAddress((void**)&wvt_h, g_wvt_h);
    cudaGetSymbolAddress((void**)&wot_h, g_wot_h);
    cudaGetSymbolAddress((void**)&wot_l, g_wot_l);

    static bool attr_done = false;
    if (!attr_done) {
        cudaFuncSetAttribute(attn_mma, cudaFuncAttributeMaxDynamicSharedMemorySize,
                             ATT_SMEM);
        cudaFuncSetAttribute(gemm_fp16_mma, cudaFuncAttributeMaxDynamicSharedMemorySize,
                             GEMM_SMEM);
        attr_done = true;
    }

    const int n_act = ROWS * EMB;
    const int conv_grid = n_act / 4 / 256;
    const dim3 wgrid(64, 64);
    const dim3 ggrid(EMB / 128, ROWS / 128);   // (16, 32)

    // Operand prep
    conv_kernel<<<conv_grid, 256>>>(inputs_q,  xq,  n_act);
    conv_kernel<<<conv_grid, 256>>>(inputs_kv, xkv, n_act);
    wsplit_kernel<<<wgrid, 256>>>(wq, wqt_h, wqt_l);
    wconv_kernel<<<wgrid, 256>>>(wk, wkt_h);
    wconv_kernel<<<wgrid, 256>>>(wv, wvt_h);
    wsplit_kernel<<<wgrid, 256>>>(wo, wot_h, wot_l);

    // Projections: q 2-pass (split weights), k/v 1-pass (single weights)
    gemm_fp16_mma<<<ggrid, 256, GEMM_SMEM>>>(xq,  wqt_h, wqt_l, nullptr, qs, nullptr, 0.125f);
    gemm_fp16_mma<<<ggrid, 256, GEMM_SMEM>>>(xkv, wkt_h, nullptr, nullptr, ks, nullptr, 1.0f);
    gemm_fp16_mma<<<ggrid, 256, GEMM_SMEM>>>(xkv, wvt_h, nullptr, nullptr, vs, nullptr, 1.0f);

    // Flash attention -> single fp16 ctx
    attn_mma<<<dim3(16, 32, 2), 256, ATT_SMEM>>>(qs, ks, vs, bias, cs);

    // Output projection (2-pass, split weights) -> f32 out
    gemm_fp16_mma<<<ggrid, 256, GEMM_SMEM>>>(cs, wot_h, wot_l, out, nullptr, nullptr, 1.0f);
}

// round 10
// speedup vs baseline: 6.0690x; 1.2852x over previous
#include <cuda_runtime.h>
#include <cuda_fp16.h>
#include <cstdint>

// Problem constants
#define BB   2
#define QQ   2048
#define KK   2048
#define EMB  2048
#define HH   32
#define DD   64
#define ROWS (BB * QQ)          // 4096

// ---------------- scratch (device globals; no allocation allowed) ----------
__device__ __half g_xq [ROWS * EMB];
__device__ __half g_xkv[ROWS * EMB];
__device__ __half g_qs [ROWS * EMB];
__device__ __half g_ks [ROWS * EMB];
__device__ __half g_vs [ROWS * EMB];
__device__ __half g_cs [ROWS * EMB];

__device__ __half g_wqt[EMB * EMB];
__device__ __half g_wkt[EMB * EMB];
__device__ __half g_wvt[EMB * EMB];
__device__ __half g_wot[EMB * EMB];

// ---------------- helpers ---------------------------------------------------
__device__ __forceinline__ uint32_t smem_u32(const void* p) {
    uint32_t a;
    asm("{ .reg .u64 t; cvta.to.shared.u64 t, %1; cvt.u32.u64 %0, t; }"
        : "=r"(a) : "l"(p));
    return a;
}

#define CP_ASYNC16(dst, src) \
    asm volatile("cp.async.cg.shared.global [%0], [%1], 16;" :: "r"(dst), "l"(src))
#define CP_COMMIT() asm volatile("cp.async.commit_group;" ::: "memory")
#define CP_WAIT(n)  asm volatile("cp.async.wait_group %0;" :: "n"(n) : "memory")

__device__ __forceinline__ void ldsm_x4(uint32_t* d, uint32_t addr) {
    asm volatile("ldmatrix.sync.aligned.m8n8.x4.shared.b16 {%0,%1,%2,%3}, [%4];"
                 : "=r"(d[0]), "=r"(d[1]), "=r"(d[2]), "=r"(d[3]) : "r"(addr));
}
__device__ __forceinline__ void ldsm_x2(uint32_t* d, uint32_t addr) {
    asm volatile("ldmatrix.sync.aligned.m8n8.x2.shared.b16 {%0,%1}, [%2];"
                 : "=r"(d[0]), "=r"(d[1]) : "r"(addr));
}
__device__ __forceinline__ void ldsm_x2_t(uint32_t* d, uint32_t addr) {
    asm volatile("ldmatrix.sync.aligned.m8n8.x2.trans.shared.b16 {%0,%1}, [%2];"
                 : "=r"(d[0]), "=r"(d[1]) : "r"(addr));
}
__device__ __forceinline__ void mma16816(float* d, const uint32_t* a, const uint32_t* b) {
    asm volatile(
        "mma.sync.aligned.m16n8k16.row.col.f32.f16.f16.f32 "
        "{%0,%1,%2,%3}, {%4,%5,%6,%7}, {%8,%9}, {%0,%1,%2,%3};"
        : "+f"(d[0]), "+f"(d[1]), "+f"(d[2]), "+f"(d[3])
        : "r"(a[0]), "r"(a[1]), "r"(a[2]), "r"(a[3]), "r"(b[0]), "r"(b[1]));
}

__device__ __forceinline__ uint32_t pack2h(float a, float b) {
    __half2 h = __floats2half2_rn(a, b);
    return *(uint32_t*)&h;
}

// ============================================================================
// Activation convert: fp32 -> fp16, blockIdx.y selects tensor
// ============================================================================
__global__ __launch_bounds__(256)
void conv_all_kernel(const float* __restrict__ x0, __half* __restrict__ y0,
                     const float* __restrict__ x1, __half* __restrict__ y1)
{
    const float* x = blockIdx.y ? x1 : x0;
    __half* y = blockIdx.y ? y1 : y0;
    int i = (blockIdx.x * 256 + threadIdx.x) * 4;
    float4 v = *(const float4*)(x + i);
    __half2* p = (__half2*)(y + i);
    p[0] = __floats2half2_rn(v.x, v.y);
    p[1] = __floats2half2_rn(v.z, v.w);
}

// ============================================================================
// Weight transpose to single fp16, blockIdx.z selects weight
// ============================================================================
__global__ __launch_bounds__(256)
void wconv_all_kernel(const float* __restrict__ w0, __half* __restrict__ t0,
                      const float* __restrict__ w1, __half* __restrict__ t1,
                      const float* __restrict__ w2, __half* __restrict__ t2,
                      const float* __restrict__ w3, __half* __restrict__ t3)
{
    const float* w = (blockIdx.z == 0) ? w0 : (blockIdx.z == 1) ? w1
                    : (blockIdx.z == 2) ? w2 : w3;
    __half* th = (blockIdx.z == 0) ? t0 : (blockIdx.z == 1) ? t1
                : (blockIdx.z == 2) ? t2 : t3;
    __shared__ float tile[32][33];
    const int bx = blockIdx.x * 32;
    const int by = blockIdx.y * 32;
    const int tx = threadIdx.x % 32;
    const int ty = threadIdx.x / 32;
#pragma unroll
    for (int j = 0; j < 32; j += 8)
        tile[ty + j][tx] = w[(size_t)(by + ty + j) * 2048 + bx + tx];
    __syncthreads();
#pragma unroll
    for (int j = 0; j < 32; j += 8)
        th[(size_t)(bx + ty + j) * 2048 + by + tx] = __float2half(tile[tx][ty + j]);
}

// ============================================================================
// fp16 GEMM on mma.sync:  C = alpha * A*B^T
// A: [4096][2048]; B: [2048][2048] [N][K]. CTA tile 128x128, 8 warps,
// K-chunk 32, 3-stage cp.async pipeline.
// Output: f32 (Cf) if non-null, else single fp16 (Ch).
// ============================================================================
#define TS      80                   // bytes per smem row
#define TILE_B  (128 * TS)           // 10240 per tile
#define NSTAGE  3
#define GEMM_SMEM (NSTAGE * 2 * TILE_B)   // 61440

__global__ __launch_bounds__(256, 2)
void gemm_fp16_mma(const __half* __restrict__ A,
                   const __half* __restrict__ B,
                   float* __restrict__ Cf,
                   __half* __restrict__ Ch, float alpha)
{
    extern __shared__ __align__(16) char smg[];
    const uint32_t smb = smem_u32(smg);

    const int tid  = threadIdx.x;
    const int wid  = tid / 32;
    const int lane = tid % 32;
    const int block_row = blockIdx.y * 128;
    const int block_col = blockIdx.x * 128;

    const int wm = (wid & 1) * 64;
    const int wn = (wid >> 1) * 32;

    const int g0r = tid >> 2;
    const int g0c = tid & 3;
    const size_t a_src0 = (size_t)(block_row + g0r)      * 2048 + g0c * 8;
    const size_t a_src1 = (size_t)(block_row + g0r + 64) * 2048 + g0c * 8;
    const size_t b_src0 = (size_t)(block_col + g0r)      * 2048 + g0c * 8;
    const size_t b_src1 = (size_t)(block_col + g0r + 64) * 2048 + g0c * 8;
    const uint32_t dst0 = g0r * TS + g0c * 16;
    const uint32_t dst1 = (g0r + 64) * TS + g0c * 16;

    const uint32_t a_lm = (wm + (lane & 15)) * TS + (lane >> 4) * 16;
    const uint32_t b_lm = (wn + (lane & 7)) * TS + ((lane >> 3) & 1) * 16;

    float acc[4][4][4];
#pragma unroll
    for (int i = 0; i < 4; i++)
#pragma unroll
        for (int j = 0; j < 4; j++)
#pragma unroll
            for (int r = 0; r < 4; r++) acc[i][j][r] = 0.f;

#define G_LOAD(kk, bufi) do {                                                  \
    const uint32_t bb_ = smb + (bufi) * (2 * TILE_B);                          \
    CP_ASYNC16(bb_ + dst0,          A + a_src0 + (kk));                        \
    CP_ASYNC16(bb_ + dst1,          A + a_src1 + (kk));                        \
    CP_ASYNC16(bb_ + TILE_B + dst0, B + b_src0 + (kk));                        \
    CP_ASYNC16(bb_ + TILE_B + dst1, B + b_src1 + (kk));                        \
} while (0)

    G_LOAD(0, 0);
    CP_COMMIT();
    G_LOAD(32, 1);
    CP_COMMIT();

    for (int i = 0; i < 64; i++) {
        const int buf = i % NSTAGE;
        if (i + 2 < 64) {
            G_LOAD((i + 2) * 32, (i + 2) % NSTAGE);
            CP_COMMIT();
            CP_WAIT(2);
        } else if (i + 1 < 64) {
            CP_WAIT(1);
        } else {
            CP_WAIT(0);
        }
        __syncthreads();

        const uint32_t base = smb + buf * (2 * TILE_B);
#pragma unroll
        for (int ks = 0; ks < 2; ks++) {
            uint32_t afrag[4][4];
#pragma unroll
            for (int mt = 0; mt < 4; mt++)
                ldsm_x4(afrag[mt], base + a_lm + mt * (16 * TS) + ks * 32);
#pragma unroll
            for (int nt = 0; nt < 4; nt++) {
                uint32_t bf[2];
                ldsm_x2(bf, base + TILE_B + b_lm + nt * (8 * TS) + ks * 32);
#pragma unroll
                for (int mt = 0; mt < 4; mt++)
                    mma16816(acc[mt][nt], afrag[mt], bf);
            }
        }
        __syncthreads();
    }

#pragma unroll
    for (int mt = 0; mt < 4; mt++) {
        const int row = block_row + wm + mt * 16 + lane / 4;
#pragma unroll
        for (int nt = 0; nt < 4; nt++) {
            const int col = block_col + wn + nt * 8 + (lane % 4) * 2;
            float v0 = alpha * acc[mt][nt][0];
            float v1 = alpha * acc[mt][nt][1];
            float v2 = alpha * acc[mt][nt][2];
            float v3 = alpha * acc[mt][nt][3];
            if (Cf) {
                *(float2*)(Cf + (size_t)row * 2048 + col)       = make_float2(v0, v1);
                *(float2*)(Cf + (size_t)(row + 8) * 2048 + col) = make_float2(v2, v3);
            } else {
                *(uint32_t*)(Ch + (size_t)row * 2048 + col)       = pack2h(v0, v1);
                *(uint32_t*)(Ch + (size_t)(row + 8) * 2048 + col) = pack2h(v2, v3);
            }
        }
    }
}

// ============================================================================
// Flash attention on mma.sync (fp16). Unchanged from R8/R9.
// ============================================================================
#define KVS 144
#define KVT (64 * KVS)
#define ATT_SMEM (2 * 2 * KVT)       // 36864

__global__ __launch_bounds__(256)
void attn_mma(const __half* __restrict__ q,
              const __half* __restrict__ k,
              const __half* __restrict__ v,
              const float* __restrict__ bias,
              __half* __restrict__ cs)
{
    extern __shared__ __align__(16) char sm[];
    const uint32_t smb = smem_u32(sm);

    const int tid  = threadIdx.x;
    const int wid  = tid / 32;
    const int lane = tid % 32;
    const int qt = blockIdx.x;
    const int h  = blockIdx.y;
    const int b  = blockIdx.z;
    const int g  = lane >> 2;
    const int t  = lane & 3;

    const int qrow  = qt * 128 + wid * 16 + g;
    const size_t arow = (size_t)(b * 2048 + qrow);
    const int dbase = h * 64;

    uint32_t qf[4][4];
    {
        const __half* q0 = q + arow * 2048 + dbase;
#pragma unroll
        for (int kk = 0; kk < 4; kk++) {
            qf[kk][0] = *(const uint32_t*)(q0 + kk * 16 + 2 * t);
            qf[kk][1] = *(const uint32_t*)(q0 + (size_t)8 * 2048 + kk * 16 + 2 * t);
            qf[kk][2] = *(const uint32_t*)(q0 + kk * 16 + 8 + 2 * t);
            qf[kk][3] = *(const uint32_t*)(q0 + (size_t)8 * 2048 + kk * 16 + 8 + 2 * t);
        }
    }

    float ctx[8][4];
#pragma unroll
    for (int nt = 0; nt < 8; nt++)
#pragma unroll
        for (int r = 0; r < 4; r++) ctx[nt][r] = 0.f;
    float m0 = -1e30f, m1 = -1e30f, l0 = 0.f, l1 = 0.f;

    const int lr  = tid >> 3;
    const int lgr = tid & 7;
#define LOAD_CHUNK(kc, bufi) do {                                              \
    const uint32_t base_ = smb + (bufi) * (2 * KVT);                           \
    _Pragma("unroll")                                                          \
    for (int i_ = 0; i_ < 4; i_++) {                                           \
        const __half* s_ = (i_ < 2) ? k : v;                                   \
        const int r_ = lr + 32 * (i_ & 1);                                     \
        const int mat_ = i_ >> 1;                                              \
        const __half* src_ = s_ +                                              \
            (size_t)(b * 2048 + (kc) + r_) * 2048 + dbase + lgr * 8;           \
        CP_ASYNC16(base_ + mat_ * KVT + r_ * KVS + lgr * 16, src_);            \
    }                                                                          \
} while (0)

    LOAD_CHUNK(0, 0);
    CP_COMMIT();

    const float* bias_b = bias + (size_t)b * 2048 * 2048
                        + (size_t)(qt * 128 + wid * 16 + g) * 2048;

    for (int c = 0; c < 32; c++) {
        const int buf = c & 1;
        if (c + 1 < 32) {
            LOAD_CHUNK((c + 1) * 64, buf ^ 1);
            CP_COMMIT();
            CP_WAIT(1);
        } else {
            CP_WAIT(0);
        }
        __syncthreads();

        const uint32_t k_s = smb + buf * (2 * KVT);
        const uint32_t v_s = k_s + KVT;

        float s[8][4];
        {
            const float* bb  = bias_b + c * 64;
            const float* bb8 = bb + 8 * 2048;
#pragma unroll
            for (int nt = 0; nt < 8; nt++) {
                float2 v01 = *(const float2*)(bb  + nt * 8 + 2 * t);
                float2 v23 = *(const float2*)(bb8 + nt * 8 + 2 * t);
                s[nt][0] = v01.x; s[nt][1] = v01.y;
                s[nt][2] = v23.x; s[nt][3] = v23.y;
            }
        }

        const uint32_t kaddr = (lane & 7) * KVS + ((lane >> 3) & 1) * 16;
#pragma unroll
        for (int kk = 0; kk < 4; kk++) {
#pragma unroll
            for (int nt = 0; nt < 8; nt++) {
                uint32_t bf[2];
                ldsm_x2(bf, k_s + nt * (8 * KVS) + kaddr + kk * 32);
                mma16816(s[nt], qf[kk], bf);
            }
        }

        float mx0 = -1e30f, mx1 = -1e30f;
#pragma unroll
        for (int nt = 0; nt < 8; nt++) {
            mx0 = fmaxf(mx0, fmaxf(s[nt][0], s[nt][1]));
            mx1 = fmaxf(mx1, fmaxf(s[nt][2], s[nt][3]));
        }
        mx0 = fmaxf(mx0, __shfl_xor_sync(0xffffffffu, mx0, 1));
        mx0 = fmaxf(mx0, __shfl_xor_sync(0xffffffffu, mx0, 2));
        mx1 = fmaxf(mx1, __shfl_xor_sync(0xffffffffu, mx1, 1));
        mx1 = fmaxf(mx1, __shfl_xor_sync(0xffffffffu, mx1, 2));
        const float mn0 = fmaxf(m0, mx0);
        const float mn1 = fmaxf(m1, mx1);
        const float sc0 = __expf(m0 - mn0);
        const float sc1 = __expf(m1 - mn1);
        m0 = mn0; m1 = mn1;

        uint32_t p01[8], p23[8];
        float rs0 = 0.f, rs1 = 0.f;
#pragma unroll
        for (int nt = 0; nt < 8; nt++) {
            float e0 = __expf(s[nt][0] - mn0);
            float e1 = __expf(s[nt][1] - mn0);
            float e2 = __expf(s[nt][2] - mn1);
            float e3 = __expf(s[nt][3] - mn1);
            __half2 h01 = __floats2half2_rn(e0, e1);
            __half2 h23 = __floats2half2_rn(e2, e3);
            p01[nt] = *(uint32_t*)&h01;
            p23[nt] = *(uint32_t*)&h23;
            rs0 += __low2float(h01) + __high2float(h01);
            rs1 += __low2float(h23) + __high2float(h23);
        }
        rs0 += __shfl_xor_sync(0xffffffffu, rs0, 1);
        rs0 += __shfl_xor_sync(0xffffffffu, rs0, 2);
        rs1 += __shfl_xor_sync(0xffffffffu, rs1, 1);
        rs1 += __shfl_xor_sync(0xffffffffu, rs1, 2);
        l0 = l0 * sc0 + rs0;
        l1 = l1 * sc1 + rs1;

#pragma unroll
        for (int nt = 0; nt < 8; nt++) {
            ctx[nt][0] *= sc0; ctx[nt][1] *= sc0;
            ctx[nt][2] *= sc1; ctx[nt][3] *= sc1;
        }

        const uint32_t vaddr = (lane & 15) * KVS;
#pragma unroll
        for (int j = 0; j < 4; j++) {
            const uint32_t pa[4] = {p01[2 * j], p23[2 * j], p01[2 * j + 1], p23[2 * j + 1]};
#pragma unroll
            for (int nt = 0; nt < 8; nt++) {
                uint32_t bv[2];
                ldsm_x2_t(bv, v_s + j * (16 * KVS) + vaddr + nt * 16);
                mma16816(ctx[nt], pa, bv);
            }
        }
        __syncthreads();
    }

    const float inv0 = 1.f / l0;
    const float inv1 = 1.f / l1;
#pragma unroll
    for (int nt = 0; nt < 8; nt++) {
        const int col = dbase + nt * 8 + 2 * t;
        *(uint32_t*)(cs + arow * 2048 + col) =
            pack2h(ctx[nt][0] * inv0, ctx[nt][1] * inv0);
        *(uint32_t*)(cs + (arow + 8) * 2048 + col) =
            pack2h(ctx[nt][2] * inv1, ctx[nt][3] * inv1);
    }
}

// ============================================================================
// Launch
// ============================================================================
extern "C" void kernel_launch(void* const* d_in, const int* in_sizes, int n_in,
                              void* d_out, int out_size)
{
    const float* inputs_q  = (const float*)d_in[0];
    const float* inputs_kv = (const float*)d_in[1];
    const float* bias      = (const float*)d_in[2];
    const float* wq        = (const float*)d_in[3];
    const float* wk        = (const float*)d_in[4];
    const float* wv        = (const float*)d_in[5];
    const float* wo        = (const float*)d_in[6];
    float* out = (float*)d_out;

    __half *xq, *xkv, *qs, *ks, *vs, *cs;
    __half *wqt, *wkt, *wvt, *wot;
    cudaGetSymbolAddress((void**)&xq,  g_xq);
    cudaGetSymbolAddress((void**)&xkv, g_xkv);
    cudaGetSymbolAddress((void**)&qs,  g_qs);
    cudaGetSymbolAddress((void**)&ks,  g_ks);
    cudaGetSymbolAddress((void**)&vs,  g_vs);
    cudaGetSymbolAddress((void**)&cs,  g_cs);
    cudaGetSymbolAddress((void**)&wqt, g_wqt);
    cudaGetSymbolAddress((void**)&wkt, g_wkt);
    cudaGetSymbolAddress((void**)&wvt, g_wvt);
    cudaGetSymbolAddress((void**)&wot, g_wot);

    static bool attr_done = false;
    if (!attr_done) {
        cudaFuncSetAttribute(attn_mma, cudaFuncAttributeMaxDynamicSharedMemorySize,
                             ATT_SMEM);
        cudaFuncSetAttribute(gemm_fp16_mma, cudaFuncAttributeMaxDynamicSharedMemorySize,
                             GEMM_SMEM);
        attr_done = true;
    }

    const int n_act = ROWS * EMB;
    const dim3 ggrid(EMB / 128, ROWS / 128);   // (16, 32)

    // Prep: 2 launches total
    conv_all_kernel<<<dim3(n_act / 1024, 2), 256>>>(inputs_q, xq, inputs_kv, xkv);
    wconv_all_kernel<<<dim3(64, 64, 4), 256>>>(wq, wqt, wk, wkt, wv, wvt, wo, wot);

    // Projections (all 1-pass; q scaled by 1/sqrt(D))
    gemm_fp16_mma<<<ggrid, 256, GEMM_SMEM>>>(xq,  wqt, nullptr, qs, 0.125f);
    gemm_fp16_mma<<<ggrid, 256, GEMM_SMEM>>>(xkv, wkt, nullptr, ks, 1.0f);
    gemm_fp16_mma<<<ggrid, 256, GEMM_SMEM>>>(xkv, wvt, nullptr, vs, 1.0f);

    // Flash attention -> single fp16 ctx
    attn_mma<<<dim3(16, 32, 2), 256, ATT_SMEM>>>(qs, ks, vs, bias, cs);

    // Output projection -> f32 out
    gemm_fp16_mma<<<ggrid, 256, GEMM_SMEM>>>(cs, wot, out, nullptr, 1.0f);
}

// round 11
// speedup vs baseline: 6.4973x; 1.0706x over previous
#include <cuda_runtime.h>
#include <cuda_fp16.h>
#include <cstdint>

// Problem constants
#define BB   2
#define QQ   2048
#define KK   2048
#define EMB  2048
#define HH   32
#define DD   64
#define ROWS (BB * QQ)          // 4096

// ---------------- scratch (device globals; no allocation allowed) ----------
__device__ __half g_xq [ROWS * EMB];
__device__ __half g_xkv[ROWS * EMB];
__device__ __half g_qs [ROWS * EMB];
__device__ __half g_ks [ROWS * EMB];
__device__ __half g_vs [ROWS * EMB];
__device__ __half g_cs [ROWS * EMB];

__device__ __half g_wqt[EMB * EMB];
__device__ __half g_wkt[EMB * EMB];
__device__ __half g_wvt[EMB * EMB];
__device__ __half g_wot[EMB * EMB];

// ---------------- helpers ---------------------------------------------------
__device__ __forceinline__ uint32_t smem_u32(const void* p) {
    uint32_t a;
    asm("{ .reg .u64 t; cvta.to.shared.u64 t, %1; cvt.u32.u64 %0, t; }"
        : "=r"(a) : "l"(p));
    return a;
}

#define CP_ASYNC16(dst, src) \
    asm volatile("cp.async.cg.shared.global [%0], [%1], 16;" :: "r"(dst), "l"(src))
#define CP_COMMIT() asm volatile("cp.async.commit_group;" ::: "memory")
#define CP_WAIT(n)  asm volatile("cp.async.wait_group %0;" :: "n"(n) : "memory")

__device__ __forceinline__ void ldsm_x4(uint32_t* d, uint32_t addr) {
    asm volatile("ldmatrix.sync.aligned.m8n8.x4.shared.b16 {%0,%1,%2,%3}, [%4];"
                 : "=r"(d[0]), "=r"(d[1]), "=r"(d[2]), "=r"(d[3]) : "r"(addr));
}
__device__ __forceinline__ void ldsm_x2(uint32_t* d, uint32_t addr) {
    asm volatile("ldmatrix.sync.aligned.m8n8.x2.shared.b16 {%0,%1}, [%2];"
                 : "=r"(d[0]), "=r"(d[1]) : "r"(addr));
}
__device__ __forceinline__ void ldsm_x2_t(uint32_t* d, uint32_t addr) {
    asm volatile("ldmatrix.sync.aligned.m8n8.x2.trans.shared.b16 {%0,%1}, [%2];"
                 : "=r"(d[0]), "=r"(d[1]) : "r"(addr));
}
__device__ __forceinline__ void mma16816(float* d, const uint32_t* a, const uint32_t* b) {
    asm volatile(
        "mma.sync.aligned.m16n8k16.row.col.f32.f16.f16.f32 "
        "{%0,%1,%2,%3}, {%4,%5,%6,%7}, {%8,%9}, {%0,%1,%2,%3};"
        : "+f"(d[0]), "+f"(d[1]), "+f"(d[2]), "+f"(d[3])
        : "r"(a[0]), "r"(a[1]), "r"(a[2]), "r"(a[3]), "r"(b[0]), "r"(b[1]));
}

__device__ __forceinline__ uint32_t pack2h(float a, float b) {
    __half2 h = __floats2half2_rn(a, b);
    return *(uint32_t*)&h;
}

// ============================================================================
// Activation convert: fp32 -> fp16, blockIdx.y selects tensor
// ============================================================================
__global__ __launch_bounds__(256)
void conv_all_kernel(const float* __restrict__ x0, __half* __restrict__ y0,
                     const float* __restrict__ x1, __half* __restrict__ y1)
{
    const float* x = blockIdx.y ? x1 : x0;
    __half* y = blockIdx.y ? y1 : y0;
    int i = (blockIdx.x * 256 + threadIdx.x) * 4;
    float4 v = *(const float4*)(x + i);
    __half2* p = (__half2*)(y + i);
    p[0] = __floats2half2_rn(v.x, v.y);
    p[1] = __floats2half2_rn(v.z, v.w);
}

// ============================================================================
// Weight transpose to single fp16, blockIdx.z selects weight
// ============================================================================
__global__ __launch_bounds__(256)
void wconv_all_kernel(const float* __restrict__ w0, __half* __restrict__ t0,
                      const float* __restrict__ w1, __half* __restrict__ t1,
                      const float* __restrict__ w2, __half* __restrict__ t2,
                      const float* __restrict__ w3, __half* __restrict__ t3)
{
    const float* w = (blockIdx.z == 0) ? w0 : (blockIdx.z == 1) ? w1
                    : (blockIdx.z == 2) ? w2 : w3;
    __half* th = (blockIdx.z == 0) ? t0 : (blockIdx.z == 1) ? t1
                : (blockIdx.z == 2) ? t2 : t3;
    __shared__ float tile[32][33];
    const int bx = blockIdx.x * 32;
    const int by = blockIdx.y * 32;
    const int tx = threadIdx.x % 32;
    const int ty = threadIdx.x / 32;
#pragma unroll
    for (int j = 0; j < 32; j += 8)
        tile[ty + j][tx] = w[(size_t)(by + ty + j) * 2048 + bx + tx];
    __syncthreads();
#pragma unroll
    for (int j = 0; j < 32; j += 8)
        th[(size_t)(bx + ty + j) * 2048 + by + tx] = __float2half(tile[tx][ty + j]);
}

// ============================================================================
// fp16 GEMM body (device): C = alpha * A*B^T
// CTA tile 128x128, 8 warps, K-chunk 32, 3-stage ring, ONE sync per iter.
// ============================================================================
#define TS      80
#define TILE_B  (128 * TS)           // 10240 per tile
#define NSTAGE  3
#define GEMM_SMEM (NSTAGE * 2 * TILE_B)   // 61440

__device__ __forceinline__
void gemm_body(const __half* __restrict__ A, const __half* __restrict__ B,
               float* __restrict__ Cf, __half* __restrict__ Ch, float alpha,
               char* smg, int bx, int by)
{
    const uint32_t smb = smem_u32(smg);
    const int tid  = threadIdx.x;
    const int wid  = tid / 32;
    const int lane = tid % 32;
    const int block_row = by * 128;
    const int block_col = bx * 128;

    const int wm = (wid & 1) * 64;
    const int wn = (wid >> 1) * 32;

    const int g0r = tid >> 2;
    const int g0c = tid & 3;
    const size_t a_src0 = (size_t)(block_row + g0r)      * 2048 + g0c * 8;
    const size_t a_src1 = (size_t)(block_row + g0r + 64) * 2048 + g0c * 8;
    const size_t b_src0 = (size_t)(block_col + g0r)      * 2048 + g0c * 8;
    const size_t b_src1 = (size_t)(block_col + g0r + 64) * 2048 + g0c * 8;
    const uint32_t dst0 = g0r * TS + g0c * 16;
    const uint32_t dst1 = (g0r + 64) * TS + g0c * 16;

    const uint32_t a_lm = (wm + (lane & 15)) * TS + (lane >> 4) * 16;
    const uint32_t b_lm = (wn + (lane & 7)) * TS + ((lane >> 3) & 1) * 16;

    float acc[4][4][4];
#pragma unroll
    for (int i = 0; i < 4; i++)
#pragma unroll
        for (int j = 0; j < 4; j++)
#pragma unroll
            for (int r = 0; r < 4; r++) acc[i][j][r] = 0.f;

#define G_LOAD(kk, bufi) do {                                                  \
    const uint32_t bb_ = smb + (bufi) * (2 * TILE_B);                          \
    CP_ASYNC16(bb_ + dst0,          A + a_src0 + (kk));                        \
    CP_ASYNC16(bb_ + dst1,          A + a_src1 + (kk));                        \
    CP_ASYNC16(bb_ + TILE_B + dst0, B + b_src0 + (kk));                        \
    CP_ASYNC16(bb_ + TILE_B + dst1, B + b_src1 + (kk));                        \
} while (0)

    G_LOAD(0, 0);
    CP_COMMIT();
    G_LOAD(32, 1);
    CP_COMMIT();

    for (int i = 0; i < 64; i++) {
        if (i < 63) { CP_WAIT(1); } else { CP_WAIT(0); }
        __syncthreads();                       // the ONLY barrier per iter
        if (i + 2 < 64) {
            G_LOAD((i + 2) * 32, (i + 2) % NSTAGE);
            CP_COMMIT();
        }
        const uint32_t base = smb + (i % NSTAGE) * (2 * TILE_B);
#pragma unroll
        for (int ks = 0; ks < 2; ks++) {
            uint32_t afrag[4][4];
#pragma unroll
            for (int mt = 0; mt < 4; mt++)
                ldsm_x4(afrag[mt], base + a_lm + mt * (16 * TS) + ks * 32);
#pragma unroll
            for (int nt = 0; nt < 4; nt++) {
                uint32_t bf[2];
                ldsm_x2(bf, base + TILE_B + b_lm + nt * (8 * TS) + ks * 32);
#pragma unroll
                for (int mt = 0; mt < 4; mt++)
                    mma16816(acc[mt][nt], afrag[mt], bf);
            }
        }
    }

#pragma unroll
    for (int mt = 0; mt < 4; mt++) {
        const int row = block_row + wm + mt * 16 + lane / 4;
#pragma unroll
        for (int nt = 0; nt < 4; nt++) {
            const int col = block_col + wn + nt * 8 + (lane % 4) * 2;
            float v0 = alpha * acc[mt][nt][0];
            float v1 = alpha * acc[mt][nt][1];
            float v2 = alpha * acc[mt][nt][2];
            float v3 = alpha * acc[mt][nt][3];
            if (Cf) {
                *(float2*)(Cf + (size_t)row * 2048 + col)       = make_float2(v0, v1);
                *(float2*)(Cf + (size_t)(row + 8) * 2048 + col) = make_float2(v2, v3);
            } else {
                *(uint32_t*)(Ch + (size_t)row * 2048 + col)       = pack2h(v0, v1);
                *(uint32_t*)(Ch + (size_t)(row + 8) * 2048 + col) = pack2h(v2, v3);
            }
        }
    }
}

// Fused Q/K/V projections: blockIdx.z selects operands
__global__ __launch_bounds__(256, 2)
void gemm_qkv_kernel(const __half* __restrict__ xq, const __half* __restrict__ xkv,
                     const __half* __restrict__ wqt, const __half* __restrict__ wkt,
                     const __half* __restrict__ wvt,
                     __half* __restrict__ qs, __half* __restrict__ ks,
                     __half* __restrict__ vs)
{
    extern __shared__ __align__(16) char smg[];
    const int z = blockIdx.z;
    const __half* A = (z == 0) ? xq : xkv;
    const __half* B = (z == 0) ? wqt : (z == 1) ? wkt : wvt;
    __half* C = (z == 0) ? qs : (z == 1) ? ks : vs;
    const float alpha = (z == 0) ? 0.125f : 1.0f;
    gemm_body(A, B, nullptr, C, alpha, smg, blockIdx.x, blockIdx.y);
}

// Output projection (f32 out)
__global__ __launch_bounds__(256, 2)
void gemm_out_kernel(const __half* __restrict__ cs, const __half* __restrict__ wot,
                     float* __restrict__ out)
{
    extern __shared__ __align__(16) char smg[];
    gemm_body(cs, wot, out, nullptr, 1.0f, smg, blockIdx.x, blockIdx.y);
}

// ============================================================================
// Flash attention on mma.sync (fp16), 3-stage KV ring, ONE sync per chunk.
// ============================================================================
#define KVS 144
#define KVT (64 * KVS)
#define ATT_SMEM (3 * 2 * KVT)       // 55296

__global__ __launch_bounds__(256)
void attn_mma(const __half* __restrict__ q,
              const __half* __restrict__ k,
              const __half* __restrict__ v,
              const float* __restrict__ bias,
              __half* __restrict__ cs)
{
    extern __shared__ __align__(16) char sm[];
    const uint32_t smb = smem_u32(sm);

    const int tid  = threadIdx.x;
    const int wid  = tid / 32;
    const int lane = tid % 32;
    const int qt = blockIdx.x;
    const int h  = blockIdx.y;
    const int b  = blockIdx.z;
    const int g  = lane >> 2;
    const int t  = lane & 3;

    const int qrow  = qt * 128 + wid * 16 + g;
    const size_t arow = (size_t)(b * 2048 + qrow);
    const int dbase = h * 64;

    uint32_t qf[4][4];
    {
        const __half* q0 = q + arow * 2048 + dbase;
#pragma unroll
        for (int kk = 0; kk < 4; kk++) {
            qf[kk][0] = *(const uint32_t*)(q0 + kk * 16 + 2 * t);
            qf[kk][1] = *(const uint32_t*)(q0 + (size_t)8 * 2048 + kk * 16 + 2 * t);
            qf[kk][2] = *(const uint32_t*)(q0 + kk * 16 + 8 + 2 * t);
            qf[kk][3] = *(const uint32_t*)(q0 + (size_t)8 * 2048 + kk * 16 + 8 + 2 * t);
        }
    }

    float ctx[8][4];
#pragma unroll
    for (int nt = 0; nt < 8; nt++)
#pragma unroll
        for (int r = 0; r < 4; r++) ctx[nt][r] = 0.f;
    float m0 = -1e30f, m1 = -1e30f, l0 = 0.f, l1 = 0.f;

    const int lr  = tid >> 3;
    const int lgr = tid & 7;
#define LOAD_CHUNK(kc, bufi) do {                                              \
    const uint32_t base_ = smb + (bufi) * (2 * KVT);                           \
    _Pragma("unroll")                                                          \
    for (int i_ = 0; i_ < 4; i_++) {                                           \
        const __half* s_ = (i_ < 2) ? k : v;                                   \
        const int r_ = lr + 32 * (i_ & 1);                                     \
        const int mat_ = i_ >> 1;                                              \
        const __half* src_ = s_ +                                              \
            (size_t)(b * 2048 + (kc) + r_) * 2048 + dbase + lgr * 8;           \
        CP_ASYNC16(base_ + mat_ * KVT + r_ * KVS + lgr * 16, src_);            \
    }                                                                          \
} while (0)

    LOAD_CHUNK(0, 0);
    CP_COMMIT();
    LOAD_CHUNK(64, 1);
    CP_COMMIT();

    const float* bias_b = bias + (size_t)b * 2048 * 2048
                        + (size_t)(qt * 128 + wid * 16 + g) * 2048;

    for (int c = 0; c < 32; c++) {
        if (c < 31) { CP_WAIT(1); } else { CP_WAIT(0); }
        __syncthreads();                       // the ONLY barrier per chunk
        if (c + 2 < 32) {
            LOAD_CHUNK((c + 2) * 64, (c + 2) % 3);
            CP_COMMIT();
        }

        const uint32_t k_s = smb + (c % 3) * (2 * KVT);
        const uint32_t v_s = k_s + KVT;

        float s[8][4];
        {
            const float* bb  = bias_b + c * 64;
            const float* bb8 = bb + 8 * 2048;
#pragma unroll
            for (int nt = 0; nt < 8; nt++) {
                float2 v01 = *(const float2*)(bb  + nt * 8 + 2 * t);
                float2 v23 = *(const float2*)(bb8 + nt * 8 + 2 * t);
                s[nt][0] = v01.x; s[nt][1] = v01.y;
                s[nt][2] = v23.x; s[nt][3] = v23.y;
            }
        }

        const uint32_t kaddr = (lane & 7) * KVS + ((lane >> 3) & 1) * 16;
#pragma unroll
        for (int kk = 0; kk < 4; kk++) {
#pragma unroll
            for (int nt = 0; nt < 8; nt++) {
                uint32_t bf[2];
                ldsm_x2(bf, k_s + nt * (8 * KVS) + kaddr + kk * 32);
                mma16816(s[nt], qf[kk], bf);
            }
        }

        float mx0 = -1e30f, mx1 = -1e30f;
#pragma unroll
        for (int nt = 0; nt < 8; nt++) {
            mx0 = fmaxf(mx0, fmaxf(s[nt][0], s[nt][1]));
            mx1 = fmaxf(mx1, fmaxf(s[nt][2], s[nt][3]));
        }
        mx0 = fmaxf(mx0, __shfl_xor_sync(0xffffffffu, mx0, 1));
        mx0 = fmaxf(mx0, __shfl_xor_sync(0xffffffffu, mx0, 2));
        mx1 = fmaxf(mx1, __shfl_xor_sync(0xffffffffu, mx1, 1));
        mx1 = fmaxf(mx1, __shfl_xor_sync(0xffffffffu, mx1, 2));
        const float mn0 = fmaxf(m0, mx0);
        const float mn1 = fmaxf(m1, mx1);
        const float sc0 = __expf(m0 - mn0);
        const float sc1 = __expf(m1 - mn1);
        m0 = mn0; m1 = mn1;

        uint32_t p01[8], p23[8];
        float rs0 = 0.f, rs1 = 0.f;
#pragma unroll
        for (int nt = 0; nt < 8; nt++) {
            float e0 = __expf(s[nt][0] - mn0);
            float e1 = __expf(s[nt][1] - mn0);
            float e2 = __expf(s[nt][2] - mn1);
            float e3 = __expf(s[nt][3] - mn1);
            __half2 h01 = __floats2half2_rn(e0, e1);
            __half2 h23 = __floats2half2_rn(e2, e3);
            p01[nt] = *(uint32_t*)&h01;
            p23[nt] = *(uint32_t*)&h23;
            rs0 += __low2float(h01) + __high2float(h01);
            rs1 += __low2float(h23) + __high2float(h23);
        }
        rs0 += __shfl_xor_sync(0xffffffffu, rs0, 1);
        rs0 += __shfl_xor_sync(0xffffffffu, rs0, 2);
        rs1 += __shfl_xor_sync(0xffffffffu, rs1, 1);
        rs1 += __shfl_xor_sync(0xffffffffu, rs1, 2);
        l0 = l0 * sc0 + rs0;
        l1 = l1 * sc1 + rs1;

#pragma unroll
        for (int nt = 0; nt < 8; nt++) {
            ctx[nt][0] *= sc0; ctx[nt][1] *= sc0;
            ctx[nt][2] *= sc1; ctx[nt][3] *= sc1;
        }

        const uint32_t vaddr = (lane & 15) * KVS;
#pragma unroll
        for (int j = 0; j < 4; j++) {
            const uint32_t pa[4] = {p01[2 * j], p23[2 * j], p01[2 * j + 1], p23[2 * j + 1]};
#pragma unroll
            for (int nt = 0; nt < 8; nt++) {
                uint32_t bv[2];
                ldsm_x2_t(bv, v_s + j * (16 * KVS) + vaddr + nt * 16);
                mma16816(ctx[nt], pa, bv);
            }
        }
    }

    const float inv0 = 1.f / l0;
    const float inv1 = 1.f / l1;
#pragma unroll
    for (int nt = 0; nt < 8; nt++) {
        const int col = dbase + nt * 8 + 2 * t;
        *(uint32_t*)(cs + arow * 2048 + col) =
            pack2h(ctx[nt][0] * inv0, ctx[nt][1] * inv0);
        *(uint32_t*)(cs + (arow + 8) * 2048 + col) =
            pack2h(ctx[nt][2] * inv1, ctx[nt][3] * inv1);
    }
}

// ============================================================================
// Launch
// ============================================================================
extern "C" void kernel_launch(void* const* d_in, const int* in_sizes, int n_in,
                              void* d_out, int out_size)
{
    const float* inputs_q  = (const float*)d_in[0];
    const float* inputs_kv = (const float*)d_in[1];
    const float* bias      = (const float*)d_in[2];
    const float* wq        = (const float*)d_in[3];
    const float* wk        = (const float*)d_in[4];
    const float* wv        = (const float*)d_in[5];
    const float* wo        = (const float*)d_in[6];
    float* out = (float*)d_out;

    __half *xq, *xkv, *qs, *ks, *vs, *cs;
    __half *wqt, *wkt, *wvt, *wot;
    cudaGetSymbolAddress((void**)&xq,  g_xq);
    cudaGetSymbolAddress((void**)&xkv, g_xkv);
    cudaGetSymbolAddress((void**)&qs,  g_qs);
    cudaGetSymbolAddress((void**)&ks,  g_ks);
    cudaGetSymbolAddress((void**)&vs,  g_vs);
    cudaGetSymbolAddress((void**)&cs,  g_cs);
    cudaGetSymbolAddress((void**)&wqt, g_wqt);
    cudaGetSymbolAddress((void**)&wkt, g_wkt);
    cudaGetSymbolAddress((void**)&wvt, g_wvt);
    cudaGetSymbolAddress((void**)&wot, g_wot);

    static bool attr_done = false;
    if (!attr_done) {
        cudaFuncSetAttribute(attn_mma, cudaFuncAttributeMaxDynamicSharedMemorySize,
                             ATT_SMEM);
        cudaFuncSetAttribute(gemm_qkv_kernel, cudaFuncAttributeMaxDynamicSharedMemorySize,
                             GEMM_SMEM);
        cudaFuncSetAttribute(gemm_out_kernel, cudaFuncAttributeMaxDynamicSharedMemorySize,
                             GEMM_SMEM);
        attr_done = true;
    }

    const int n_act = ROWS * EMB;
    const dim3 ggrid(EMB / 128, ROWS / 128);          // (16, 32)
    const dim3 gqkv(EMB / 128, ROWS / 128, 3);        // fused QKV

    // Prep: 2 launches
    conv_all_kernel<<<dim3(n_act / 1024, 2), 256>>>(inputs_q, xq, inputs_kv, xkv);
    wconv_all_kernel<<<dim3(64, 64, 4), 256>>>(wq, wqt, wk, wkt, wv, wvt, wo, wot);

    // Fused Q/K/V projections (q scaled inside via alpha)
    gemm_qkv_kernel<<<gqkv, 256, GEMM_SMEM>>>(xq, xkv, wqt, wkt, wvt, qs, ks, vs);

    // Flash attention -> single fp16 ctx
    attn_mma<<<dim3(16, 32, 2), 256, ATT_SMEM>>>(qs, ks, vs, bias, cs);

    // Output projection -> f32 out
    gemm_out_kernel<<<ggrid, 256, GEMM_SMEM>>>(cs, wot, out);
}

// round 12
// speedup vs baseline: 7.7050x; 1.1859x over previous
#include <cuda_runtime.h>
#include <cuda_fp16.h>
#include <cstdint>

// Problem constants
#define BB   2
#define QQ   2048
#define KK   2048
#define EMB  2048
#define HH   32
#define DD   64
#define ROWS (BB * QQ)          // 4096

// ---------------- scratch (device globals; no allocation allowed) ----------
__device__ __half g_xq [ROWS * EMB];
__device__ __half g_xkv[ROWS * EMB];
__device__ __half g_bh [BB * QQ * KK];   // bias in fp16
__device__ __half g_qs [ROWS * EMB];
__device__ __half g_ks [ROWS * EMB];
__device__ __half g_vs [ROWS * EMB];
__device__ __half g_cs [ROWS * EMB];

__device__ __half g_wqt[EMB * EMB];
__device__ __half g_wkt[EMB * EMB];
__device__ __half g_wvt[EMB * EMB];
__device__ __half g_wot[EMB * EMB];

// ---------------- helpers ---------------------------------------------------
__device__ __forceinline__ uint32_t smem_u32(const void* p) {
    uint32_t a;
    asm("{ .reg .u64 t; cvta.to.shared.u64 t, %1; cvt.u32.u64 %0, t; }"
        : "=r"(a) : "l"(p));
    return a;
}

#define CP_ASYNC16(dst, src) \
    asm volatile("cp.async.cg.shared.global [%0], [%1], 16;" :: "r"(dst), "l"(src))
#define CP_COMMIT() asm volatile("cp.async.commit_group;" ::: "memory")
#define CP_WAIT(n)  asm volatile("cp.async.wait_group %0;" :: "n"(n) : "memory")

__device__ __forceinline__ void ldsm_x4(uint32_t* d, uint32_t addr) {
    asm volatile("ldmatrix.sync.aligned.m8n8.x4.shared.b16 {%0,%1,%2,%3}, [%4];"
                 : "=r"(d[0]), "=r"(d[1]), "=r"(d[2]), "=r"(d[3]) : "r"(addr));
}
__device__ __forceinline__ void ldsm_x4_t(uint32_t* d, uint32_t addr) {
    asm volatile("ldmatrix.sync.aligned.m8n8.x4.trans.shared.b16 {%0,%1,%2,%3}, [%4];"
                 : "=r"(d[0]), "=r"(d[1]), "=r"(d[2]), "=r"(d[3]) : "r"(addr));
}
__device__ __forceinline__ void mma16816(float* d, const uint32_t* a, const uint32_t* b) {
    asm volatile(
        "mma.sync.aligned.m16n8k16.row.col.f32.f16.f16.f32 "
        "{%0,%1,%2,%3}, {%4,%5,%6,%7}, {%8,%9}, {%0,%1,%2,%3};"
        : "+f"(d[0]), "+f"(d[1]), "+f"(d[2]), "+f"(d[3])
        : "r"(a[0]), "r"(a[1]), "r"(a[2]), "r"(a[3]), "r"(b[0]), "r"(b[1]));
}

__device__ __forceinline__ uint32_t pack2h(float a, float b) {
    __half2 h = __floats2half2_rn(a, b);
    return *(uint32_t*)&h;
}

// ============================================================================
// Elementwise fp32 -> fp16 convert; blockIdx.y selects tensor (xq/xkv/bias)
// ============================================================================
__global__ __launch_bounds__(256)
void conv_all_kernel(const float* __restrict__ x0, __half* __restrict__ y0,
                     const float* __restrict__ x1, __half* __restrict__ y1,
                     const float* __restrict__ x2, __half* __restrict__ y2)
{
    const float* x = (blockIdx.y == 0) ? x0 : (blockIdx.y == 1) ? x1 : x2;
    __half* y = (blockIdx.y == 0) ? y0 : (blockIdx.y == 1) ? y1 : y2;
    size_t i = ((size_t)blockIdx.x * 256 + threadIdx.x) * 4;
    float4 v = *(const float4*)(x + i);
    __half2* p = (__half2*)(y + i);
    p[0] = __floats2half2_rn(v.x, v.y);
    p[1] = __floats2half2_rn(v.z, v.w);
}

// ============================================================================
// Weight transpose to single fp16, blockIdx.z selects weight
// ============================================================================
__global__ __launch_bounds__(256)
void wconv_all_kernel(const float* __restrict__ w0, __half* __restrict__ t0,
                      const float* __restrict__ w1, __half* __restrict__ t1,
                      const float* __restrict__ w2, __half* __restrict__ t2,
                      const float* __restrict__ w3, __half* __restrict__ t3)
{
    const float* w = (blockIdx.z == 0) ? w0 : (blockIdx.z == 1) ? w1
                    : (blockIdx.z == 2) ? w2 : w3;
    __half* th = (blockIdx.z == 0) ? t0 : (blockIdx.z == 1) ? t1
                : (blockIdx.z == 2) ? t2 : t3;
    __shared__ float tile[32][33];
    const int bx = blockIdx.x * 32;
    const int by = blockIdx.y * 32;
    const int tx = threadIdx.x % 32;
    const int ty = threadIdx.x / 32;
#pragma unroll
    for (int j = 0; j < 32; j += 8)
        tile[ty + j][tx] = w[(size_t)(by + ty + j) * 2048 + bx + tx];
    __syncthreads();
#pragma unroll
    for (int j = 0; j < 32; j += 8)
        th[(size_t)(bx + ty + j) * 2048 + by + tx] = __float2half(tile[tx][ty + j]);
}

// ============================================================================
// fp16 GEMM body: C = alpha * A*B^T.  128x128 tile, 8 warps, K-chunk 32,
// 3-stage ring, one sync per iter, x4 ldmatrix for both operands.
// ============================================================================
#define TS      80
#define TILE_B  (128 * TS)
#define NSTAGE  3
#define GEMM_SMEM (NSTAGE * 2 * TILE_B)   // 61440

__device__ __forceinline__
void gemm_body(const __half* __restrict__ A, const __half* __restrict__ B,
               float* __restrict__ Cf, __half* __restrict__ Ch, float alpha,
               char* smg, int bx, int by)
{
    const uint32_t smb = smem_u32(smg);
    const int tid  = threadIdx.x;
    const int wid  = tid / 32;
    const int lane = tid % 32;
    const int block_row = by * 128;
    const int block_col = bx * 128;

    const int wm = (wid & 1) * 64;
    const int wn = (wid >> 1) * 32;

    const int g0r = tid >> 2;
    const int g0c = tid & 3;
    const size_t a_src0 = (size_t)(block_row + g0r)      * 2048 + g0c * 8;
    const size_t a_src1 = (size_t)(block_row + g0r + 64) * 2048 + g0c * 8;
    const size_t b_src0 = (size_t)(block_col + g0r)      * 2048 + g0c * 8;
    const size_t b_src1 = (size_t)(block_col + g0r + 64) * 2048 + g0c * 8;
    const uint32_t dst0 = g0r * TS + g0c * 16;
    const uint32_t dst1 = (g0r + 64) * TS + g0c * 16;

    const uint32_t a_lm  = (wm + (lane & 15)) * TS + (lane >> 4) * 16;
    // x4 B-load: lanes 0-15 -> nt even (k-lo/k-hi), lanes 16-31 -> nt odd
    const uint32_t b_lm4 = (wn + (lane & 7)) * TS + ((lane >> 3) & 1) * 16
                         + (lane >> 4) * (8 * TS);

    float acc[4][4][4];
#pragma unroll
    for (int i = 0; i < 4; i++)
#pragma unroll
        for (int j = 0; j < 4; j++)
#pragma unroll
            for (int r = 0; r < 4; r++) acc[i][j][r] = 0.f;

#define G_LOAD(kk, bufi) do {                                                  \
    const uint32_t bb_ = smb + (bufi) * (2 * TILE_B);                          \
    CP_ASYNC16(bb_ + dst0,          A + a_src0 + (kk));                        \
    CP_ASYNC16(bb_ + dst1,          A + a_src1 + (kk));                        \
    CP_ASYNC16(bb_ + TILE_B + dst0, B + b_src0 + (kk));                        \
    CP_ASYNC16(bb_ + TILE_B + dst1, B + b_src1 + (kk));                        \
} while (0)

    G_LOAD(0, 0);
    CP_COMMIT();
    G_LOAD(32, 1);
    CP_COMMIT();

    for (int i = 0; i < 64; i++) {
        if (i < 63) { CP_WAIT(1); } else { CP_WAIT(0); }
        __syncthreads();
        if (i + 2 < 64) {
            G_LOAD((i + 2) * 32, (i + 2) % NSTAGE);
            CP_COMMIT();
        }
        const uint32_t base = smb + (i % NSTAGE) * (2 * TILE_B);
#pragma unroll
        for (int ks = 0; ks < 2; ks++) {
            uint32_t afrag[4][4];
#pragma unroll
            for (int mt = 0; mt < 4; mt++)
                ldsm_x4(afrag[mt], base + a_lm + mt * (16 * TS) + ks * 32);
#pragma unroll
            for (int nt2 = 0; nt2 < 2; nt2++) {
                uint32_t bfr[4];
                ldsm_x4(bfr, base + TILE_B + b_lm4 + nt2 * (16 * TS) + ks * 32);
#pragma unroll
                for (int mt = 0; mt < 4; mt++) {
                    mma16816(acc[mt][2 * nt2],     afrag[mt], bfr);
                    mma16816(acc[mt][2 * nt2 + 1], afrag[mt], bfr + 2);
                }
            }
        }
    }

#pragma unroll
    for (int mt = 0; mt < 4; mt++) {
        const int row = block_row + wm + mt * 16 + lane / 4;
#pragma unroll
        for (int nt = 0; nt < 4; nt++) {
            const int col = block_col + wn + nt * 8 + (lane % 4) * 2;
            float v0 = alpha * acc[mt][nt][0];
            float v1 = alpha * acc[mt][nt][1];
            float v2 = alpha * acc[mt][nt][2];
            float v3 = alpha * acc[mt][nt][3];
            if (Cf) {
                *(float2*)(Cf + (size_t)row * 2048 + col)       = make_float2(v0, v1);
                *(float2*)(Cf + (size_t)(row + 8) * 2048 + col) = make_float2(v2, v3);
            } else {
                *(uint32_t*)(Ch + (size_t)row * 2048 + col)       = pack2h(v0, v1);
                *(uint32_t*)(Ch + (size_t)(row + 8) * 2048 + col) = pack2h(v2, v3);
            }
        }
    }
}

__global__ __launch_bounds__(256, 2)
void gemm_qkv_kernel(const __half* __restrict__ xq, const __half* __restrict__ xkv,
                     const __half* __restrict__ wqt, const __half* __restrict__ wkt,
                     const __half* __restrict__ wvt,
                     __half* __restrict__ qs, __half* __restrict__ ks,
                     __half* __restrict__ vs)
{
    extern __shared__ __align__(16) char smg[];
    const int z = blockIdx.z;
    const __half* A = (z == 0) ? xq : xkv;
    const __half* B = (z == 0) ? wqt : (z == 1) ? wkt : wvt;
    __half* C = (z == 0) ? qs : (z == 1) ? ks : vs;
    const float alpha = (z == 0) ? 0.125f : 1.0f;
    gemm_body(A, B, nullptr, C, alpha, smg, blockIdx.x, blockIdx.y);
}

__global__ __launch_bounds__(256, 2)
void gemm_out_kernel(const __half* __restrict__ cs, const __half* __restrict__ wot,
                     float* __restrict__ out)
{
    extern __shared__ __align__(16) char smg[];
    gemm_body(cs, wot, out, nullptr, 1.0f, smg, blockIdx.x, blockIdx.y);
}

// ============================================================================
// Flash attention (fp16): 3-stage KV ring, one sync per chunk,
// x4 ldmatrix, fp16 bias prefetched into registers one chunk ahead.
// ============================================================================
#define KVS 144
#define KVT (64 * KVS)
#define ATT_SMEM (3 * 2 * KVT)       // 55296

__global__ __launch_bounds__(256, 2)
void attn_mma(const __half* __restrict__ q,
              const __half* __restrict__ k,
              const __half* __restrict__ v,
              const __half* __restrict__ bias,
              __half* __restrict__ cs)
{
    extern __shared__ __align__(16) char sm[];
    const uint32_t smb = smem_u32(sm);

    const int tid  = threadIdx.x;
    const int wid  = tid / 32;
    const int lane = tid % 32;
    const int qt = blockIdx.x;
    const int h  = blockIdx.y;
    const int b  = blockIdx.z;
    const int g  = lane >> 2;
    const int t  = lane & 3;

    const int qrow  = qt * 128 + wid * 16 + g;
    const size_t arow = (size_t)(b * 2048 + qrow);
    const int dbase = h * 64;

    uint32_t qf[4][4];
    {
        const __half* q0 = q + arow * 2048 + dbase;
#pragma unroll
        for (int kk = 0; kk < 4; kk++) {
            qf[kk][0] = *(const uint32_t*)(q0 + kk * 16 + 2 * t);
            qf[kk][1] = *(const uint32_t*)(q0 + (size_t)8 * 2048 + kk * 16 + 2 * t);
            qf[kk][2] = *(const uint32_t*)(q0 + kk * 16 + 8 + 2 * t);
            qf[kk][3] = *(const uint32_t*)(q0 + (size_t)8 * 2048 + kk * 16 + 8 + 2 * t);
        }
    }

    float ctx[8][4];
#pragma unroll
    for (int nt = 0; nt < 8; nt++)
#pragma unroll
        for (int r = 0; r < 4; r++) ctx[nt][r] = 0.f;
    float m0 = -1e30f, m1 = -1e30f, l0 = 0.f, l1 = 0.f;

    const int lr  = tid >> 3;
    const int lgr = tid & 7;
#define LOAD_CHUNK(kc, bufi) do {                                              \
    const uint32_t base_ = smb + (bufi) * (2 * KVT);                           \
    _Pragma("unroll")                                                          \
    for (int i_ = 0; i_ < 4; i_++) {                                           \
        const __half* s_ = (i_ < 2) ? k : v;                                   \
        const int r_ = lr + 32 * (i_ & 1);                                     \
        const int mat_ = i_ >> 1;                                              \
        const __half* src_ = s_ +                                              \
            (size_t)(b * 2048 + (kc) + r_) * 2048 + dbase + lgr * 8;           \
        CP_ASYNC16(base_ + mat_ * KVT + r_ * KVS + lgr * 16, src_);            \
    }                                                                          \
} while (0)

    LOAD_CHUNK(0, 0);
    CP_COMMIT();
    LOAD_CHUNK(64, 1);
    CP_COMMIT();

    const __half* bias_b  = bias + (size_t)b * 2048 * 2048
                          + (size_t)(qt * 128 + wid * 16 + g) * 2048;
    const __half* bias_b8 = bias_b + (size_t)8 * 2048;

    // bias register double-buffer (fp16): 16 half2 regs
    __half2 pb[8], pb8[8];
#pragma unroll
    for (int nt = 0; nt < 8; nt++) {
        pb[nt]  = *(const __half2*)(bias_b  + nt * 8 + 2 * t);
        pb8[nt] = *(const __half2*)(bias_b8 + nt * 8 + 2 * t);
    }

    // x4 ldmatrix lane addresses
    const uint32_t kaddr4 = (lane & 7) * KVS + ((lane >> 3) & 1) * 16
                          + (lane >> 4) * (8 * KVS);
    const uint32_t vaddr4 = (lane & 15) * KVS + (lane >> 4) * 16;

    for (int c = 0; c < 32; c++) {
        if (c < 31) { CP_WAIT(1); } else { CP_WAIT(0); }
        __syncthreads();
        if (c + 2 < 32) {
            LOAD_CHUNK((c + 2) * 64, (c + 2) % 3);
            CP_COMMIT();
        }

        const uint32_t k_s = smb + (c % 3) * (2 * KVT);
        const uint32_t v_s = k_s + KVT;

        // ---- S init from prefetched bias regs
        float s[8][4];
#pragma unroll
        for (int nt = 0; nt < 8; nt++) {
            s[nt][0] = __low2float(pb[nt]);
            s[nt][1] = __high2float(pb[nt]);
            s[nt][2] = __low2float(pb8[nt]);
            s[nt][3] = __high2float(pb8[nt]);
        }
        // ---- prefetch bias for chunk c+1 (latency hidden behind MMAs)
        if (c + 1 < 32) {
            const __half* nb  = bias_b  + (c + 1) * 64;
            const __half* nb8 = bias_b8 + (c + 1) * 64;
#pragma unroll
            for (int nt = 0; nt < 8; nt++) {
                pb[nt]  = *(const __half2*)(nb  + nt * 8 + 2 * t);
                pb8[nt] = *(const __half2*)(nb8 + nt * 8 + 2 * t);
            }
        }

        // ---- QK: x4 B loads
#pragma unroll
        for (int kk = 0; kk < 4; kk++) {
#pragma unroll
            for (int nt2 = 0; nt2 < 4; nt2++) {
                uint32_t bfr[4];
                ldsm_x4(bfr, k_s + nt2 * (16 * KVS) + kaddr4 + kk * 32);
                mma16816(s[2 * nt2],     qf[kk], bfr);
                mma16816(s[2 * nt2 + 1], qf[kk], bfr + 2);
            }
        }

        // ---- online softmax
        float mx0 = -1e30f, mx1 = -1e30f;
#pragma unroll
        for (int nt = 0; nt < 8; nt++) {
            mx0 = fmaxf(mx0, fmaxf(s[nt][0], s[nt][1]));
            mx1 = fmaxf(mx1, fmaxf(s[nt][2], s[nt][3]));
        }
        mx0 = fmaxf(mx0, __shfl_xor_sync(0xffffffffu, mx0, 1));
        mx0 = fmaxf(mx0, __shfl_xor_sync(0xffffffffu, mx0, 2));
        mx1 = fmaxf(mx1, __shfl_xor_sync(0xffffffffu, mx1, 1));
        mx1 = fmaxf(mx1, __shfl_xor_sync(0xffffffffu, mx1, 2));
        const float mn0 = fmaxf(m0, mx0);
        const float mn1 = fmaxf(m1, mx1);
        const float sc0 = __expf(m0 - mn0);
        const float sc1 = __expf(m1 - mn1);
        m0 = mn0; m1 = mn1;

        uint32_t p01[8], p23[8];
        float rs0 = 0.f, rs1 = 0.f;
#pragma unroll
        for (int nt = 0; nt < 8; nt++) {
            float e0 = __expf(s[nt][0] - mn0);
            float e1 = __expf(s[nt][1] - mn0);
            float e2 = __expf(s[nt][2] - mn1);
            float e3 = __expf(s[nt][3] - mn1);
            __half2 h01 = __floats2half2_rn(e0, e1);
            __half2 h23 = __floats2half2_rn(e2, e3);
            p01[nt] = *(uint32_t*)&h01;
            p23[nt] = *(uint32_t*)&h23;
            rs0 += __low2float(h01) + __high2float(h01);
            rs1 += __low2float(h23) + __high2float(h23);
        }
        rs0 += __shfl_xor_sync(0xffffffffu, rs0, 1);
        rs0 += __shfl_xor_sync(0xffffffffu, rs0, 2);
        rs1 += __shfl_xor_sync(0xffffffffu, rs1, 1);
        rs1 += __shfl_xor_sync(0xffffffffu, rs1, 2);
        l0 = l0 * sc0 + rs0;
        l1 = l1 * sc1 + rs1;

#pragma unroll
        for (int nt = 0; nt < 8; nt++) {
            ctx[nt][0] *= sc0; ctx[nt][1] *= sc0;
            ctx[nt][2] *= sc1; ctx[nt][3] *= sc1;
        }

        // ---- PV: x4.trans V loads
#pragma unroll
        for (int j = 0; j < 4; j++) {
            const uint32_t pa[4] = {p01[2 * j], p23[2 * j], p01[2 * j + 1], p23[2 * j + 1]};
#pragma unroll
            for (int nt2 = 0; nt2 < 4; nt2++) {
                uint32_t bvr[4];
                ldsm_x4_t(bvr, v_s + j * (16 * KVS) + vaddr4 + nt2 * 32);
                mma16816(ctx[2 * nt2],     pa, bvr);
                mma16816(ctx[2 * nt2 + 1], pa, bvr + 2);
            }
        }
    }

    const float inv0 = 1.f / l0;
    const float inv1 = 1.f / l1;
#pragma unroll
    for (int nt = 0; nt < 8; nt++) {
        const int col = dbase + nt * 8 + 2 * t;
        *(uint32_t*)(cs + arow * 2048 + col) =
            pack2h(ctx[nt][0] * inv0, ctx[nt][1] * inv0);
        *(uint32_t*)(cs + (arow + 8) * 2048 + col) =
            pack2h(ctx[nt][2] * inv1, ctx[nt][3] * inv1);
    }
}

// ============================================================================
// Launch
// ============================================================================
extern "C" void kernel_launch(void* const* d_in, const int* in_sizes, int n_in,
                              void* d_out, int out_size)
{
    const float* inputs_q  = (const float*)d_in[0];
    const float* inputs_kv = (const float*)d_in[1];
    const float* bias      = (const float*)d_in[2];
    const float* wq        = (const float*)d_in[3];
    const float* wk        = (const float*)d_in[4];
    const float* wv        = (const float*)d_in[5];
    const float* wo        = (const float*)d_in[6];
    float* out = (float*)d_out;

    __half *xq, *xkv, *bh, *qs, *ks, *vs, *cs;
    __half *wqt, *wkt, *wvt, *wot;
    cudaGetSymbolAddress((void**)&xq,  g_xq);
    cudaGetSymbolAddress((void**)&xkv, g_xkv);
    cudaGetSymbolAddress((void**)&bh,  g_bh);
    cudaGetSymbolAddress((void**)&qs,  g_qs);
    cudaGetSymbolAddress((void**)&ks,  g_ks);
    cudaGetSymbolAddress((void**)&vs,  g_vs);
    cudaGetSymbolAddress((void**)&cs,  g_cs);
    cudaGetSymbolAddress((void**)&wqt, g_wqt);
    cudaGetSymbolAddress((void**)&wkt, g_wkt);
    cudaGetSymbolAddress((void**)&wvt, g_wvt);
    cudaGetSymbolAddress((void**)&wot, g_wot);

    static bool attr_done = false;
    if (!attr_done) {
        cudaFuncSetAttribute(attn_mma, cudaFuncAttributeMaxDynamicSharedMemorySize,
                             ATT_SMEM);
        cudaFuncSetAttribute(gemm_qkv_kernel, cudaFuncAttributeMaxDynamicSharedMemorySize,
                             GEMM_SMEM);
        cudaFuncSetAttribute(gemm_out_kernel, cudaFuncAttributeMaxDynamicSharedMemorySize,
                             GEMM_SMEM);
        attr_done = true;
    }

    const int n_act = ROWS * EMB;                     // 8388608 (== bias elems)
    const dim3 ggrid(EMB / 128, ROWS / 128);          // (16, 32)
    const dim3 gqkv(EMB / 128, ROWS / 128, 3);

    // Prep: 2 launches (activations + bias -> fp16; weights -> fp16 transposed)
    conv_all_kernel<<<dim3(n_act / 1024, 3), 256>>>(inputs_q, xq, inputs_kv, xkv,
                                                    bias, bh);
    wconv_all_kernel<<<dim3(64, 64, 4), 256>>>(wq, wqt, wk, wkt, wv, wvt, wo, wot);

    // Fused Q/K/V projections
    gemm_qkv_kernel<<<gqkv, 256, GEMM_SMEM>>>(xq, xkv, wqt, wkt, wvt, qs, ks, vs);

    // Flash attention -> single fp16 ctx
    attn_mma<<<dim3(16, 32, 2), 256, ATT_SMEM>>>(qs, ks, vs, bh, cs);

    // Output projection -> f32 out
    gemm_out_kernel<<<ggrid, 256, GEMM_SMEM>>>(cs, wot, out);
}

// round 13
// speedup vs baseline: 7.7643x; 1.0077x over previous
#include <cuda_runtime.h>
#include <cuda_fp16.h>
#include <cstdint>

// Problem constants
#define BB   2
#define QQ   2048
#define KK   2048
#define EMB  2048
#define HH   32
#define DD   64
#define ROWS (BB * QQ)          // 4096

// ---------------- scratch (device globals; no allocation allowed) ----------
__device__ __half g_xq [ROWS * EMB];
__device__ __half g_xkv[ROWS * EMB];
__device__ __half g_bh [BB * QQ * KK];   // bias in fp16
__device__ __half g_qs [ROWS * EMB];
__device__ __half g_ks [ROWS * EMB];
__device__ __half g_vs [ROWS * EMB];
__device__ __half g_cs [ROWS * EMB];

__device__ __half g_wqt[EMB * EMB];
__device__ __half g_wkt[EMB * EMB];
__device__ __half g_wvt[EMB * EMB];
__device__ __half g_wot[EMB * EMB];

// ---------------- helpers ---------------------------------------------------
__device__ __forceinline__ uint32_t smem_u32(const void* p) {
    uint32_t a;
    asm("{ .reg .u64 t; cvta.to.shared.u64 t, %1; cvt.u32.u64 %0, t; }"
        : "=r"(a) : "l"(p));
    return a;
}

#define CP_ASYNC16(dst, src) \
    asm volatile("cp.async.cg.shared.global [%0], [%1], 16;" :: "r"(dst), "l"(src))
#define CP_COMMIT() asm volatile("cp.async.commit_group;" ::: "memory")
#define CP_WAIT(n)  asm volatile("cp.async.wait_group %0;" :: "n"(n) : "memory")

__device__ __forceinline__ void ldsm_x4(uint32_t* d, uint32_t addr) {
    asm volatile("ldmatrix.sync.aligned.m8n8.x4.shared.b16 {%0,%1,%2,%3}, [%4];"
                 : "=r"(d[0]), "=r"(d[1]), "=r"(d[2]), "=r"(d[3]) : "r"(addr));
}
__device__ __forceinline__ void ldsm_x4_t(uint32_t* d, uint32_t addr) {
    asm volatile("ldmatrix.sync.aligned.m8n8.x4.trans.shared.b16 {%0,%1,%2,%3}, [%4];"
                 : "=r"(d[0]), "=r"(d[1]), "=r"(d[2]), "=r"(d[3]) : "r"(addr));
}
__device__ __forceinline__ void mma16816(float* d, const uint32_t* a, const uint32_t* b) {
    asm volatile(
        "mma.sync.aligned.m16n8k16.row.col.f32.f16.f16.f32 "
        "{%0,%1,%2,%3}, {%4,%5,%6,%7}, {%8,%9}, {%0,%1,%2,%3};"
        : "+f"(d[0]), "+f"(d[1]), "+f"(d[2]), "+f"(d[3])
        : "r"(a[0]), "r"(a[1]), "r"(a[2]), "r"(a[3]), "r"(b[0]), "r"(b[1]));
}

__device__ __forceinline__ uint32_t pack2h(float a, float b) {
    __half2 h = __floats2half2_rn(a, b);
    return *(uint32_t*)&h;
}

// ============================================================================
// Elementwise fp32 -> fp16 convert; blockIdx.y selects tensor (xq/xkv/bias)
// ============================================================================
__global__ __launch_bounds__(256)
void conv_all_kernel(const float* __restrict__ x0, __half* __restrict__ y0,
                     const float* __restrict__ x1, __half* __restrict__ y1,
                     const float* __restrict__ x2, __half* __restrict__ y2)
{
    const float* x = (blockIdx.y == 0) ? x0 : (blockIdx.y == 1) ? x1 : x2;
    __half* y = (blockIdx.y == 0) ? y0 : (blockIdx.y == 1) ? y1 : y2;
    size_t i = ((size_t)blockIdx.x * 256 + threadIdx.x) * 4;
    float4 v = *(const float4*)(x + i);
    __half2* p = (__half2*)(y + i);
    p[0] = __floats2half2_rn(v.x, v.y);
    p[1] = __floats2half2_rn(v.z, v.w);
}

// ============================================================================
// Weight transpose to single fp16, blockIdx.z selects weight
// ============================================================================
__global__ __launch_bounds__(256)
void wconv_all_kernel(const float* __restrict__ w0, __half* __restrict__ t0,
                      const float* __restrict__ w1, __half* __restrict__ t1,
                      const float* __restrict__ w2, __half* __restrict__ t2,
                      const float* __restrict__ w3, __half* __restrict__ t3)
{
    const float* w = (blockIdx.z == 0) ? w0 : (blockIdx.z == 1) ? w1
                    : (blockIdx.z == 2) ? w2 : w3;
    __half* th = (blockIdx.z == 0) ? t0 : (blockIdx.z == 1) ? t1
                : (blockIdx.z == 2) ? t2 : t3;
    __shared__ float tile[32][33];
    const int bx = blockIdx.x * 32;
    const int by = blockIdx.y * 32;
    const int tx = threadIdx.x % 32;
    const int ty = threadIdx.x / 32;
#pragma unroll
    for (int j = 0; j < 32; j += 8)
        tile[ty + j][tx] = w[(size_t)(by + ty + j) * 2048 + bx + tx];
    __syncthreads();
#pragma unroll
    for (int j = 0; j < 32; j += 8)
        th[(size_t)(bx + ty + j) * 2048 + by + tx] = __float2half(tile[tx][ty + j]);
}

// ============================================================================
// fp16 GEMM body: C = alpha * A*B^T. Unchanged from R12.
// ============================================================================
#define TS      80
#define TILE_B  (128 * TS)
#define NSTAGE  3
#define GEMM_SMEM (NSTAGE * 2 * TILE_B)   // 61440

__device__ __forceinline__
void gemm_body(const __half* __restrict__ A, const __half* __restrict__ B,
               float* __restrict__ Cf, __half* __restrict__ Ch, float alpha,
               char* smg, int bx, int by)
{
    const uint32_t smb = smem_u32(smg);
    const int tid  = threadIdx.x;
    const int wid  = tid / 32;
    const int lane = tid % 32;
    const int block_row = by * 128;
    const int block_col = bx * 128;

    const int wm = (wid & 1) * 64;
    const int wn = (wid >> 1) * 32;

    const int g0r = tid >> 2;
    const int g0c = tid & 3;
    const size_t a_src0 = (size_t)(block_row + g0r)      * 2048 + g0c * 8;
    const size_t a_src1 = (size_t)(block_row + g0r + 64) * 2048 + g0c * 8;
    const size_t b_src0 = (size_t)(block_col + g0r)      * 2048 + g0c * 8;
    const size_t b_src1 = (size_t)(block_col + g0r + 64) * 2048 + g0c * 8;
    const uint32_t dst0 = g0r * TS + g0c * 16;
    const uint32_t dst1 = (g0r + 64) * TS + g0c * 16;

    const uint32_t a_lm  = (wm + (lane & 15)) * TS + (lane >> 4) * 16;
    const uint32_t b_lm4 = (wn + (lane & 7)) * TS + ((lane >> 3) & 1) * 16
                         + (lane >> 4) * (8 * TS);

    float acc[4][4][4];
#pragma unroll
    for (int i = 0; i < 4; i++)
#pragma unroll
        for (int j = 0; j < 4; j++)
#pragma unroll
            for (int r = 0; r < 4; r++) acc[i][j][r] = 0.f;

#define G_LOAD(kk, bufi) do {                                                  \
    const uint32_t bb_ = smb + (bufi) * (2 * TILE_B);                          \
    CP_ASYNC16(bb_ + dst0,          A + a_src0 + (kk));                        \
    CP_ASYNC16(bb_ + dst1,          A + a_src1 + (kk));                        \
    CP_ASYNC16(bb_ + TILE_B + dst0, B + b_src0 + (kk));                        \
    CP_ASYNC16(bb_ + TILE_B + dst1, B + b_src1 + (kk));                        \
} while (0)

    G_LOAD(0, 0);
    CP_COMMIT();
    G_LOAD(32, 1);
    CP_COMMIT();

    for (int i = 0; i < 64; i++) {
        if (i < 63) { CP_WAIT(1); } else { CP_WAIT(0); }
        __syncthreads();
        if (i + 2 < 64) {
            G_LOAD((i + 2) * 32, (i + 2) % NSTAGE);
            CP_COMMIT();
        }
        const uint32_t base = smb + (i % NSTAGE) * (2 * TILE_B);
#pragma unroll
        for (int ks = 0; ks < 2; ks++) {
            uint32_t afrag[4][4];
#pragma unroll
            for (int mt = 0; mt < 4; mt++)
                ldsm_x4(afrag[mt], base + a_lm + mt * (16 * TS) + ks * 32);
#pragma unroll
            for (int nt2 = 0; nt2 < 2; nt2++) {
                uint32_t bfr[4];
                ldsm_x4(bfr, base + TILE_B + b_lm4 + nt2 * (16 * TS) + ks * 32);
#pragma unroll
                for (int mt = 0; mt < 4; mt++) {
                    mma16816(acc[mt][2 * nt2],     afrag[mt], bfr);
                    mma16816(acc[mt][2 * nt2 + 1], afrag[mt], bfr + 2);
                }
            }
        }
    }

#pragma unroll
    for (int mt = 0; mt < 4; mt++) {
        const int row = block_row + wm + mt * 16 + lane / 4;
#pragma unroll
        for (int nt = 0; nt < 4; nt++) {
            const int col = block_col + wn + nt * 8 + (lane % 4) * 2;
            float v0 = alpha * acc[mt][nt][0];
            float v1 = alpha * acc[mt][nt][1];
            float v2 = alpha * acc[mt][nt][2];
            float v3 = alpha * acc[mt][nt][3];
            if (Cf) {
                *(float2*)(Cf + (size_t)row * 2048 + col)       = make_float2(v0, v1);
                *(float2*)(Cf + (size_t)(row + 8) * 2048 + col) = make_float2(v2, v3);
            } else {
                *(uint32_t*)(Ch + (size_t)row * 2048 + col)       = pack2h(v0, v1);
                *(uint32_t*)(Ch + (size_t)(row + 8) * 2048 + col) = pack2h(v2, v3);
            }
        }
    }
}

__global__ __launch_bounds__(256, 2)
void gemm_qkv_kernel(const __half* __restrict__ xq, const __half* __restrict__ xkv,
                     const __half* __restrict__ wqt, const __half* __restrict__ wkt,
                     const __half* __restrict__ wvt,
                     __half* __restrict__ qs, __half* __restrict__ ks,
                     __half* __restrict__ vs)
{
    extern __shared__ __align__(16) char smg[];
    const int z = blockIdx.z;
    const __half* A = (z == 0) ? xq : xkv;
    const __half* B = (z == 0) ? wqt : (z == 1) ? wkt : wvt;
    __half* C = (z == 0) ? qs : (z == 1) ? ks : vs;
    const float alpha = (z == 0) ? 0.125f : 1.0f;
    gemm_body(A, B, nullptr, C, alpha, smg, blockIdx.x, blockIdx.y);
}

__global__ __launch_bounds__(256, 2)
void gemm_out_kernel(const __half* __restrict__ cs, const __half* __restrict__ wot,
                     float* __restrict__ out)
{
    extern __shared__ __align__(16) char smg[];
    gemm_body(cs, wot, out, nullptr, 1.0f, smg, blockIdx.x, blockIdx.y);
}

// ============================================================================
// Flash attention (fp16): 4 warps x 32 q-rows (2 m-tiles each) — every K/V
// fragment feeds 2 MMAs, halving smem ldmatrix traffic vs 8x16 layout.
// 3-stage KV ring, one sync per chunk, fp16 bias prefetched in registers.
// ============================================================================
#define KVS 144
#define KVT (64 * KVS)
#define ATT_SMEM (3 * 2 * KVT)       // 55296

__global__ __launch_bounds__(128, 2)
void attn_mma(const __half* __restrict__ q,
              const __half* __restrict__ k,
              const __half* __restrict__ v,
              const __half* __restrict__ bias,
              __half* __restrict__ cs)
{
    extern __shared__ __align__(16) char sm[];
    const uint32_t smb = smem_u32(sm);

    const int tid  = threadIdx.x;
    const int wid  = tid / 32;          // 0..3
    const int lane = tid % 32;
    const int qt = blockIdx.x;
    const int h  = blockIdx.y;
    const int b  = blockIdx.z;
    const int g  = lane >> 2;
    const int t  = lane & 3;

    const int qrow  = qt * 128 + wid * 32 + g;      // m-tile 0 row (thread)
    const size_t arow = (size_t)(b * 2048 + qrow);
    const int dbase = h * 64;

    // ---- Q fragments: 2 m-tiles x 4 k-tiles
    uint32_t qf[2][4][4];
#pragma unroll
    for (int mt = 0; mt < 2; mt++) {
        const __half* q0 = q + (arow + mt * 16) * 2048 + dbase;
#pragma unroll
        for (int kk = 0; kk < 4; kk++) {
            qf[mt][kk][0] = *(const uint32_t*)(q0 + kk * 16 + 2 * t);
            qf[mt][kk][1] = *(const uint32_t*)(q0 + (size_t)8 * 2048 + kk * 16 + 2 * t);
            qf[mt][kk][2] = *(const uint32_t*)(q0 + kk * 16 + 8 + 2 * t);
            qf[mt][kk][3] = *(const uint32_t*)(q0 + (size_t)8 * 2048 + kk * 16 + 8 + 2 * t);
        }
    }

    float ctx[2][8][4];
#pragma unroll
    for (int mt = 0; mt < 2; mt++)
#pragma unroll
        for (int nt = 0; nt < 8; nt++)
#pragma unroll
            for (int r = 0; r < 4; r++) ctx[mt][nt][r] = 0.f;
    // softmax state: index = mt*2 + half (rows g / g+8)
    float m[4] = {-1e30f, -1e30f, -1e30f, -1e30f};
    float l[4] = {0.f, 0.f, 0.f, 0.f};

    // ---- chunk loader: 128 threads, 8 granules each (K,V tiles 64x128B)
#define LOAD_CHUNK(kc, bufi) do {                                              \
    const uint32_t base_ = smb + (bufi) * (2 * KVT);                           \
    _Pragma("unroll")                                                          \
    for (int i_ = 0; i_ < 8; i_++) {                                           \
        const __half* s_ = (i_ < 4) ? k : v;                                   \
        const int mat_ = i_ >> 2;                                              \
        const int idx_ = tid + 128 * (i_ & 3);     /* 0..511 */                \
        const int r_ = idx_ >> 3;                                              \
        const int c_ = idx_ & 7;                                               \
        const __half* src_ = s_ +                                              \
            (size_t)(b * 2048 + (kc) + r_) * 2048 + dbase + c_ * 8;            \
        CP_ASYNC16(base_ + mat_ * KVT + r_ * KVS + c_ * 16, src_);             \
    }                                                                          \
} while (0)

    LOAD_CHUNK(0, 0);
    CP_COMMIT();
    LOAD_CHUNK(64, 1);
    CP_COMMIT();

    // bias pointers per m-tile (rows g and g+8)
    const __half* bias_p[2][2];
#pragma unroll
    for (int mt = 0; mt < 2; mt++) {
        bias_p[mt][0] = bias + (size_t)b * 2048 * 2048
                      + (size_t)(qrow + mt * 16) * 2048;
        bias_p[mt][1] = bias_p[mt][0] + (size_t)8 * 2048;
    }

    // bias register double-buffer: [mt][half][nt]
    __half2 pb[2][2][8];
#pragma unroll
    for (int mt = 0; mt < 2; mt++)
#pragma unroll
        for (int hf = 0; hf < 2; hf++)
#pragma unroll
            for (int nt = 0; nt < 8; nt++)
                pb[mt][hf][nt] = *(const __half2*)(bias_p[mt][hf] + nt * 8 + 2 * t);

    const uint32_t kaddr4 = (lane & 7) * KVS + ((lane >> 3) & 1) * 16
                          + (lane >> 4) * (8 * KVS);
    const uint32_t vaddr4 = (lane & 15) * KVS + (lane >> 4) * 16;

    for (int c = 0; c < 32; c++) {
        if (c < 31) { CP_WAIT(1); } else { CP_WAIT(0); }
        __syncthreads();
        if (c + 2 < 32) {
            LOAD_CHUNK((c + 2) * 64, (c + 2) % 3);
            CP_COMMIT();
        }

        const uint32_t k_s = smb + (c % 3) * (2 * KVT);
        const uint32_t v_s = k_s + KVT;

        // ---- S init from prefetched bias regs
        float s[2][8][4];
#pragma unroll
        for (int mt = 0; mt < 2; mt++)
#pragma unroll
            for (int nt = 0; nt < 8; nt++) {
                s[mt][nt][0] = __low2float(pb[mt][0][nt]);
                s[mt][nt][1] = __high2float(pb[mt][0][nt]);
                s[mt][nt][2] = __low2float(pb[mt][1][nt]);
                s[mt][nt][3] = __high2float(pb[mt][1][nt]);
            }
        // ---- prefetch bias for chunk c+1
        if (c + 1 < 32) {
#pragma unroll
            for (int mt = 0; mt < 2; mt++)
#pragma unroll
                for (int hf = 0; hf < 2; hf++)
#pragma unroll
                    for (int nt = 0; nt < 8; nt++)
                        pb[mt][hf][nt] = *(const __half2*)(bias_p[mt][hf]
                                          + (c + 1) * 64 + nt * 8 + 2 * t);
        }

        // ---- QK: each K fragment feeds both m-tiles
#pragma unroll
        for (int kk = 0; kk < 4; kk++) {
#pragma unroll
            for (int nt2 = 0; nt2 < 4; nt2++) {
                uint32_t bfr[4];
                ldsm_x4(bfr, k_s + nt2 * (16 * KVS) + kaddr4 + kk * 32);
#pragma unroll
                for (int mt = 0; mt < 2; mt++) {
                    mma16816(s[mt][2 * nt2],     qf[mt][kk], bfr);
                    mma16816(s[mt][2 * nt2 + 1], qf[mt][kk], bfr + 2);
                }
            }
        }

        // ---- online softmax (per m-tile, per row-half)
        uint32_t p01[2][8], p23[2][8];
        float sc[4];
#pragma unroll
        for (int mt = 0; mt < 2; mt++) {
            float mx0 = -1e30f, mx1 = -1e30f;
#pragma unroll
            for (int nt = 0; nt < 8; nt++) {
                mx0 = fmaxf(mx0, fmaxf(s[mt][nt][0], s[mt][nt][1]));
                mx1 = fmaxf(mx1, fmaxf(s[mt][nt][2], s[mt][nt][3]));
            }
            mx0 = fmaxf(mx0, __shfl_xor_sync(0xffffffffu, mx0, 1));
            mx0 = fmaxf(mx0, __shfl_xor_sync(0xffffffffu, mx0, 2));
            mx1 = fmaxf(mx1, __shfl_xor_sync(0xffffffffu, mx1, 1));
            mx1 = fmaxf(mx1, __shfl_xor_sync(0xffffffffu, mx1, 2));
            const float mn0 = fmaxf(m[2 * mt],     mx0);
            const float mn1 = fmaxf(m[2 * mt + 1], mx1);
            sc[2 * mt]     = __expf(m[2 * mt] - mn0);
            sc[2 * mt + 1] = __expf(m[2 * mt + 1] - mn1);
            m[2 * mt] = mn0; m[2 * mt + 1] = mn1;

            float rs0 = 0.f, rs1 = 0.f;
#pragma unroll
            for (int nt = 0; nt < 8; nt++) {
                float e0 = __expf(s[mt][nt][0] - mn0);
                float e1 = __expf(s[mt][nt][1] - mn0);
                float e2 = __expf(s[mt][nt][2] - mn1);
                float e3 = __expf(s[mt][nt][3] - mn1);
                __half2 h01 = __floats2half2_rn(e0, e1);
                __half2 h23 = __floats2half2_rn(e2, e3);
                p01[mt][nt] = *(uint32_t*)&h01;
                p23[mt][nt] = *(uint32_t*)&h23;
                rs0 += __low2float(h01) + __high2float(h01);
                rs1 += __low2float(h23) + __high2float(h23);
            }
            rs0 += __shfl_xor_sync(0xffffffffu, rs0, 1);
            rs0 += __shfl_xor_sync(0xffffffffu, rs0, 2);
            rs1 += __shfl_xor_sync(0xffffffffu, rs1, 1);
            rs1 += __shfl_xor_sync(0xffffffffu, rs1, 2);
            l[2 * mt]     = l[2 * mt]     * sc[2 * mt]     + rs0;
            l[2 * mt + 1] = l[2 * mt + 1] * sc[2 * mt + 1] + rs1;

#pragma unroll
            for (int nt = 0; nt < 8; nt++) {
                ctx[mt][nt][0] *= sc[2 * mt];     ctx[mt][nt][1] *= sc[2 * mt];
                ctx[mt][nt][2] *= sc[2 * mt + 1]; ctx[mt][nt][3] *= sc[2 * mt + 1];
            }
        }

        // ---- PV: each V fragment feeds both m-tiles
#pragma unroll
        for (int j = 0; j < 4; j++) {
            uint32_t pa[2][4];
#pragma unroll
            for (int mt = 0; mt < 2; mt++) {
                pa[mt][0] = p01[mt][2 * j];
                pa[mt][1] = p23[mt][2 * j];
                pa[mt][2] = p01[mt][2 * j + 1];
                pa[mt][3] = p23[mt][2 * j + 1];
            }
#pragma unroll
            for (int nt2 = 0; nt2 < 4; nt2++) {
                uint32_t bvr[4];
                ldsm_x4_t(bvr, v_s + j * (16 * KVS) + vaddr4 + nt2 * 32);
#pragma unroll
                for (int mt = 0; mt < 2; mt++) {
                    mma16816(ctx[mt][2 * nt2],     pa[mt], bvr);
                    mma16816(ctx[mt][2 * nt2 + 1], pa[mt], bvr + 2);
                }
            }
        }
    }

    // ---- epilogue
#pragma unroll
    for (int mt = 0; mt < 2; mt++) {
        const float inv0 = 1.f / l[2 * mt];
        const float inv1 = 1.f / l[2 * mt + 1];
        const size_t r0 = arow + mt * 16;
#pragma unroll
        for (int nt = 0; nt < 8; nt++) {
            const int col = dbase + nt * 8 + 2 * t;
            *(uint32_t*)(cs + r0 * 2048 + col) =
                pack2h(ctx[mt][nt][0] * inv0, ctx[mt][nt][1] * inv0);
            *(uint32_t*)(cs + (r0 + 8) * 2048 + col) =
                pack2h(ctx[mt][nt][2] * inv1, ctx[mt][nt][3] * inv1);
        }
    }
}

// ============================================================================
// Launch
// ============================================================================
extern "C" void kernel_launch(void* const* d_in, const int* in_sizes, int n_in,
                              void* d_out, int out_size)
{
    const float* inputs_q  = (const float*)d_in[0];
    const float* inputs_kv = (const float*)d_in[1];
    const float* bias      = (const float*)d_in[2];
    const float* wq        = (const float*)d_in[3];
    const float* wk        = (const float*)d_in[4];
    const float* wv        = (const float*)d_in[5];
    const float* wo        = (const float*)d_in[6];
    float* out = (float*)d_out;

    __half *xq, *xkv, *bh, *qs, *ks, *vs, *cs;
    __half *wqt, *wkt, *wvt, *wot;
    cudaGetSymbolAddress((void**)&xq,  g_xq);
    cudaGetSymbolAddress((void**)&xkv, g_xkv);
    cudaGetSymbolAddress((void**)&bh,  g_bh);
    cudaGetSymbolAddress((void**)&qs,  g_qs);
    cudaGetSymbolAddress((void**)&ks,  g_ks);
    cudaGetSymbolAddress((void**)&vs,  g_vs);
    cudaGetSymbolAddress((void**)&cs,  g_cs);
    cudaGetSymbolAddress((void**)&wqt, g_wqt);
    cudaGetSymbolAddress((void**)&wkt, g_wkt);
    cudaGetSymbolAddress((void**)&wvt, g_wvt);
    cudaGetSymbolAddress((void**)&wot, g_wot);

    static bool attr_done = false;
    if (!attr_done) {
        cudaFuncSetAttribute(attn_mma, cudaFuncAttributeMaxDynamicSharedMemorySize,
                             ATT_SMEM);
        cudaFuncSetAttribute(gemm_qkv_kernel, cudaFuncAttributeMaxDynamicSharedMemorySize,
                             GEMM_SMEM);
        cudaFuncSetAttribute(gemm_out_kernel, cudaFuncAttributeMaxDynamicSharedMemorySize,
                             GEMM_SMEM);
        attr_done = true;
    }

    const int n_act = ROWS * EMB;
    const dim3 ggrid(EMB / 128, ROWS / 128);          // (16, 32)
    const dim3 gqkv(EMB / 128, ROWS / 128, 3);

    // Prep: 2 launches
    conv_all_kernel<<<dim3(n_act / 1024, 3), 256>>>(inputs_q, xq, inputs_kv, xkv,
                                                    bias, bh);
    wconv_all_kernel<<<dim3(64, 64, 4), 256>>>(wq, wqt, wk, wkt, wv, wvt, wo, wot);

    // Fused Q/K/V projections
    gemm_qkv_kernel<<<gqkv, 256, GEMM_SMEM>>>(xq, xkv, wqt, wkt, wvt, qs, ks, vs);

    // Flash attention (4 warps x 32 rows) -> single fp16 ctx
    attn_mma<<<dim3(16, 32, 2), 128, ATT_SMEM>>>(qs, ks, vs, bh, cs);

    // Output projection -> f32 out
    gemm_out_kernel<<<ggrid, 256, GEMM_SMEM>>>(cs, wot, out);
}

// round 14
// speedup vs baseline: 8.2729x; 1.0655x over previous
#include <cuda_runtime.h>
#include <cuda_fp16.h>
#include <cstdint>

// Problem constants
#define BB   2
#define QQ   2048
#define KK   2048
#define EMB  2048
#define HH   32
#define DD   64
#define ROWS (BB * QQ)          // 4096

// ---------------- scratch (device globals; no allocation allowed) ----------
__device__ __half g_xq [ROWS * EMB];
__device__ __half g_xkv[ROWS * EMB];
__device__ __half g_bh [BB * QQ * KK];   // bias in fp16
__device__ __half g_qs [ROWS * EMB];
__device__ __half g_ks [ROWS * EMB];
__device__ __half g_vs [ROWS * EMB];
__device__ __half g_cs [ROWS * EMB];

__device__ __half g_wqt[EMB * EMB];
__device__ __half g_wkt[EMB * EMB];
__device__ __half g_wvt[EMB * EMB];
__device__ __half g_wot[EMB * EMB];

// ---------------- helpers ---------------------------------------------------
__device__ __forceinline__ uint32_t smem_u32(const void* p) {
    uint32_t a;
    asm("{ .reg .u64 t; cvta.to.shared.u64 t, %1; cvt.u32.u64 %0, t; }"
        : "=r"(a) : "l"(p));
    return a;
}

#define CP_ASYNC16(dst, src) \
    asm volatile("cp.async.cg.shared.global [%0], [%1], 16;" :: "r"(dst), "l"(src))
#define CP_COMMIT() asm volatile("cp.async.commit_group;" ::: "memory")
#define CP_WAIT(n)  asm volatile("cp.async.wait_group %0;" :: "n"(n) : "memory")

__device__ __forceinline__ void ldsm_x4(uint32_t* d, uint32_t addr) {
    asm volatile("ldmatrix.sync.aligned.m8n8.x4.shared.b16 {%0,%1,%2,%3}, [%4];"
                 : "=r"(d[0]), "=r"(d[1]), "=r"(d[2]), "=r"(d[3]) : "r"(addr));
}
__device__ __forceinline__ void ldsm_x4_t(uint32_t* d, uint32_t addr) {
    asm volatile("ldmatrix.sync.aligned.m8n8.x4.trans.shared.b16 {%0,%1,%2,%3}, [%4];"
                 : "=r"(d[0]), "=r"(d[1]), "=r"(d[2]), "=r"(d[3]) : "r"(addr));
}
__device__ __forceinline__ void mma16816(float* d, const uint32_t* a, const uint32_t* b) {
    asm volatile(
        "mma.sync.aligned.m16n8k16.row.col.f32.f16.f16.f32 "
        "{%0,%1,%2,%3}, {%4,%5,%6,%7}, {%8,%9}, {%0,%1,%2,%3};"
        : "+f"(d[0]), "+f"(d[1]), "+f"(d[2]), "+f"(d[3])
        : "r"(a[0]), "r"(a[1]), "r"(a[2]), "r"(a[3]), "r"(b[0]), "r"(b[1]));
}

__device__ __forceinline__ uint32_t pack2h(float a, float b) {
    __half2 h = __floats2half2_rn(a, b);
    return *(uint32_t*)&h;
}

// ============================================================================
// Elementwise fp32 -> fp16 convert; blockIdx.y selects tensor (xq/xkv/bias)
// ============================================================================
__global__ __launch_bounds__(256)
void conv_all_kernel(const float* __restrict__ x0, __half* __restrict__ y0,
                     const float* __restrict__ x1, __half* __restrict__ y1,
                     const float* __restrict__ x2, __half* __restrict__ y2)
{
    const float* x = (blockIdx.y == 0) ? x0 : (blockIdx.y == 1) ? x1 : x2;
    __half* y = (blockIdx.y == 0) ? y0 : (blockIdx.y == 1) ? y1 : y2;
    size_t i = ((size_t)blockIdx.x * 256 + threadIdx.x) * 4;
    float4 v = *(const float4*)(x + i);
    __half2* p = (__half2*)(y + i);
    p[0] = __floats2half2_rn(v.x, v.y);
    p[1] = __floats2half2_rn(v.z, v.w);
}

// ============================================================================
// Weight transpose to single fp16, blockIdx.z selects weight
// ============================================================================
__global__ __launch_bounds__(256)
void wconv_all_kernel(const float* __restrict__ w0, __half* __restrict__ t0,
                      const float* __restrict__ w1, __half* __restrict__ t1,
                      const float* __restrict__ w2, __half* __restrict__ t2,
                      const float* __restrict__ w3, __half* __restrict__ t3)
{
    const float* w = (blockIdx.z == 0) ? w0 : (blockIdx.z == 1) ? w1
                    : (blockIdx.z == 2) ? w2 : w3;
    __half* th = (blockIdx.z == 0) ? t0 : (blockIdx.z == 1) ? t1
                : (blockIdx.z == 2) ? t2 : t3;
    __shared__ float tile[32][33];
    const int bx = blockIdx.x * 32;
    const int by = blockIdx.y * 32;
    const int tx = threadIdx.x % 32;
    const int ty = threadIdx.x / 32;
#pragma unroll
    for (int j = 0; j < 32; j += 8)
        tile[ty + j][tx] = w[(size_t)(by + ty + j) * 2048 + bx + tx];
    __syncthreads();
#pragma unroll
    for (int j = 0; j < 32; j += 8)
        th[(size_t)(bx + ty + j) * 2048 + by + tx] = __float2half(tile[tx][ty + j]);
}

// ============================================================================
// fp16 GEMM body: C = alpha * A*B^T.  128x128 tile, 8 warps, K-chunk 64
// (32 iterations — half the syncs), 2-stage ring, x4 ldmatrix.
// Accumulation order per acc identical to K-chunk-32 version.
// ============================================================================
#define TS      144                  // bytes per smem row (128B data + 16 pad)
#define TILE_B  (128 * TS)           // 18432 per tile
#define GEMM_SMEM (2 * 2 * TILE_B)   // 73728

__device__ __forceinline__
void gemm_body(const __half* __restrict__ A, const __half* __restrict__ B,
               float* __restrict__ Cf, __half* __restrict__ Ch, float alpha,
               char* smg, int bx, int by)
{
    const uint32_t smb = smem_u32(smg);
    const int tid  = threadIdx.x;
    const int wid  = tid / 32;
    const int lane = tid % 32;
    const int block_row = by * 128;
    const int block_col = bx * 128;

    const int wm = (wid & 1) * 64;
    const int wn = (wid >> 1) * 32;

    const uint32_t a_lm  = (wm + (lane & 15)) * TS + (lane >> 4) * 16;
    const uint32_t b_lm4 = (wn + (lane & 7)) * TS + ((lane >> 3) & 1) * 16
                         + (lane >> 4) * (8 * TS);

    float acc[4][4][4];
#pragma unroll
    for (int i = 0; i < 4; i++)
#pragma unroll
        for (int j = 0; j < 4; j++)
#pragma unroll
            for (int r = 0; r < 4; r++) acc[i][j][r] = 0.f;

    // loader: per tile 128 rows x 8 granules (128B data) = 1024 granules;
    // 2 tiles = 2048 granules / 256 threads = 8 cp.async per thread.
#define G_LOAD(kk, bufi) do {                                                  \
    const uint32_t bb_ = smb + (bufi) * (2 * TILE_B);                          \
    _Pragma("unroll")                                                          \
    for (int j_ = 0; j_ < 4; j_++) {                                           \
        const int idx_ = tid + 256 * j_;          /* 0..1023 */                \
        const int r_ = idx_ >> 3;                                              \
        const int c_ = idx_ & 7;                                               \
        CP_ASYNC16(bb_ + r_ * TS + c_ * 16,                                    \
                   A + (size_t)(block_row + r_) * 2048 + (kk) + c_ * 8);       \
        CP_ASYNC16(bb_ + TILE_B + r_ * TS + c_ * 16,                           \
                   B + (size_t)(block_col + r_) * 2048 + (kk) + c_ * 8);       \
    }                                                                          \
} while (0)

    G_LOAD(0, 0);
    CP_COMMIT();

    for (int i = 0; i < 32; i++) {
        CP_WAIT(0);                           // chunk i resident
        __syncthreads();                      // one barrier per iter
        if (i + 1 < 32) {
            G_LOAD((i + 1) * 64, (i + 1) & 1);  // overlaps compute below
            CP_COMMIT();
        }
        const uint32_t base = smb + (i & 1) * (2 * TILE_B);
#pragma unroll
        for (int ks = 0; ks < 4; ks++) {
            uint32_t afrag[4][4];
#pragma unroll
            for (int mt = 0; mt < 4; mt++)
                ldsm_x4(afrag[mt], base + a_lm + mt * (16 * TS) + ks * 32);
#pragma unroll
            for (int nt2 = 0; nt2 < 2; nt2++) {
                uint32_t bfr[4];
                ldsm_x4(bfr, base + TILE_B + b_lm4 + nt2 * (16 * TS) + ks * 32);
#pragma unroll
                for (int mt = 0; mt < 4; mt++) {
                    mma16816(acc[mt][2 * nt2],     afrag[mt], bfr);
                    mma16816(acc[mt][2 * nt2 + 1], afrag[mt], bfr + 2);
                }
            }
        }
    }

#pragma unroll
    for (int mt = 0; mt < 4; mt++) {
        const int row = block_row + wm + mt * 16 + lane / 4;
#pragma unroll
        for (int nt = 0; nt < 4; nt++) {
            const int col = block_col + wn + nt * 8 + (lane % 4) * 2;
            float v0 = alpha * acc[mt][nt][0];
            float v1 = alpha * acc[mt][nt][1];
            float v2 = alpha * acc[mt][nt][2];
            float v3 = alpha * acc[mt][nt][3];
            if (Cf) {
                *(float2*)(Cf + (size_t)row * 2048 + col)       = make_float2(v0, v1);
                *(float2*)(Cf + (size_t)(row + 8) * 2048 + col) = make_float2(v2, v3);
            } else {
                *(uint32_t*)(Ch + (size_t)row * 2048 + col)       = pack2h(v0, v1);
                *(uint32_t*)(Ch + (size_t)(row + 8) * 2048 + col) = pack2h(v2, v3);
            }
        }
    }
}

__global__ __launch_bounds__(256, 2)
void gemm_qkv_kernel(const __half* __restrict__ xq, const __half* __restrict__ xkv,
                     const __half* __restrict__ wqt, const __half* __restrict__ wkt,
                     const __half* __restrict__ wvt,
                     __half* __restrict__ qs, __half* __restrict__ ks,
                     __half* __restrict__ vs)
{
    extern __shared__ __align__(16) char smg[];
    const int z = blockIdx.z;
    const __half* A = (z == 0) ? xq : xkv;
    const __half* B = (z == 0) ? wqt : (z == 1) ? wkt : wvt;
    __half* C = (z == 0) ? qs : (z == 1) ? ks : vs;
    const float alpha = (z == 0) ? 0.125f : 1.0f;
    gemm_body(A, B, nullptr, C, alpha, smg, blockIdx.x, blockIdx.y);
}

__global__ __launch_bounds__(256, 2)
void gemm_out_kernel(const __half* __restrict__ cs, const __half* __restrict__ wot,
                     float* __restrict__ out)
{
    extern __shared__ __align__(16) char smg[];
    gemm_body(cs, wot, out, nullptr, 1.0f, smg, blockIdx.x, blockIdx.y);
}

// ============================================================================
// Flash attention (fp16): EXACT R12 version — 8 warps x 16 q-rows,
// 3-stage KV ring, one sync per chunk, x4 ldmatrix, bias reg prefetch.
// ============================================================================
#define KVS 144
#define KVT (64 * KVS)
#define ATT_SMEM (3 * 2 * KVT)       // 55296

__global__ __launch_bounds__(256, 2)
void attn_mma(const __half* __restrict__ q,
              const __half* __restrict__ k,
              const __half* __restrict__ v,
              const __half* __restrict__ bias,
              __half* __restrict__ cs)
{
    extern __shared__ __align__(16) char sm[];
    const uint32_t smb = smem_u32(sm);

    const int tid  = threadIdx.x;
    const int wid  = tid / 32;
    const int lane = tid % 32;
    const int qt = blockIdx.x;
    const int h  = blockIdx.y;
    const int b  = blockIdx.z;
    const int g  = lane >> 2;
    const int t  = lane & 3;

    const int qrow  = qt * 128 + wid * 16 + g;
    const size_t arow = (size_t)(b * 2048 + qrow);
    const int dbase = h * 64;

    uint32_t qf[4][4];
    {
        const __half* q0 = q + arow * 2048 + dbase;
#pragma unroll
        for (int kk = 0; kk < 4; kk++) {
            qf[kk][0] = *(const uint32_t*)(q0 + kk * 16 + 2 * t);
            qf[kk][1] = *(const uint32_t*)(q0 + (size_t)8 * 2048 + kk * 16 + 2 * t);
            qf[kk][2] = *(const uint32_t*)(q0 + kk * 16 + 8 + 2 * t);
            qf[kk][3] = *(const uint32_t*)(q0 + (size_t)8 * 2048 + kk * 16 + 8 + 2 * t);
        }
    }

    float ctx[8][4];
#pragma unroll
    for (int nt = 0; nt < 8; nt++)
#pragma unroll
        for (int r = 0; r < 4; r++) ctx[nt][r] = 0.f;
    float m0 = -1e30f, m1 = -1e30f, l0 = 0.f, l1 = 0.f;

    const int lr  = tid >> 3;
    const int lgr = tid & 7;
#define LOAD_CHUNK(kc, bufi) do {                                              \
    const uint32_t base_ = smb + (bufi) * (2 * KVT);                           \
    _Pragma("unroll")                                                          \
    for (int i_ = 0; i_ < 4; i_++) {                                           \
        const __half* s_ = (i_ < 2) ? k : v;                                   \
        const int r_ = lr + 32 * (i_ & 1);                                     \
        const int mat_ = i_ >> 1;                                              \
        const __half* src_ = s_ +                                              \
            (size_t)(b * 2048 + (kc) + r_) * 2048 + dbase + lgr * 8;           \
        CP_ASYNC16(base_ + mat_ * KVT + r_ * KVS + lgr * 16, src_);            \
    }                                                                          \
} while (0)

    LOAD_CHUNK(0, 0);
    CP_COMMIT();
    LOAD_CHUNK(64, 1);
    CP_COMMIT();

    const __half* bias_b  = bias + (size_t)b * 2048 * 2048
                          + (size_t)(qt * 128 + wid * 16 + g) * 2048;
    const __half* bias_b8 = bias_b + (size_t)8 * 2048;

    __half2 pb[8], pb8[8];
#pragma unroll
    for (int nt = 0; nt < 8; nt++) {
        pb[nt]  = *(const __half2*)(bias_b  + nt * 8 + 2 * t);
        pb8[nt] = *(const __half2*)(bias_b8 + nt * 8 + 2 * t);
    }

    const uint32_t kaddr4 = (lane & 7) * KVS + ((lane >> 3) & 1) * 16
                          + (lane >> 4) * (8 * KVS);
    const uint32_t vaddr4 = (lane & 15) * KVS + (lane >> 4) * 16;

    for (int c = 0; c < 32; c++) {
        if (c < 31) { CP_WAIT(1); } else { CP_WAIT(0); }
        __syncthreads();
        if (c + 2 < 32) {
            LOAD_CHUNK((c + 2) * 64, (c + 2) % 3);
            CP_COMMIT();
        }

        const uint32_t k_s = smb + (c % 3) * (2 * KVT);
        const uint32_t v_s = k_s + KVT;

        float s[8][4];
#pragma unroll
        for (int nt = 0; nt < 8; nt++) {
            s[nt][0] = __low2float(pb[nt]);
            s[nt][1] = __high2float(pb[nt]);
            s[nt][2] = __low2float(pb8[nt]);
            s[nt][3] = __high2float(pb8[nt]);
        }
        if (c + 1 < 32) {
            const __half* nb  = bias_b  + (c + 1) * 64;
            const __half* nb8 = bias_b8 + (c + 1) * 64;
#pragma unroll
            for (int nt = 0; nt < 8; nt++) {
                pb[nt]  = *(const __half2*)(nb  + nt * 8 + 2 * t);
                pb8[nt] = *(const __half2*)(nb8 + nt * 8 + 2 * t);
            }
        }

#pragma unroll
        for (int kk = 0; kk < 4; kk++) {
#pragma unroll
            for (int nt2 = 0; nt2 < 4; nt2++) {
                uint32_t bfr[4];
                ldsm_x4(bfr, k_s + nt2 * (16 * KVS) + kaddr4 + kk * 32);
                mma16816(s[2 * nt2],     qf[kk], bfr);
                mma16816(s[2 * nt2 + 1], qf[kk], bfr + 2);
            }
        }

        float mx0 = -1e30f, mx1 = -1e30f;
#pragma unroll
        for (int nt = 0; nt < 8; nt++) {
            mx0 = fmaxf(mx0, fmaxf(s[nt][0], s[nt][1]));
            mx1 = fmaxf(mx1, fmaxf(s[nt][2], s[nt][3]));
        }
        mx0 = fmaxf(mx0, __shfl_xor_sync(0xffffffffu, mx0, 1));
        mx0 = fmaxf(mx0, __shfl_xor_sync(0xffffffffu, mx0, 2));
        mx1 = fmaxf(mx1, __shfl_xor_sync(0xffffffffu, mx1, 1));
        mx1 = fmaxf(mx1, __shfl_xor_sync(0xffffffffu, mx1, 2));
        const float mn0 = fmaxf(m0, mx0);
        const float mn1 = fmaxf(m1, mx1);
        const float sc0 = __expf(m0 - mn0);
        const float sc1 = __expf(m1 - mn1);
        m0 = mn0; m1 = mn1;

        uint32_t p01[8], p23[8];
        float rs0 = 0.f, rs1 = 0.f;
#pragma unroll
        for (int nt = 0; nt < 8; nt++) {
            float e0 = __expf(s[nt][0] - mn0);
            float e1 = __expf(s[nt][1] - mn0);
            float e2 = __expf(s[nt][2] - mn1);
            float e3 = __expf(s[nt][3] - mn1);
            __half2 h01 = __floats2half2_rn(e0, e1);
            __half2 h23 = __floats2half2_rn(e2, e3);
            p01[nt] = *(uint32_t*)&h01;
            p23[nt] = *(uint32_t*)&h23;
            rs0 += __low2float(h01) + __high2float(h01);
            rs1 += __low2float(h23) + __high2float(h23);
        }
        rs0 += __shfl_xor_sync(0xffffffffu, rs0, 1);
        rs0 += __shfl_xor_sync(0xffffffffu, rs0, 2);
        rs1 += __shfl_xor_sync(0xffffffffu, rs1, 1);
        rs1 += __shfl_xor_sync(0xffffffffu, rs1, 2);
        l0 = l0 * sc0 + rs0;
        l1 = l1 * sc1 + rs1;

#pragma unroll
        for (int nt = 0; nt < 8; nt++) {
            ctx[nt][0] *= sc0; ctx[nt][1] *= sc0;
            ctx[nt][2] *= sc1; ctx[nt][3] *= sc1;
        }

#pragma unroll
        for (int j = 0; j < 4; j++) {
            const uint32_t pa[4] = {p01[2 * j], p23[2 * j], p01[2 * j + 1], p23[2 * j + 1]};
#pragma unroll
            for (int nt2 = 0; nt2 < 4; nt2++) {
                uint32_t bvr[4];
                ldsm_x4_t(bvr, v_s + j * (16 * KVS) + vaddr4 + nt2 * 32);
                mma16816(ctx[2 * nt2],     pa, bvr);
                mma16816(ctx[2 * nt2 + 1], pa, bvr + 2);
            }
        }
    }

    const float inv0 = 1.f / l0;
    const float inv1 = 1.f / l1;
#pragma unroll
    for (int nt = 0; nt < 8; nt++) {
        const int col = dbase + nt * 8 + 2 * t;
        *(uint32_t*)(cs + arow * 2048 + col) =
            pack2h(ctx[nt][0] * inv0, ctx[nt][1] * inv0);
        *(uint32_t*)(cs + (arow + 8) * 2048 + col) =
            pack2h(ctx[nt][2] * inv1, ctx[nt][3] * inv1);
    }
}

// ============================================================================
// Launch
// ============================================================================
extern "C" void kernel_launch(void* const* d_in, const int* in_sizes, int n_in,
                              void* d_out, int out_size)
{
    const float* inputs_q  = (const float*)d_in[0];
    const float* inputs_kv = (const float*)d_in[1];
    const float* bias      = (const float*)d_in[2];
    const float* wq        = (const float*)d_in[3];
    const float* wk        = (const float*)d_in[4];
    const float* wv        = (const float*)d_in[5];
    const float* wo        = (const float*)d_in[6];
    float* out = (float*)d_out;

    __half *xq, *xkv, *bh, *qs, *ks, *vs, *cs;
    __half *wqt, *wkt, *wvt, *wot;
    cudaGetSymbolAddress((void**)&xq,  g_xq);
    cudaGetSymbolAddress((void**)&xkv, g_xkv);
    cudaGetSymbolAddress((void**)&bh,  g_bh);
    cudaGetSymbolAddress((void**)&qs,  g_qs);
    cudaGetSymbolAddress((void**)&ks,  g_ks);
    cudaGetSymbolAddress((void**)&vs,  g_vs);
    cudaGetSymbolAddress((void**)&cs,  g_cs);
    cudaGetSymbolAddress((void**)&wqt, g_wqt);
    cudaGetSymbolAddress((void**)&wkt, g_wkt);
    cudaGetSymbolAddress((void**)&wvt, g_wvt);
    cudaGetSymbolAddress((void**)&wot, g_wot);

    static bool attr_done = false;
    if (!attr_done) {
        cudaFuncSetAttribute(attn_mma, cudaFuncAttributeMaxDynamicSharedMemorySize,
                             ATT_SMEM);
        cudaFuncSetAttribute(gemm_qkv_kernel, cudaFuncAttributeMaxDynamicSharedMemorySize,
                             GEMM_SMEM);
        cudaFuncSetAttribute(gemm_out_kernel, cudaFuncAttributeMaxDynamicSharedMemorySize,
                             GEMM_SMEM);
        attr_done = true;
    }

    const int n_act = ROWS * EMB;
    const dim3 ggrid(EMB / 128, ROWS / 128);          // (16, 32)
    const dim3 gqkv(EMB / 128, ROWS / 128, 3);

    // Prep: 2 launches
    conv_all_kernel<<<dim3(n_act / 1024, 3), 256>>>(inputs_q, xq, inputs_kv, xkv,
                                                    bias, bh);
    wconv_all_kernel<<<dim3(64, 64, 4), 256>>>(wq, wqt, wk, wkt, wv, wvt, wo, wot);

    // Fused Q/K/V projections
    gemm_qkv_kernel<<<gqkv, 256, GEMM_SMEM>>>(xq, xkv, wqt, wkt, wvt, qs, ks, vs);

    // Flash attention (8 warps x 16 rows, R12 config) -> single fp16 ctx
    attn_mma<<<dim3(16, 32, 2), 256, ATT_SMEM>>>(qs, ks, vs, bh, cs);

    // Output projection -> f32 out
    gemm_out_kernel<<<ggrid, 256, GEMM_SMEM>>>(cs, wot, out);
}

// round 15
// speedup vs baseline: 8.4065x; 1.0162x over previous
#include <cuda_runtime.h>
#include <cuda_fp16.h>
#include <cstdint>

// Problem constants
#define BB   2
#define QQ   2048
#define KK   2048
#define EMB  2048
#define HH   32
#define DD   64
#define ROWS (BB * QQ)          // 4096

#define LOG2E 1.4426950408889634f

// ---------------- scratch (device globals; no allocation allowed) ----------
__device__ __half g_xq [ROWS * EMB];
__device__ __half g_xkv[ROWS * EMB];
__device__ __half g_bh [BB * QQ * KK];   // bias * log2e, fp16
__device__ __half g_qs [ROWS * EMB];
__device__ __half g_ks [ROWS * EMB];
__device__ __half g_vs [ROWS * EMB];
__device__ __half g_cs [ROWS * EMB];

__device__ __half g_wqt[EMB * EMB];
__device__ __half g_wkt[EMB * EMB];
__device__ __half g_wvt[EMB * EMB];
__device__ __half g_wot[EMB * EMB];

// ---------------- helpers ---------------------------------------------------
__device__ __forceinline__ uint32_t smem_u32(const void* p) {
    uint32_t a;
    asm("{ .reg .u64 t; cvta.to.shared.u64 t, %1; cvt.u32.u64 %0, t; }"
        : "=r"(a) : "l"(p));
    return a;
}
__device__ __forceinline__ float ex2f(float x) {
    float y; asm("ex2.approx.f32 %0, %1;" : "=f"(y) : "f"(x)); return y;
}

#define CP_ASYNC16(dst, src) \
    asm volatile("cp.async.cg.shared.global [%0], [%1], 16;" :: "r"(dst), "l"(src))
#define CP_COMMIT() asm volatile("cp.async.commit_group;" ::: "memory")
#define CP_WAIT(n)  asm volatile("cp.async.wait_group %0;" :: "n"(n) : "memory")

__device__ __forceinline__ void ldsm_x4(uint32_t* d, uint32_t addr) {
    asm volatile("ldmatrix.sync.aligned.m8n8.x4.shared.b16 {%0,%1,%2,%3}, [%4];"
                 : "=r"(d[0]), "=r"(d[1]), "=r"(d[2]), "=r"(d[3]) : "r"(addr));
}
__device__ __forceinline__ void ldsm_x4_t(uint32_t* d, uint32_t addr) {
    asm volatile("ldmatrix.sync.aligned.m8n8.x4.trans.shared.b16 {%0,%1,%2,%3}, [%4];"
                 : "=r"(d[0]), "=r"(d[1]), "=r"(d[2]), "=r"(d[3]) : "r"(addr));
}
__device__ __forceinline__ void mma16816(float* d, const uint32_t* a, const uint32_t* b) {
    asm volatile(
        "mma.sync.aligned.m16n8k16.row.col.f32.f16.f16.f32 "
        "{%0,%1,%2,%3}, {%4,%5,%6,%7}, {%8,%9}, {%0,%1,%2,%3};"
        : "+f"(d[0]), "+f"(d[1]), "+f"(d[2]), "+f"(d[3])
        : "r"(a[0]), "r"(a[1]), "r"(a[2]), "r"(a[3]), "r"(b[0]), "r"(b[1]));
}

__device__ __forceinline__ uint32_t pack2h(float a, float b) {
    __half2 h = __floats2half2_rn(a, b);
    return *(uint32_t*)&h;
}

// ============================================================================
// Elementwise fp32 -> fp16 convert with per-tensor scale;
// blockIdx.y selects tensor (xq, xkv, bias*log2e)
// ============================================================================
__global__ __launch_bounds__(256)
void conv_all_kernel(const float* __restrict__ x0, __half* __restrict__ y0,
                     const float* __restrict__ x1, __half* __restrict__ y1,
                     const float* __restrict__ x2, __half* __restrict__ y2)
{
    const float* x = (blockIdx.y == 0) ? x0 : (blockIdx.y == 1) ? x1 : x2;
    __half* y = (blockIdx.y == 0) ? y0 : (blockIdx.y == 1) ? y1 : y2;
    const float sc = (blockIdx.y == 2) ? LOG2E : 1.0f;
    size_t i = ((size_t)blockIdx.x * 256 + threadIdx.x) * 4;
    float4 v = *(const float4*)(x + i);
    __half2* p = (__half2*)(y + i);
    p[0] = __floats2half2_rn(v.x * sc, v.y * sc);
    p[1] = __floats2half2_rn(v.z * sc, v.w * sc);
}

// ============================================================================
// Weight transpose to single fp16, blockIdx.z selects weight
// ============================================================================
__global__ __launch_bounds__(256)
void wconv_all_kernel(const float* __restrict__ w0, __half* __restrict__ t0,
                      const float* __restrict__ w1, __half* __restrict__ t1,
                      const float* __restrict__ w2, __half* __restrict__ t2,
                      const float* __restrict__ w3, __half* __restrict__ t3)
{
    const float* w = (blockIdx.z == 0) ? w0 : (blockIdx.z == 1) ? w1
                    : (blockIdx.z == 2) ? w2 : w3;
    __half* th = (blockIdx.z == 0) ? t0 : (blockIdx.z == 1) ? t1
                : (blockIdx.z == 2) ? t2 : t3;
    __shared__ float tile[32][33];
    const int bx = blockIdx.x * 32;
    const int by = blockIdx.y * 32;
    const int tx = threadIdx.x % 32;
    const int ty = threadIdx.x / 32;
#pragma unroll
    for (int j = 0; j < 32; j += 8)
        tile[ty + j][tx] = w[(size_t)(by + ty + j) * 2048 + bx + tx];
    __syncthreads();
#pragma unroll
    for (int j = 0; j < 32; j += 8)
        th[(size_t)(bx + ty + j) * 2048 + by + tx] = __float2half(tile[tx][ty + j]);
}

// ============================================================================
// fp16 GEMM body: C = alpha * A*B^T.  Unchanged from R14 (K-chunk 64,
// 32 iters, 2-stage ring, one sync per iter, x4 ldmatrix).
// ============================================================================
#define TS      144
#define TILE_B  (128 * TS)           // 18432 per tile
#define GEMM_SMEM (2 * 2 * TILE_B)   // 73728

__device__ __forceinline__
void gemm_body(const __half* __restrict__ A, const __half* __restrict__ B,
               float* __restrict__ Cf, __half* __restrict__ Ch, float alpha,
               char* smg, int bx, int by)
{
    const uint32_t smb = smem_u32(smg);
    const int tid  = threadIdx.x;
    const int wid  = tid / 32;
    const int lane = tid % 32;
    const int block_row = by * 128;
    const int block_col = bx * 128;

    const int wm = (wid & 1) * 64;
    const int wn = (wid >> 1) * 32;

    const uint32_t a_lm  = (wm + (lane & 15)) * TS + (lane >> 4) * 16;
    const uint32_t b_lm4 = (wn + (lane & 7)) * TS + ((lane >> 3) & 1) * 16
                         + (lane >> 4) * (8 * TS);

    float acc[4][4][4];
#pragma unroll
    for (int i = 0; i < 4; i++)
#pragma unroll
        for (int j = 0; j < 4; j++)
#pragma unroll
            for (int r = 0; r < 4; r++) acc[i][j][r] = 0.f;

#define G_LOAD(kk, bufi) do {                                                  \
    const uint32_t bb_ = smb + (bufi) * (2 * TILE_B);                          \
    _Pragma("unroll")                                                          \
    for (int j_ = 0; j_ < 4; j_++) {                                           \
        const int idx_ = tid + 256 * j_;                                       \
        const int r_ = idx_ >> 3;                                              \
        const int c_ = idx_ & 7;                                               \
        CP_ASYNC16(bb_ + r_ * TS + c_ * 16,                                    \
                   A + (size_t)(block_row + r_) * 2048 + (kk) + c_ * 8);       \
        CP_ASYNC16(bb_ + TILE_B + r_ * TS + c_ * 16,                           \
                   B + (size_t)(block_col + r_) * 2048 + (kk) + c_ * 8);       \
    }                                                                          \
} while (0)

    G_LOAD(0, 0);
    CP_COMMIT();

    for (int i = 0; i < 32; i++) {
        CP_WAIT(0);
        __syncthreads();
        if (i + 1 < 32) {
            G_LOAD((i + 1) * 64, (i + 1) & 1);
            CP_COMMIT();
        }
        const uint32_t base = smb + (i & 1) * (2 * TILE_B);
#pragma unroll
        for (int ks = 0; ks < 4; ks++) {
            uint32_t afrag[4][4];
#pragma unroll
            for (int mt = 0; mt < 4; mt++)
                ldsm_x4(afrag[mt], base + a_lm + mt * (16 * TS) + ks * 32);
#pragma unroll
            for (int nt2 = 0; nt2 < 2; nt2++) {
                uint32_t bfr[4];
                ldsm_x4(bfr, base + TILE_B + b_lm4 + nt2 * (16 * TS) + ks * 32);
#pragma unroll
                for (int mt = 0; mt < 4; mt++) {
                    mma16816(acc[mt][2 * nt2],     afrag[mt], bfr);
                    mma16816(acc[mt][2 * nt2 + 1], afrag[mt], bfr + 2);
                }
            }
        }
    }

#pragma unroll
    for (int mt = 0; mt < 4; mt++) {
        const int row = block_row + wm + mt * 16 + lane / 4;
#pragma unroll
        for (int nt = 0; nt < 4; nt++) {
            const int col = block_col + wn + nt * 8 + (lane % 4) * 2;
            float v0 = alpha * acc[mt][nt][0];
            float v1 = alpha * acc[mt][nt][1];
            float v2 = alpha * acc[mt][nt][2];
            float v3 = alpha * acc[mt][nt][3];
            if (Cf) {
                *(float2*)(Cf + (size_t)row * 2048 + col)       = make_float2(v0, v1);
                *(float2*)(Cf + (size_t)(row + 8) * 2048 + col) = make_float2(v2, v3);
            } else {
                *(uint32_t*)(Ch + (size_t)row * 2048 + col)       = pack2h(v0, v1);
                *(uint32_t*)(Ch + (size_t)(row + 8) * 2048 + col) = pack2h(v2, v3);
            }
        }
    }
}

__global__ __launch_bounds__(256, 2)
void gemm_qkv_kernel(const __half* __restrict__ xq, const __half* __restrict__ xkv,
                     const __half* __restrict__ wqt, const __half* __restrict__ wkt,
                     const __half* __restrict__ wvt,
                     __half* __restrict__ qs, __half* __restrict__ ks,
                     __half* __restrict__ vs)
{
    extern __shared__ __align__(16) char smg[];
    const int z = blockIdx.z;
    const __half* A = (z == 0) ? xq : xkv;
    const __half* B = (z == 0) ? wqt : (z == 1) ? wkt : wvt;
    __half* C = (z == 0) ? qs : (z == 1) ? ks : vs;
    // q scaled by (1/sqrt(D)) * log2(e) for the exp2-domain softmax
    const float alpha = (z == 0) ? 0.125f * LOG2E : 1.0f;
    gemm_body(A, B, nullptr, C, alpha, smg, blockIdx.x, blockIdx.y);
}

__global__ __launch_bounds__(256, 2)
void gemm_out_kernel(const __half* __restrict__ cs, const __half* __restrict__ wot,
                     float* __restrict__ out)
{
    extern __shared__ __align__(16) char smg[];
    gemm_body(cs, wot, out, nullptr, 1.0f, smg, blockIdx.x, blockIdx.y);
}

// ============================================================================
// Flash attention (fp16, exp2 domain): 8 warps x 16 q-rows, 3-stage KV ring,
// one sync per chunk, x4 ldmatrix, bias reg prefetch.
// l kept as PER-LANE partials (sc is row-uniform) — reduced once at the end.
// ============================================================================
#define KVS 144
#define KVT (64 * KVS)
#define ATT_SMEM (3 * 2 * KVT)       // 55296

__global__ __launch_bounds__(256, 2)
void attn_mma(const __half* __restrict__ q,
              const __half* __restrict__ k,
              const __half* __restrict__ v,
              const __half* __restrict__ bias,
              __half* __restrict__ cs)
{
    extern __shared__ __align__(16) char sm[];
    const uint32_t smb = smem_u32(sm);

    const int tid  = threadIdx.x;
    const int wid  = tid / 32;
    const int lane = tid % 32;
    const int qt = blockIdx.x;
    const int h  = blockIdx.y;
    const int b  = blockIdx.z;
    const int g  = lane >> 2;
    const int t  = lane & 3;

    const int qrow  = qt * 128 + wid * 16 + g;
    const size_t arow = (size_t)(b * 2048 + qrow);
    const int dbase = h * 64;

    uint32_t qf[4][4];
    {
        const __half* q0 = q + arow * 2048 + dbase;
#pragma unroll
        for (int kk = 0; kk < 4; kk++) {
            qf[kk][0] = *(const uint32_t*)(q0 + kk * 16 + 2 * t);
            qf[kk][1] = *(const uint32_t*)(q0 + (size_t)8 * 2048 + kk * 16 + 2 * t);
            qf[kk][2] = *(const uint32_t*)(q0 + kk * 16 + 8 + 2 * t);
            qf[kk][3] = *(const uint32_t*)(q0 + (size_t)8 * 2048 + kk * 16 + 8 + 2 * t);
        }
    }

    float ctx[8][4];
#pragma unroll
    for (int nt = 0; nt < 8; nt++)
#pragma unroll
        for (int r = 0; r < 4; r++) ctx[nt][r] = 0.f;
    float m0 = -1e30f, m1 = -1e30f;
    float l0 = 0.f, l1 = 0.f;           // per-lane partials

    const int lr  = tid >> 3;
    const int lgr = tid & 7;
#define LOAD_CHUNK(kc, bufi) do {                                              \
    const uint32_t base_ = smb + (bufi) * (2 * KVT);                           \
    _Pragma("unroll")                                                          \
    for (int i_ = 0; i_ < 4; i_++) {                                           \
        const __half* s_ = (i_ < 2) ? k : v;                                   \
        const int r_ = lr + 32 * (i_ & 1);                                     \
        const int mat_ = i_ >> 1;                                              \
        const __half* src_ = s_ +                                              \
            (size_t)(b * 2048 + (kc) + r_) * 2048 + dbase + lgr * 8;           \
        CP_ASYNC16(base_ + mat_ * KVT + r_ * KVS + lgr * 16, src_);            \
    }                                                                          \
} while (0)

    LOAD_CHUNK(0, 0);
    CP_COMMIT();
    LOAD_CHUNK(64, 1);
    CP_COMMIT();

    const __half* bias_b  = bias + (size_t)b * 2048 * 2048
                          + (size_t)(qt * 128 + wid * 16 + g) * 2048;
    const __half* bias_b8 = bias_b + (size_t)8 * 2048;

    __half2 pb[8], pb8[8];
#pragma unroll
    for (int nt = 0; nt < 8; nt++) {
        pb[nt]  = *(const __half2*)(bias_b  + nt * 8 + 2 * t);
        pb8[nt] = *(const __half2*)(bias_b8 + nt * 8 + 2 * t);
    }

    const uint32_t kaddr4 = (lane & 7) * KVS + ((lane >> 3) & 1) * 16
                          + (lane >> 4) * (8 * KVS);
    const uint32_t vaddr4 = (lane & 15) * KVS + (lane >> 4) * 16;

    for (int c = 0; c < 32; c++) {
        if (c < 31) { CP_WAIT(1); } else { CP_WAIT(0); }
        __syncthreads();
        if (c + 2 < 32) {
            LOAD_CHUNK((c + 2) * 64, (c + 2) % 3);
            CP_COMMIT();
        }

        const uint32_t k_s = smb + (c % 3) * (2 * KVT);
        const uint32_t v_s = k_s + KVT;

        float s[8][4];
#pragma unroll
        for (int nt = 0; nt < 8; nt++) {
            s[nt][0] = __low2float(pb[nt]);
            s[nt][1] = __high2float(pb[nt]);
            s[nt][2] = __low2float(pb8[nt]);
            s[nt][3] = __high2float(pb8[nt]);
        }
        if (c + 1 < 32) {
            const __half* nb  = bias_b  + (c + 1) * 64;
            const __half* nb8 = bias_b8 + (c + 1) * 64;
#pragma unroll
            for (int nt = 0; nt < 8; nt++) {
                pb[nt]  = *(const __half2*)(nb  + nt * 8 + 2 * t);
                pb8[nt] = *(const __half2*)(nb8 + nt * 8 + 2 * t);
            }
        }

#pragma unroll
        for (int kk = 0; kk < 4; kk++) {
#pragma unroll
            for (int nt2 = 0; nt2 < 4; nt2++) {
                uint32_t bfr[4];
                ldsm_x4(bfr, k_s + nt2 * (16 * KVS) + kaddr4 + kk * 32);
                mma16816(s[2 * nt2],     qf[kk], bfr);
                mma16816(s[2 * nt2 + 1], qf[kk], bfr + 2);
            }
        }

        // ---- online softmax (exp2 domain; s already includes log2e factors)
        float mx0 = -1e30f, mx1 = -1e30f;
#pragma unroll
        for (int nt = 0; nt < 8; nt++) {
            mx0 = fmaxf(mx0, fmaxf(s[nt][0], s[nt][1]));
            mx1 = fmaxf(mx1, fmaxf(s[nt][2], s[nt][3]));
        }
        mx0 = fmaxf(mx0, __shfl_xor_sync(0xffffffffu, mx0, 1));
        mx0 = fmaxf(mx0, __shfl_xor_sync(0xffffffffu, mx0, 2));
        mx1 = fmaxf(mx1, __shfl_xor_sync(0xffffffffu, mx1, 1));
        mx1 = fmaxf(mx1, __shfl_xor_sync(0xffffffffu, mx1, 2));
        const float mn0 = fmaxf(m0, mx0);
        const float mn1 = fmaxf(m1, mx1);
        const float sc0 = ex2f(m0 - mn0);
        const float sc1 = ex2f(m1 - mn1);
        m0 = mn0; m1 = mn1;

        uint32_t p01[8], p23[8];
        float rs0 = 0.f, rs1 = 0.f;
#pragma unroll
        for (int nt = 0; nt < 8; nt++) {
            float e0 = ex2f(s[nt][0] - mn0);
            float e1 = ex2f(s[nt][1] - mn0);
            float e2 = ex2f(s[nt][2] - mn1);
            float e3 = ex2f(s[nt][3] - mn1);
            __half2 h01 = __floats2half2_rn(e0, e1);
            __half2 h23 = __floats2half2_rn(e2, e3);
            p01[nt] = *(uint32_t*)&h01;
            p23[nt] = *(uint32_t*)&h23;
            rs0 += __low2float(h01) + __high2float(h01);
            rs1 += __low2float(h23) + __high2float(h23);
        }
        // per-lane partial update; cross-lane reduction deferred to epilogue
        l0 = l0 * sc0 + rs0;
        l1 = l1 * sc1 + rs1;

#pragma unroll
        for (int nt = 0; nt < 8; nt++) {
            ctx[nt][0] *= sc0; ctx[nt][1] *= sc0;
            ctx[nt][2] *= sc1; ctx[nt][3] *= sc1;
        }

#pragma unroll
        for (int j = 0; j < 4; j++) {
            const uint32_t pa[4] = {p01[2 * j], p23[2 * j], p01[2 * j + 1], p23[2 * j + 1]};
#pragma unroll
            for (int nt2 = 0; nt2 < 4; nt2++) {
                uint32_t bvr[4];
                ldsm_x4_t(bvr, v_s + j * (16 * KVS) + vaddr4 + nt2 * 32);
                mma16816(ctx[2 * nt2],     pa, bvr);
                mma16816(ctx[2 * nt2 + 1], pa, bvr + 2);
            }
        }
    }

    // ---- final cross-lane l reduction (4 lanes share a row)
    l0 += __shfl_xor_sync(0xffffffffu, l0, 1);
    l0 += __shfl_xor_sync(0xffffffffu, l0, 2);
    l1 += __shfl_xor_sync(0xffffffffu, l1, 1);
    l1 += __shfl_xor_sync(0xffffffffu, l1, 2);

    const float inv0 = 1.f / l0;
    const float inv1 = 1.f / l1;
#pragma unroll
    for (int nt = 0; nt < 8; nt++) {
        const int col = dbase + nt * 8 + 2 * t;
        *(uint32_t*)(cs + arow * 2048 + col) =
            pack2h(ctx[nt][0] * inv0, ctx[nt][1] * inv0);
        *(uint32_t*)(cs + (arow + 8) * 2048 + col) =
            pack2h(ctx[nt][2] * inv1, ctx[nt][3] * inv1);
    }
}

// ============================================================================
// Launch
// ============================================================================
extern "C" void kernel_launch(void* const* d_in, const int* in_sizes, int n_in,
                              void* d_out, int out_size)
{
    const float* inputs_q  = (const float*)d_in[0];
    const float* inputs_kv = (const float*)d_in[1];
    const float* bias      = (const float*)d_in[2];
    const float* wq        = (const float*)d_in[3];
    const float* wk        = (const float*)d_in[4];
    const float* wv        = (const float*)d_in[5];
    const float* wo        = (const float*)d_in[6];
    float* out = (float*)d_out;

    __half *xq, *xkv, *bh, *qs, *ks, *vs, *cs;
    __half *wqt, *wkt, *wvt, *wot;
    cudaGetSymbolAddress((void**)&xq,  g_xq);
    cudaGetSymbolAddress((void**)&xkv, g_xkv);
    cudaGetSymbolAddress((void**)&bh,  g_bh);
    cudaGetSymbolAddress((void**)&qs,  g_qs);
    cudaGetSymbolAddress((void**)&ks,  g_ks);
    cudaGetSymbolAddress((void**)&vs,  g_vs);
    cudaGetSymbolAddress((void**)&cs,  g_cs);
    cudaGetSymbolAddress((void**)&wqt, g_wqt);
    cudaGetSymbolAddress((void**)&wkt, g_wkt);
    cudaGetSymbolAddress((void**)&wvt, g_wvt);
    cudaGetSymbolAddress((void**)&wot, g_wot);

    static bool attr_done = false;
    if (!attr_done) {
        cudaFuncSetAttribute(attn_mma, cudaFuncAttributeMaxDynamicSharedMemorySize,
                             ATT_SMEM);
        cudaFuncSetAttribute(gemm_qkv_kernel, cudaFuncAttributeMaxDynamicSharedMemorySize,
                             GEMM_SMEM);
        cudaFuncSetAttribute(gemm_out_kernel, cudaFuncAttributeMaxDynamicSharedMemorySize,
                             GEMM_SMEM);
        attr_done = true;
    }

    const int n_act = ROWS * EMB;
    const dim3 ggrid(EMB / 128, ROWS / 128);          // (16, 32)
    const dim3 gqkv(EMB / 128, ROWS / 128, 3);

    // Prep: 2 launches (bias scaled by log2e during conversion)
    conv_all_kernel<<<dim3(n_act / 1024, 3), 256>>>(inputs_q, xq, inputs_kv, xkv,
                                                    bias, bh);
    wconv_all_kernel<<<dim3(64, 64, 4), 256>>>(wq, wqt, wk, wkt, wv, wvt, wo, wot);

    // Fused Q/K/V projections (q scaled by 0.125*log2e)
    gemm_qkv_kernel<<<gqkv, 256, GEMM_SMEM>>>(xq, xkv, wqt, wkt, wvt, qs, ks, vs);

    // Flash attention (exp2 domain) -> single fp16 ctx
    attn_mma<<<dim3(16, 32, 2), 256, ATT_SMEM>>>(qs, ks, vs, bh, cs);

    // Output projection -> f32 out
    gemm_out_kernel<<<ggrid, 256, GEMM_SMEM>>>(cs, wot, out);
}